// round 1
// baseline (speedup 1.0000x reference)
#include <cuda_runtime.h>
#include <math.h>

#define BATCH 8
#define CCH   256
#define HH    64
#define WW    64
#define NN    4096   // HH*WW
#define MM    1024   // (HH/2)*(WW/2)
#define HK    32
#define WK    32

// Scratch (static device allocations are allowed)
__device__ float g_q[(size_t)BATCH * CCH * NN];   // 32 MB
__device__ float g_k[(size_t)BATCH * CCH * MM];   // 8 MB
__device__ float g_v[(size_t)BATCH * CCH * MM];   // 8 MB
__device__ float g_e[(size_t)BATCH * NN * MM];    // 128 MB

// ---------------------------------------------------------------------------
// 3x3 conv, stride 1, pad 1.  Tile: 64 co x 64 px (one output row h).
// 256 threads = 64 px * 4 co-groups; each thread accumulates 16 couts.
// grid: (H=64, C/64=4, B=8)
// ---------------------------------------------------------------------------
__global__ __launch_bounds__(256) void conv3_kernel(
    const float* __restrict__ x, const float* __restrict__ Wt,
    const float* __restrict__ bias, float* __restrict__ out)
{
    const int h   = blockIdx.x;
    const int co0 = blockIdx.y * 64;
    const int b   = blockIdx.z;
    const int tid = threadIdx.x;
    const int w0  = tid & 63;
    const int cg  = tid >> 6;          // 0..3
    const int cbase = cg * 16;

    __shared__ __align__(16) float sx[8][3][66];
    __shared__ __align__(16) float sw[8][9][64];

    float acc[16];
#pragma unroll
    for (int i = 0; i < 16; i++) acc[i] = 0.f;

    const float* xb = x + (size_t)b * CCH * (HH * WW);

    for (int c0 = 0; c0 < CCH; c0 += 8) {
        // x tile: 8 ci x 3 rows x 66 cols (zero-padded halo)
        for (int i = tid; i < 8 * 3 * 66; i += 256) {
            int ci  = i / (3 * 66);
            int r   = (i / 66) % 3;
            int col = i % 66;
            int gh = h + r - 1;
            int gw = col - 1;
            float v = 0.f;
            if ((unsigned)gh < HH && (unsigned)gw < WW)
                v = xb[(size_t)(c0 + ci) * (HH * WW) + gh * WW + gw];
            sx[ci][r][col] = v;
        }
        // weights: 8 ci x 9 k x 64 co  (co contiguous for float4 broadcast)
        for (int i = tid; i < 8 * 9 * 64; i += 256) {
            int ci = i / (9 * 64);
            int k  = (i / 64) % 9;
            int co = i % 64;
            sw[ci][k][co] = Wt[((size_t)(co0 + co) * CCH + (c0 + ci)) * 9 + k];
        }
        __syncthreads();

        for (int ci = 0; ci < 8; ci++) {
#pragma unroll
            for (int k = 0; k < 9; k++) {
                const int kh = k / 3, kw = k % 3;
                float xv = sx[ci][kh][w0 + kw];
                const float4* wp = reinterpret_cast<const float4*>(&sw[ci][k][cbase]);
                float4 a0 = wp[0], a1 = wp[1], a2 = wp[2], a3 = wp[3];
                acc[0]  = fmaf(xv, a0.x, acc[0]);
                acc[1]  = fmaf(xv, a0.y, acc[1]);
                acc[2]  = fmaf(xv, a0.z, acc[2]);
                acc[3]  = fmaf(xv, a0.w, acc[3]);
                acc[4]  = fmaf(xv, a1.x, acc[4]);
                acc[5]  = fmaf(xv, a1.y, acc[5]);
                acc[6]  = fmaf(xv, a1.z, acc[6]);
                acc[7]  = fmaf(xv, a1.w, acc[7]);
                acc[8]  = fmaf(xv, a2.x, acc[8]);
                acc[9]  = fmaf(xv, a2.y, acc[9]);
                acc[10] = fmaf(xv, a2.z, acc[10]);
                acc[11] = fmaf(xv, a2.w, acc[11]);
                acc[12] = fmaf(xv, a3.x, acc[12]);
                acc[13] = fmaf(xv, a3.y, acc[13]);
                acc[14] = fmaf(xv, a3.z, acc[14]);
                acc[15] = fmaf(xv, a3.w, acc[15]);
            }
        }
        __syncthreads();
    }

    float* ob = out + ((size_t)b * CCH + co0 + cbase) * NN + h * WW + w0;
#pragma unroll
    for (int i = 0; i < 16; i++)
        ob[(size_t)i * NN] = acc[i] + bias[co0 + cbase + i];
}

// ---------------------------------------------------------------------------
// 2x2 conv, stride 2, no pad.  Tile: 64 co x 32 px (one output row).
// 256 threads = 32 px * 8 co-groups; each thread accumulates 8 couts.
// grid: (HK=32, 4, 8)
// ---------------------------------------------------------------------------
__global__ __launch_bounds__(256) void conv2_kernel(
    const float* __restrict__ y, const float* __restrict__ Wt,
    const float* __restrict__ bias, float* __restrict__ out)
{
    const int h   = blockIdx.x;       // output row
    const int co0 = blockIdx.y * 64;
    const int b   = blockIdx.z;
    const int tid = threadIdx.x;
    const int w0  = tid & 31;
    const int cg  = tid >> 5;         // 0..7
    const int cbase = cg * 8;

    __shared__ __align__(16) float sy[8][2][64];
    __shared__ __align__(16) float sw[8][4][64];

    float acc[8];
#pragma unroll
    for (int i = 0; i < 8; i++) acc[i] = 0.f;

    const float* yb = y + (size_t)b * CCH * (HH * WW);

    for (int c0 = 0; c0 < CCH; c0 += 8) {
        for (int i = tid; i < 8 * 2 * 64; i += 256) {
            int ci  = i >> 7;
            int r   = (i >> 6) & 1;
            int col = i & 63;
            sy[ci][r][col] = yb[(size_t)(c0 + ci) * (HH * WW) + (2 * h + r) * WW + col];
        }
        for (int i = tid; i < 8 * 4 * 64; i += 256) {
            int ci = i >> 8;
            int k  = (i >> 6) & 3;
            int co = i & 63;
            sw[ci][k][co] = Wt[((size_t)(co0 + co) * CCH + (c0 + ci)) * 4 + k];
        }
        __syncthreads();

        for (int ci = 0; ci < 8; ci++) {
#pragma unroll
            for (int k = 0; k < 4; k++) {
                const int kh = k >> 1, kw = k & 1;
                float xv = sy[ci][kh][2 * w0 + kw];
                const float4* wp = reinterpret_cast<const float4*>(&sw[ci][k][cbase]);
                float4 a0 = wp[0], a1 = wp[1];
                acc[0] = fmaf(xv, a0.x, acc[0]);
                acc[1] = fmaf(xv, a0.y, acc[1]);
                acc[2] = fmaf(xv, a0.z, acc[2]);
                acc[3] = fmaf(xv, a0.w, acc[3]);
                acc[4] = fmaf(xv, a1.x, acc[4]);
                acc[5] = fmaf(xv, a1.y, acc[5]);
                acc[6] = fmaf(xv, a1.z, acc[6]);
                acc[7] = fmaf(xv, a1.w, acc[7]);
            }
        }
        __syncthreads();
    }

    float* ob = out + ((size_t)b * CCH + co0 + cbase) * MM + h * WK + w0;
#pragma unroll
    for (int i = 0; i < 8; i++)
        ob[(size_t)i * MM] = acc[i] + bias[co0 + cbase + i];
}

// ---------------------------------------------------------------------------
// GroupNorm(32 groups of 8 ch) + affine + SiLU, in place.
// One block per (b, group); two passes over the group's data.
// grid: B*32 blocks, 256 threads.
// ---------------------------------------------------------------------------
__global__ __launch_bounds__(256) void gn_silu_kernel(
    float* __restrict__ buf, const float* __restrict__ scale,
    const float* __restrict__ bias, int S)
{
    const int b = blockIdx.x >> 5;
    const int g = blockIdx.x & 31;
    float* base = buf + ((size_t)b * CCH + g * 8) * S;
    const int tot = 8 * S;
    const int tid = threadIdx.x;

    float s = 0.f, ss = 0.f;
    for (int i = tid; i < tot; i += 256) {
        float v = base[i];
        s += v;
        ss = fmaf(v, v, ss);
    }
    __shared__ float r1[256], r2[256];
    r1[tid] = s; r2[tid] = ss;
    __syncthreads();
    for (int st = 128; st > 0; st >>= 1) {
        if (tid < st) { r1[tid] += r1[tid + st]; r2[tid] += r2[tid + st]; }
        __syncthreads();
    }
    const float mu   = r1[0] / (float)tot;
    const float var  = r2[0] / (float)tot - mu * mu;
    const float rstd = rsqrtf(var + 1e-5f);

    for (int i = tid; i < tot; i += 256) {
        int c = g * 8 + i / S;
        float v = (base[i] - mu) * rstd * scale[c] + bias[c];
        base[i] = v / (1.f + __expf(-v));   // SiLU
    }
}

// ---------------------------------------------------------------------------
// E[b][n][m] = (1/16) * sum_c Q[b][c][n] * K[b][c][m]
// 64x64 tile, k-chunks of 16, 4x4 register micro-tile.
// grid: (M/64=16, N/64=64, B=8), 256 threads.
// ---------------------------------------------------------------------------
__global__ __launch_bounds__(256) void gemm_qk_kernel(
    const float* __restrict__ Q, const float* __restrict__ K,
    float* __restrict__ E)
{
    const int mb = blockIdx.x * 64;
    const int nb = blockIdx.y * 64;
    const int b  = blockIdx.z;
    const int tid = threadIdx.x;
    const int tx = tid & 15;     // m
    const int ty = tid >> 4;     // n

    __shared__ __align__(16) float sq[16][64];
    __shared__ __align__(16) float sk[16][64];

    float acc[4][4];
#pragma unroll
    for (int i = 0; i < 4; i++)
#pragma unroll
        for (int j = 0; j < 4; j++) acc[i][j] = 0.f;

    const float* Qb = Q + (size_t)b * CCH * NN;
    const float* Kb = K + (size_t)b * CCH * MM;

    for (int c0 = 0; c0 < CCH; c0 += 16) {
        for (int i = tid; i < 1024; i += 256) {
            int kc = i >> 6, nn2 = i & 63;
            sq[kc][nn2] = Qb[(size_t)(c0 + kc) * NN + nb + nn2];
        }
        for (int i = tid; i < 1024; i += 256) {
            int kc = i >> 6, mm2 = i & 63;
            sk[kc][mm2] = Kb[(size_t)(c0 + kc) * MM + mb + mm2];
        }
        __syncthreads();
#pragma unroll
        for (int kc = 0; kc < 16; kc++) {
            float4 a  = *reinterpret_cast<const float4*>(&sq[kc][ty * 4]);
            float4 bb = *reinterpret_cast<const float4*>(&sk[kc][tx * 4]);
            acc[0][0] = fmaf(a.x, bb.x, acc[0][0]);
            acc[0][1] = fmaf(a.x, bb.y, acc[0][1]);
            acc[0][2] = fmaf(a.x, bb.z, acc[0][2]);
            acc[0][3] = fmaf(a.x, bb.w, acc[0][3]);
            acc[1][0] = fmaf(a.y, bb.x, acc[1][0]);
            acc[1][1] = fmaf(a.y, bb.y, acc[1][1]);
            acc[1][2] = fmaf(a.y, bb.z, acc[1][2]);
            acc[1][3] = fmaf(a.y, bb.w, acc[1][3]);
            acc[2][0] = fmaf(a.z, bb.x, acc[2][0]);
            acc[2][1] = fmaf(a.z, bb.y, acc[2][1]);
            acc[2][2] = fmaf(a.z, bb.z, acc[2][2]);
            acc[2][3] = fmaf(a.z, bb.w, acc[2][3]);
            acc[3][0] = fmaf(a.w, bb.x, acc[3][0]);
            acc[3][1] = fmaf(a.w, bb.y, acc[3][1]);
            acc[3][2] = fmaf(a.w, bb.z, acc[3][2]);
            acc[3][3] = fmaf(a.w, bb.w, acc[3][3]);
        }
        __syncthreads();
    }

    const float scale = 0.0625f;  // 1/sqrt(256)
    float* Eb = E + ((size_t)b * NN + nb) * MM + mb;
#pragma unroll
    for (int i = 0; i < 4; i++) {
        float4 st;
        st.x = acc[i][0] * scale;
        st.y = acc[i][1] * scale;
        st.z = acc[i][2] * scale;
        st.w = acc[i][3] * scale;
        *reinterpret_cast<float4*>(&Eb[(size_t)(ty * 4 + i) * MM + tx * 4]) = st;
    }
}

// ---------------------------------------------------------------------------
// In-place softmax over last dim (M=1024). One block per row (b*N rows).
// ---------------------------------------------------------------------------
__global__ __launch_bounds__(256) void softmax_kernel(float* __restrict__ E)
{
    const size_t row = blockIdx.x;
    float* p = E + row * MM;
    const int tid = threadIdx.x;

    float v[4];
    float mx = -1e30f;
#pragma unroll
    for (int i = 0; i < 4; i++) {
        v[i] = p[tid + 256 * i];
        mx = fmaxf(mx, v[i]);
    }
    __shared__ float red[256];
    red[tid] = mx;
    __syncthreads();
    for (int s = 128; s > 0; s >>= 1) {
        if (tid < s) red[tid] = fmaxf(red[tid], red[tid + s]);
        __syncthreads();
    }
    mx = red[0];
    __syncthreads();

    float sum = 0.f;
#pragma unroll
    for (int i = 0; i < 4; i++) {
        v[i] = __expf(v[i] - mx);
        sum += v[i];
    }
    red[tid] = sum;
    __syncthreads();
    for (int s = 128; s > 0; s >>= 1) {
        if (tid < s) red[tid] += red[tid + s];
        __syncthreads();
    }
    float inv = 1.f / red[0];
#pragma unroll
    for (int i = 0; i < 4; i++)
        p[tid + 256 * i] = v[i] * inv;
}

// ---------------------------------------------------------------------------
// out[b][c][n] = gamma * sum_m V[b][c][m] * A[b][n][m]
// 64c x 64n tile, m-chunks of 16. Coalesced loads, padded smem (stride 68).
// grid: (N/64=64, C/64=4, B=8), 256 threads.
// ---------------------------------------------------------------------------
__global__ __launch_bounds__(256) void gemm_av_kernel(
    const float* __restrict__ V, const float* __restrict__ A,
    const float* __restrict__ gamma, float* __restrict__ out)
{
    const int nb = blockIdx.x * 64;
    const int cb = blockIdx.y * 64;
    const int b  = blockIdx.z;
    const int tid = threadIdx.x;
    const int tx = tid & 15;   // n
    const int ty = tid >> 4;   // c

    __shared__ __align__(16) float sv[16][68];
    __shared__ __align__(16) float sa[16][68];

    float acc[4][4];
#pragma unroll
    for (int i = 0; i < 4; i++)
#pragma unroll
        for (int j = 0; j < 4; j++) acc[i][j] = 0.f;

    const float* Vb = V + (size_t)b * CCH * MM;
    const float* Ab = A + (size_t)b * NN * MM;

    for (int m0 = 0; m0 < MM; m0 += 16) {
        for (int i = tid; i < 1024; i += 256) {
            int mk = i & 15, cc = i >> 4;
            sv[mk][cc] = Vb[(size_t)(cb + cc) * MM + m0 + mk];
        }
        for (int i = tid; i < 1024; i += 256) {
            int mk = i & 15, nn2 = i >> 4;
            sa[mk][nn2] = Ab[(size_t)(nb + nn2) * MM + m0 + mk];
        }
        __syncthreads();
#pragma unroll
        for (int kc = 0; kc < 16; kc++) {
            float4 a  = *reinterpret_cast<const float4*>(&sv[kc][ty * 4]);  // c
            float4 bb = *reinterpret_cast<const float4*>(&sa[kc][tx * 4]);  // n
            acc[0][0] = fmaf(a.x, bb.x, acc[0][0]);
            acc[0][1] = fmaf(a.x, bb.y, acc[0][1]);
            acc[0][2] = fmaf(a.x, bb.z, acc[0][2]);
            acc[0][3] = fmaf(a.x, bb.w, acc[0][3]);
            acc[1][0] = fmaf(a.y, bb.x, acc[1][0]);
            acc[1][1] = fmaf(a.y, bb.y, acc[1][1]);
            acc[1][2] = fmaf(a.y, bb.z, acc[1][2]);
            acc[1][3] = fmaf(a.y, bb.w, acc[1][3]);
            acc[2][0] = fmaf(a.z, bb.x, acc[2][0]);
            acc[2][1] = fmaf(a.z, bb.y, acc[2][1]);
            acc[2][2] = fmaf(a.z, bb.z, acc[2][2]);
            acc[2][3] = fmaf(a.z, bb.w, acc[2][3]);
            acc[3][0] = fmaf(a.w, bb.x, acc[3][0]);
            acc[3][1] = fmaf(a.w, bb.y, acc[3][1]);
            acc[3][2] = fmaf(a.w, bb.z, acc[3][2]);
            acc[3][3] = fmaf(a.w, bb.w, acc[3][3]);
        }
        __syncthreads();
    }

    const float gm = gamma[0];
#pragma unroll
    for (int i = 0; i < 4; i++) {
        int c = cb + ty * 4 + i;
        float4 st;
        st.x = gm * acc[i][0];
        st.y = gm * acc[i][1];
        st.z = gm * acc[i][2];
        st.w = gm * acc[i][3];
        *reinterpret_cast<float4*>(&out[((size_t)b * CCH + c) * NN + nb + tx * 4]) = st;
    }
}

// ---------------------------------------------------------------------------
extern "C" void kernel_launch(void* const* d_in, const int* in_sizes, int n_in,
                              void* d_out, int out_size)
{
    const float* x        = (const float*)d_in[0];
    const float* y        = (const float*)d_in[1];
    const float* Wq       = (const float*)d_in[2];
    const float* bq       = (const float*)d_in[3];
    const float* gq_scale = (const float*)d_in[4];
    const float* gq_bias  = (const float*)d_in[5];
    const float* Wk       = (const float*)d_in[6];
    const float* bk       = (const float*)d_in[7];
    const float* gk_scale = (const float*)d_in[8];
    const float* gk_bias  = (const float*)d_in[9];
    const float* Wv       = (const float*)d_in[10];
    const float* bv       = (const float*)d_in[11];
    const float* gv_scale = (const float*)d_in[12];
    const float* gv_bias  = (const float*)d_in[13];
    const float* gamma    = (const float*)d_in[14];
    float* out = (float*)d_out;

    float *qp = nullptr, *kp = nullptr, *vp = nullptr, *ep = nullptr;
    cudaGetSymbolAddress((void**)&qp, g_q);
    cudaGetSymbolAddress((void**)&kp, g_k);
    cudaGetSymbolAddress((void**)&vp, g_v);
    cudaGetSymbolAddress((void**)&ep, g_e);

    // Projections (raw conv + bias)
    conv3_kernel<<<dim3(HH, CCH / 64, BATCH), 256>>>(x, Wq, bq, qp);
    conv2_kernel<<<dim3(HK, CCH / 64, BATCH), 256>>>(y, Wk, bk, kp);
    conv2_kernel<<<dim3(HK, CCH / 64, BATCH), 256>>>(y, Wv, bv, vp);

    // GroupNorm + SiLU, in place
    gn_silu_kernel<<<BATCH * 32, 256>>>(qp, gq_scale, gq_bias, NN);
    gn_silu_kernel<<<BATCH * 32, 256>>>(kp, gk_scale, gk_bias, MM);
    gn_silu_kernel<<<BATCH * 32, 256>>>(vp, gv_scale, gv_bias, MM);

    // Attention
    gemm_qk_kernel<<<dim3(MM / 64, NN / 64, BATCH), 256>>>(qp, kp, ep);
    softmax_kernel<<<BATCH * NN, 256>>>(ep);
    gemm_av_kernel<<<dim3(NN / 64, CCH / 64, BATCH), 256>>>(vp, ep, gamma, out);
}

// round 2
// speedup vs baseline: 1.4041x; 1.4041x over previous
#include <cuda_runtime.h>
#include <math.h>

#define BATCH 8
#define CCH   256
#define HH    64
#define WW    64
#define NN    4096   // HH*WW
#define MM    1024   // (HH/2)*(WW/2)
#define HK    32
#define WK    32

typedef unsigned long long u64;

__device__ __forceinline__ u64 pk2(float lo, float hi) {
    u64 r; asm("mov.b64 %0,{%1,%2};" : "=l"(r) : "f"(lo), "f"(hi)); return r;
}
__device__ __forceinline__ float2 upk2(u64 v) {
    float2 f; asm("mov.b64 {%0,%1},%2;" : "=f"(f.x), "=f"(f.y) : "l"(v)); return f;
}
__device__ __forceinline__ u64 ffma2(u64 a, u64 b, u64 c) {
    u64 d; asm("fma.rn.f32x2 %0,%1,%2,%3;" : "=l"(d) : "l"(a), "l"(b), "l"(c)); return d;
}

// Scratch
__device__ float g_q[(size_t)BATCH * CCH * NN];   // 32 MB
__device__ float g_k[(size_t)BATCH * CCH * MM];   // 8 MB
__device__ float g_v[(size_t)BATCH * CCH * MM];   // 8 MB
__device__ float g_e[(size_t)BATCH * NN * MM];    // 128 MB

// ---------------------------------------------------------------------------
// 3x3 conv, stride 1, pad 1.  Tile: 64 co x 64 px (one output row h).
// 256 threads = 32 px-groups (2 px each) x 8 co-groups (8 co each).
// Each thread: 2 px x 8 co via 8 FFMA2 per (ci,k).
// grid: (H=64, C/64=4, B=8)
// ---------------------------------------------------------------------------
__global__ __launch_bounds__(256) void conv3_kernel(
    const float* __restrict__ x, const float* __restrict__ Wt,
    const float* __restrict__ bias, float* __restrict__ out)
{
    const int h   = blockIdx.x;
    const int co0 = blockIdx.y * 64;
    const int b   = blockIdx.z;
    const int tid = threadIdx.x;
    const int w0  = tid & 31;
    const int cg  = tid >> 5;          // 0..7
    const int cbase = cg * 8;

    __shared__ __align__(16) float sx[8][3][66];
    __shared__ __align__(16) float sw[8][9][64];

    u64 acc0[4], acc1[4];
#pragma unroll
    for (int j = 0; j < 4; j++) { acc0[j] = 0ULL; acc1[j] = 0ULL; }

    const float* xb = x + (size_t)b * CCH * (HH * WW);

    for (int c0 = 0; c0 < CCH; c0 += 8) {
        for (int i = tid; i < 8 * 3 * 66; i += 256) {
            int ci  = i / (3 * 66);
            int r   = (i / 66) % 3;
            int col = i % 66;
            int gh = h + r - 1;
            int gw = col - 1;
            float v = 0.f;
            if ((unsigned)gh < HH && (unsigned)gw < WW)
                v = xb[(size_t)(c0 + ci) * (HH * WW) + gh * WW + gw];
            sx[ci][r][col] = v;
        }
        for (int i = tid; i < 8 * 9 * 64; i += 256) {
            int ci = i / (9 * 64);
            int k  = (i / 64) % 9;
            int co = i % 64;
            sw[ci][k][co] = Wt[((size_t)(co0 + co) * CCH + (c0 + ci)) * 9 + k];
        }
        __syncthreads();

        for (int ci = 0; ci < 8; ci++) {
#pragma unroll
            for (int k = 0; k < 9; k++) {
                const int kh = k / 3, kw = k % 3;
                float xv0 = sx[ci][kh][w0 + kw];
                float xv1 = sx[ci][kh][w0 + 32 + kw];
                const float4* wp = reinterpret_cast<const float4*>(&sw[ci][k][cbase]);
                float4 wA = wp[0], wB = wp[1];
                u64 w0p = pk2(wA.x, wA.y), w1p = pk2(wA.z, wA.w);
                u64 w2p = pk2(wB.x, wB.y), w3p = pk2(wB.z, wB.w);
                u64 x0 = pk2(xv0, xv0), x1 = pk2(xv1, xv1);
                acc0[0] = ffma2(x0, w0p, acc0[0]);
                acc0[1] = ffma2(x0, w1p, acc0[1]);
                acc0[2] = ffma2(x0, w2p, acc0[2]);
                acc0[3] = ffma2(x0, w3p, acc0[3]);
                acc1[0] = ffma2(x1, w0p, acc1[0]);
                acc1[1] = ffma2(x1, w1p, acc1[1]);
                acc1[2] = ffma2(x1, w2p, acc1[2]);
                acc1[3] = ffma2(x1, w3p, acc1[3]);
            }
        }
        __syncthreads();
    }

    float* ob = out + ((size_t)b * CCH + co0 + cbase) * NN + h * WW + w0;
#pragma unroll
    for (int j = 0; j < 4; j++) {
        float2 f0 = upk2(acc0[j]);
        float2 f1 = upk2(acc1[j]);
        float b0v = bias[co0 + cbase + 2 * j];
        float b1v = bias[co0 + cbase + 2 * j + 1];
        ob[(size_t)(2 * j) * NN]          = f0.x + b0v;
        ob[(size_t)(2 * j) * NN + 32]     = f1.x + b0v;
        ob[(size_t)(2 * j + 1) * NN]      = f0.y + b1v;
        ob[(size_t)(2 * j + 1) * NN + 32] = f1.y + b1v;
    }
}

// ---------------------------------------------------------------------------
// 2x2 conv, stride 2, no pad.  Tile: 64 co x 64 px (two output rows).
// 256 threads = 32 px-groups x 8 co-groups; thread: 2 px (rows h0,h0+1) x 8 co.
// grid: (HK/2=16, 4, 8)
// ---------------------------------------------------------------------------
__global__ __launch_bounds__(256) void conv2_kernel(
    const float* __restrict__ y, const float* __restrict__ Wt,
    const float* __restrict__ bias, float* __restrict__ out)
{
    const int h0  = blockIdx.x * 2;   // first output row
    const int co0 = blockIdx.y * 64;
    const int b   = blockIdx.z;
    const int tid = threadIdx.x;
    const int w0  = tid & 31;
    const int cg  = tid >> 5;
    const int cbase = cg * 8;

    __shared__ __align__(16) float sy[8][4][64];
    __shared__ __align__(16) float sw[8][4][64];

    u64 acc0[4], acc1[4];
#pragma unroll
    for (int j = 0; j < 4; j++) { acc0[j] = 0ULL; acc1[j] = 0ULL; }

    const float* yb = y + (size_t)b * CCH * (HH * WW);

    for (int c0 = 0; c0 < CCH; c0 += 8) {
        for (int i = tid; i < 8 * 4 * 64; i += 256) {
            int ci  = i >> 8;
            int r   = (i >> 6) & 3;
            int col = i & 63;
            sy[ci][r][col] = yb[(size_t)(c0 + ci) * (HH * WW) + (2 * h0 + r) * WW + col];
        }
        for (int i = tid; i < 8 * 4 * 64; i += 256) {
            int ci = i >> 8;
            int k  = (i >> 6) & 3;
            int co = i & 63;
            sw[ci][k][co] = Wt[((size_t)(co0 + co) * CCH + (c0 + ci)) * 4 + k];
        }
        __syncthreads();

        for (int ci = 0; ci < 8; ci++) {
#pragma unroll
            for (int k = 0; k < 4; k++) {
                const int kh = k >> 1, kw = k & 1;
                float xv0 = sy[ci][kh][2 * w0 + kw];
                float xv1 = sy[ci][2 + kh][2 * w0 + kw];
                const float4* wp = reinterpret_cast<const float4*>(&sw[ci][k][cbase]);
                float4 wA = wp[0], wB = wp[1];
                u64 w0p = pk2(wA.x, wA.y), w1p = pk2(wA.z, wA.w);
                u64 w2p = pk2(wB.x, wB.y), w3p = pk2(wB.z, wB.w);
                u64 x0 = pk2(xv0, xv0), x1 = pk2(xv1, xv1);
                acc0[0] = ffma2(x0, w0p, acc0[0]);
                acc0[1] = ffma2(x0, w1p, acc0[1]);
                acc0[2] = ffma2(x0, w2p, acc0[2]);
                acc0[3] = ffma2(x0, w3p, acc0[3]);
                acc1[0] = ffma2(x1, w0p, acc1[0]);
                acc1[1] = ffma2(x1, w1p, acc1[1]);
                acc1[2] = ffma2(x1, w2p, acc1[2]);
                acc1[3] = ffma2(x1, w3p, acc1[3]);
            }
        }
        __syncthreads();
    }

    float* ob = out + ((size_t)b * CCH + co0 + cbase) * MM + h0 * WK + w0;
#pragma unroll
    for (int j = 0; j < 4; j++) {
        float2 f0 = upk2(acc0[j]);   // row h0
        float2 f1 = upk2(acc1[j]);   // row h0+1
        float b0v = bias[co0 + cbase + 2 * j];
        float b1v = bias[co0 + cbase + 2 * j + 1];
        ob[(size_t)(2 * j) * MM]          = f0.x + b0v;
        ob[(size_t)(2 * j) * MM + WK]     = f1.x + b0v;
        ob[(size_t)(2 * j + 1) * MM]      = f0.y + b1v;
        ob[(size_t)(2 * j + 1) * MM + WK] = f1.y + b1v;
    }
}

// ---------------------------------------------------------------------------
// GroupNorm(32 groups of 8 ch) + affine + SiLU, in place. float4, 512 thr.
// ---------------------------------------------------------------------------
__global__ __launch_bounds__(512) void gn_silu_kernel(
    float* __restrict__ buf, const float* __restrict__ scale,
    const float* __restrict__ bias, int S)
{
    const int b = blockIdx.x >> 5;
    const int g = blockIdx.x & 31;
    float* base = buf + ((size_t)b * CCH + g * 8) * S;
    float4* p4 = reinterpret_cast<float4*>(base);
    const int tot4 = (8 * S) >> 2;
    const int tid = threadIdx.x;

    float s = 0.f, ss = 0.f;
    for (int i = tid; i < tot4; i += 512) {
        float4 v = p4[i];
        s += v.x + v.y + v.z + v.w;
        ss = fmaf(v.x, v.x, ss);
        ss = fmaf(v.y, v.y, ss);
        ss = fmaf(v.z, v.z, ss);
        ss = fmaf(v.w, v.w, ss);
    }
    __shared__ float r1[512], r2[512];
    r1[tid] = s; r2[tid] = ss;
    __syncthreads();
    for (int st = 256; st > 0; st >>= 1) {
        if (tid < st) { r1[tid] += r1[tid + st]; r2[tid] += r2[tid + st]; }
        __syncthreads();
    }
    const float tot = (float)(8 * S);
    const float mu   = r1[0] / tot;
    const float var  = r2[0] / tot - mu * mu;
    const float rstd = rsqrtf(var + 1e-5f);

    const int s4 = S >> 2;
    for (int i = tid; i < tot4; i += 512) {
        int c = g * 8 + i / s4;
        float sc = scale[c] * rstd, bi = bias[c] - mu * scale[c] * rstd;
        float4 v = p4[i];
        v.x = fmaf(v.x, sc, bi);
        v.y = fmaf(v.y, sc, bi);
        v.z = fmaf(v.z, sc, bi);
        v.w = fmaf(v.w, sc, bi);
        v.x = v.x / (1.f + __expf(-v.x));
        v.y = v.y / (1.f + __expf(-v.y));
        v.z = v.z / (1.f + __expf(-v.z));
        v.w = v.w / (1.f + __expf(-v.w));
        p4[i] = v;
    }
}

// ---------------------------------------------------------------------------
// E[b][n][m] = (1/16) * sum_c Q[b][c][n] * K[b][c][m]
// 128x128 tile, k-chunk 16, 8x8 micro-tile via FFMA2.
// grid: (M/128=8, N/128=32, B=8), 256 threads.
// ---------------------------------------------------------------------------
__global__ __launch_bounds__(256) void gemm_qk_kernel(
    const float* __restrict__ Q, const float* __restrict__ K,
    float* __restrict__ E)
{
    const int mb = blockIdx.x * 128;
    const int nb = blockIdx.y * 128;
    const int b  = blockIdx.z;
    const int tid = threadIdx.x;
    const int tx = tid & 15;     // m-group
    const int ty = tid >> 4;     // n-group

    __shared__ __align__(16) float sq[16][128];
    __shared__ __align__(16) float sk[16][128];

    u64 acc[8][4];
#pragma unroll
    for (int i = 0; i < 8; i++)
#pragma unroll
        for (int j = 0; j < 4; j++) acc[i][j] = 0ULL;

    const float* Qb = Q + (size_t)b * CCH * NN + nb;
    const float* Kb = K + (size_t)b * CCH * MM + mb;

    for (int c0 = 0; c0 < CCH; c0 += 16) {
#pragma unroll
        for (int r = 0; r < 2; r++) {
            int s = tid + r * 256;
            int kc = s >> 5, col = (s & 31) * 4;
            *reinterpret_cast<float4*>(&sq[kc][col]) =
                *reinterpret_cast<const float4*>(&Qb[(size_t)(c0 + kc) * NN + col]);
            *reinterpret_cast<float4*>(&sk[kc][col]) =
                *reinterpret_cast<const float4*>(&Kb[(size_t)(c0 + kc) * MM + col]);
        }
        __syncthreads();
#pragma unroll
        for (int kc = 0; kc < 16; kc++) {
            float4 a0 = *reinterpret_cast<const float4*>(&sq[kc][ty * 8]);
            float4 a1 = *reinterpret_cast<const float4*>(&sq[kc][ty * 8 + 4]);
            float4 b0 = *reinterpret_cast<const float4*>(&sk[kc][tx * 8]);
            float4 b1 = *reinterpret_cast<const float4*>(&sk[kc][tx * 8 + 4]);
            u64 bp0 = pk2(b0.x, b0.y), bp1 = pk2(b0.z, b0.w);
            u64 bp2 = pk2(b1.x, b1.y), bp3 = pk2(b1.z, b1.w);
            float av[8] = {a0.x, a0.y, a0.z, a0.w, a1.x, a1.y, a1.z, a1.w};
#pragma unroll
            for (int i = 0; i < 8; i++) {
                u64 ad = pk2(av[i], av[i]);
                acc[i][0] = ffma2(ad, bp0, acc[i][0]);
                acc[i][1] = ffma2(ad, bp1, acc[i][1]);
                acc[i][2] = ffma2(ad, bp2, acc[i][2]);
                acc[i][3] = ffma2(ad, bp3, acc[i][3]);
            }
        }
        __syncthreads();
    }

    const float scale = 0.0625f;  // 1/sqrt(256)
    float* Eb = E + ((size_t)b * NN + nb) * MM + mb;
#pragma unroll
    for (int i = 0; i < 8; i++) {
        float2 c0 = upk2(acc[i][0]), c1 = upk2(acc[i][1]);
        float2 c2 = upk2(acc[i][2]), c3 = upk2(acc[i][3]);
        float4 s0 = {c0.x * scale, c0.y * scale, c1.x * scale, c1.y * scale};
        float4 s1 = {c2.x * scale, c2.y * scale, c3.x * scale, c3.y * scale};
        float* row = Eb + (size_t)(ty * 8 + i) * MM + tx * 8;
        *reinterpret_cast<float4*>(row)     = s0;
        *reinterpret_cast<float4*>(row + 4) = s1;
    }
}

// ---------------------------------------------------------------------------
// In-place softmax over last dim (M=1024). One block per row, float4.
// ---------------------------------------------------------------------------
__global__ __launch_bounds__(256) void softmax_kernel(float* __restrict__ E)
{
    float4* p = reinterpret_cast<float4*>(E + (size_t)blockIdx.x * MM);
    const int tid = threadIdx.x;

    float4 v = p[tid];
    float mx = fmaxf(fmaxf(v.x, v.y), fmaxf(v.z, v.w));
    __shared__ float red[256];
    red[tid] = mx;
    __syncthreads();
    for (int s = 128; s > 0; s >>= 1) {
        if (tid < s) red[tid] = fmaxf(red[tid], red[tid + s]);
        __syncthreads();
    }
    mx = red[0];
    __syncthreads();

    v.x = __expf(v.x - mx);
    v.y = __expf(v.y - mx);
    v.z = __expf(v.z - mx);
    v.w = __expf(v.w - mx);
    float sum = v.x + v.y + v.z + v.w;
    red[tid] = sum;
    __syncthreads();
    for (int s = 128; s > 0; s >>= 1) {
        if (tid < s) red[tid] += red[tid + s];
        __syncthreads();
    }
    float inv = 1.f / red[0];
    v.x *= inv; v.y *= inv; v.z *= inv; v.w *= inv;
    p[tid] = v;
}

// ---------------------------------------------------------------------------
// out[b][c][n] = gamma * sum_m V[b][c][m] * A[b][n][m]
// 128c x 128n tile, m-chunk 16, 8x8 micro-tile via FFMA2. Transposed staging.
// grid: (N/128=32, C/128=2, B=8), 256 threads.
// ---------------------------------------------------------------------------
__global__ __launch_bounds__(256) void gemm_av_kernel(
    const float* __restrict__ V, const float* __restrict__ A,
    const float* __restrict__ gamma, float* __restrict__ out)
{
    const int nb = blockIdx.x * 128;
    const int cb = blockIdx.y * 128;
    const int b  = blockIdx.z;
    const int tid = threadIdx.x;
    const int tx = tid & 15;   // n-group
    const int ty = tid >> 4;   // c-group

    __shared__ float sv[16][132];
    __shared__ float sa[16][132];

    u64 acc[8][4];
#pragma unroll
    for (int i = 0; i < 8; i++)
#pragma unroll
        for (int j = 0; j < 4; j++) acc[i][j] = 0ULL;

    const float* Vb = V + (size_t)b * CCH * MM;
    const float* Ab = A + (size_t)b * NN * MM;

    for (int m0 = 0; m0 < MM; m0 += 16) {
#pragma unroll
        for (int r = 0; r < 2; r++) {
            int s = tid + r * 256;      // 0..511
            int row = s >> 2, f = s & 3;
            float4 vv = *reinterpret_cast<const float4*>(&Vb[(size_t)(cb + row) * MM + m0 + f * 4]);
            sv[f * 4 + 0][row] = vv.x;
            sv[f * 4 + 1][row] = vv.y;
            sv[f * 4 + 2][row] = vv.z;
            sv[f * 4 + 3][row] = vv.w;
            float4 aa = *reinterpret_cast<const float4*>(&Ab[(size_t)(nb + row) * MM + m0 + f * 4]);
            sa[f * 4 + 0][row] = aa.x;
            sa[f * 4 + 1][row] = aa.y;
            sa[f * 4 + 2][row] = aa.z;
            sa[f * 4 + 3][row] = aa.w;
        }
        __syncthreads();
#pragma unroll
        for (int kc = 0; kc < 16; kc++) {
            float4 a0 = *reinterpret_cast<const float4*>(&sv[kc][ty * 8]);
            float4 a1 = *reinterpret_cast<const float4*>(&sv[kc][ty * 8 + 4]);
            float4 b0 = *reinterpret_cast<const float4*>(&sa[kc][tx * 8]);
            float4 b1 = *reinterpret_cast<const float4*>(&sa[kc][tx * 8 + 4]);
            u64 bp0 = pk2(b0.x, b0.y), bp1 = pk2(b0.z, b0.w);
            u64 bp2 = pk2(b1.x, b1.y), bp3 = pk2(b1.z, b1.w);
            float av[8] = {a0.x, a0.y, a0.z, a0.w, a1.x, a1.y, a1.z, a1.w};
#pragma unroll
            for (int i = 0; i < 8; i++) {
                u64 ad = pk2(av[i], av[i]);
                acc[i][0] = ffma2(ad, bp0, acc[i][0]);
                acc[i][1] = ffma2(ad, bp1, acc[i][1]);
                acc[i][2] = ffma2(ad, bp2, acc[i][2]);
                acc[i][3] = ffma2(ad, bp3, acc[i][3]);
            }
        }
        __syncthreads();
    }

    const float gm = gamma[0];
#pragma unroll
    for (int i = 0; i < 8; i++) {
        int c = cb + ty * 8 + i;
        float2 c0 = upk2(acc[i][0]), c1 = upk2(acc[i][1]);
        float2 c2 = upk2(acc[i][2]), c3 = upk2(acc[i][3]);
        float4 s0 = {gm * c0.x, gm * c0.y, gm * c1.x, gm * c1.y};
        float4 s1 = {gm * c2.x, gm * c2.y, gm * c3.x, gm * c3.y};
        float* row = out + ((size_t)b * CCH + c) * NN + nb + tx * 8;
        *reinterpret_cast<float4*>(row)     = s0;
        *reinterpret_cast<float4*>(row + 4) = s1;
    }
}

// ---------------------------------------------------------------------------
extern "C" void kernel_launch(void* const* d_in, const int* in_sizes, int n_in,
                              void* d_out, int out_size)
{
    const float* x        = (const float*)d_in[0];
    const float* y        = (const float*)d_in[1];
    const float* Wq       = (const float*)d_in[2];
    const float* bq       = (const float*)d_in[3];
    const float* gq_scale = (const float*)d_in[4];
    const float* gq_bias  = (const float*)d_in[5];
    const float* Wk       = (const float*)d_in[6];
    const float* bk       = (const float*)d_in[7];
    const float* gk_scale = (const float*)d_in[8];
    const float* gk_bias  = (const float*)d_in[9];
    const float* Wv       = (const float*)d_in[10];
    const float* bv       = (const float*)d_in[11];
    const float* gv_scale = (const float*)d_in[12];
    const float* gv_bias  = (const float*)d_in[13];
    const float* gamma    = (const float*)d_in[14];
    float* out = (float*)d_out;

    float *qp = nullptr, *kp = nullptr, *vp = nullptr, *ep = nullptr;
    cudaGetSymbolAddress((void**)&qp, g_q);
    cudaGetSymbolAddress((void**)&kp, g_k);
    cudaGetSymbolAddress((void**)&vp, g_v);
    cudaGetSymbolAddress((void**)&ep, g_e);

    conv3_kernel<<<dim3(HH, CCH / 64, BATCH), 256>>>(x, Wq, bq, qp);
    conv2_kernel<<<dim3(HK / 2, CCH / 64, BATCH), 256>>>(y, Wk, bk, kp);
    conv2_kernel<<<dim3(HK / 2, CCH / 64, BATCH), 256>>>(y, Wv, bv, vp);

    gn_silu_kernel<<<BATCH * 32, 512>>>(qp, gq_scale, gq_bias, NN);
    gn_silu_kernel<<<BATCH * 32, 512>>>(kp, gk_scale, gk_bias, MM);
    gn_silu_kernel<<<BATCH * 32, 512>>>(vp, gv_scale, gv_bias, MM);

    gemm_qk_kernel<<<dim3(MM / 128, NN / 128, BATCH), 256>>>(qp, kp, ep);
    softmax_kernel<<<BATCH * NN, 256>>>(ep);
    gemm_av_kernel<<<dim3(NN / 128, CCH / 128, BATCH), 256>>>(vp, ep, gamma, out);
}

// round 3
// speedup vs baseline: 3.6225x; 2.5800x over previous
#include <cuda_runtime.h>
#include <math.h>

#define BATCH 8
#define CCH   256
#define HH    64
#define WW    64
#define NN    4096   // HH*WW
#define MM    1024   // (HH/2)*(WW/2)
#define HK    32
#define WK    32

typedef unsigned long long u64;
typedef unsigned int u32;

__device__ __forceinline__ u64 pk2(float lo, float hi) {
    u64 r; asm("mov.b64 %0,{%1,%2};" : "=l"(r) : "f"(lo), "f"(hi)); return r;
}
__device__ __forceinline__ float2 upk2(u64 v) {
    float2 f; asm("mov.b64 {%0,%1},%2;" : "=f"(f.x), "=f"(f.y) : "l"(v)); return f;
}
__device__ __forceinline__ u64 ffma2(u64 a, u64 b, u64 c) {
    u64 d; asm("fma.rn.f32x2 %0,%1,%2,%3;" : "=l"(d) : "l"(a), "l"(b), "l"(c)); return d;
}
__device__ __forceinline__ u32 f2tf(float f) {
    u32 u; asm("cvt.rna.tf32.f32 %0,%1;" : "=r"(u) : "f"(f)); return u;
}
__device__ __forceinline__ void mma_tf32(float* d, const u32* a, const u32* b) {
    asm volatile(
        "mma.sync.aligned.m16n8k8.row.col.f32.tf32.tf32.f32 "
        "{%0,%1,%2,%3},{%4,%5,%6,%7},{%8,%9},{%0,%1,%2,%3};"
        : "+f"(d[0]), "+f"(d[1]), "+f"(d[2]), "+f"(d[3])
        : "r"(a[0]), "r"(a[1]), "r"(a[2]), "r"(a[3]), "r"(b[0]), "r"(b[1]));
}

// Scratch
__device__ float g_q[(size_t)BATCH * CCH * NN];   // 32 MB
__device__ float g_k[(size_t)BATCH * CCH * MM];   // 8 MB
__device__ float g_v[(size_t)BATCH * CCH * MM];   // 8 MB
__device__ float g_e[(size_t)BATCH * NN * MM];    // 128 MB
__device__ u32   g_wt[9 * 256 * 256];             // transposed Wq as tf32

// ---------------------------------------------------------------------------
// Transpose Wq (OIHW [co][ci][3][3]) -> g_wt[k][ci][co] as tf32. One-time.
// ---------------------------------------------------------------------------
__global__ __launch_bounds__(256) void transpose_w3(
    const float* __restrict__ Wt, u32* __restrict__ wt2)
{
    int i = blockIdx.x * 256 + threadIdx.x;   // over 9*256*256
    if (i < 9 * 256 * 256) {
        int co = i & 255;
        int ci = (i >> 8) & 255;
        int k  = i >> 16;
        wt2[i] = f2tf(Wt[((size_t)co * 256 + ci) * 9 + k]);
    }
}

// ---------------------------------------------------------------------------
// 3x3 conv s1 p1 as implicit GEMM on tensor cores (tf32).
// Block: 64 co x 128 px (2 output rows). 8 warps: (co 2 x px 4), warp tile
// 32co x 32px. K = 256ci x 9k, ci-chunks of 8.
// grid: (HH/2=32, CCH/64=4, B=8)
// ---------------------------------------------------------------------------
__global__ __launch_bounds__(256) void conv3_mma(
    const u32* __restrict__ wt2, const float* __restrict__ x,
    const float* __restrict__ bias, float* __restrict__ out)
{
    const int h0  = blockIdx.x * 2;
    const int co0 = blockIdx.y * 64;
    const int b   = blockIdx.z;
    const int tid  = threadIdx.x;
    const int lane = tid & 31;
    const int w    = tid >> 5;
    const int gid  = lane >> 2;
    const int ctid = lane & 3;
    const int co_base = (w >> 2) * 32;
    const int px_base = (w & 3) * 32;

    __shared__ u32 sxt[4 * 8 * 72];   // [r 0..3][ci 0..7][col 0..65 pad 72]
    __shared__ u32 swt[8 * 9 * 72];   // [ci][k][co 0..63 pad 72]

    float acc[2][4][4];
#pragma unroll
    for (int i = 0; i < 2; i++)
#pragma unroll
        for (int j = 0; j < 4; j++)
#pragma unroll
            for (int l = 0; l < 4; l++) acc[i][j][l] = 0.f;

    const float* xb = x + (size_t)b * CCH * (HH * WW);

    for (int ci0 = 0; ci0 < CCH; ci0 += 8) {
        // stage x tile: rows h0-1..h0+2, cols -1..64 (zero halo), tf32
        for (int i = tid; i < 4 * 8 * 66; i += 256) {
            int r   = i / (8 * 66);
            int ci  = (i / 66) & 7;
            int col = i % 66;
            int gh = h0 - 1 + r;
            int gw = col - 1;
            float v = 0.f;
            if ((unsigned)gh < HH && (unsigned)gw < WW)
                v = xb[(size_t)(ci0 + ci) * (HH * WW) + gh * WW + gw];
            sxt[(r * 8 + ci) * 72 + col] = f2tf(v);
        }
        // stage weights: swt[ci][k][co], coalesced uint4 from g_wt[k][ci][co]
        for (int i = tid; i < 8 * 9 * 16; i += 256) {
            int k   = i / 128;          // 0..8
            int ci  = (i >> 4) & 7;
            int co4 = (i & 15) * 4;
            uint4 v = *reinterpret_cast<const uint4*>(
                &wt2[((size_t)k * 256 + ci0 + ci) * 256 + co0 + co4]);
            *reinterpret_cast<uint4*>(&swt[(ci * 9 + k) * 72 + co4]) = v;
        }
        __syncthreads();

#pragma unroll
        for (int k = 0; k < 9; k++) {
            const int kh = k / 3, kw = k % 3;
            u32 a[2][4];
#pragma unroll
            for (int rm = 0; rm < 2; rm++) {
                int cof = co_base + rm * 16;
                a[rm][0] = swt[((ctid) * 9 + k) * 72 + cof + gid];
                a[rm][1] = swt[((ctid) * 9 + k) * 72 + cof + gid + 8];
                a[rm][2] = swt[((ctid + 4) * 9 + k) * 72 + cof + gid];
                a[rm][3] = swt[((ctid + 4) * 9 + k) * 72 + cof + gid + 8];
            }
#pragma unroll
            for (int f = 0; f < 4; f++) {
                int px = px_base + f * 8 + gid;
                int rl = px >> 6;
                int wc = (px & 63) + kw;
                u32 bf[2];
                bf[0] = sxt[((rl + kh) * 8 + ctid) * 72 + wc];
                bf[1] = sxt[((rl + kh) * 8 + ctid + 4) * 72 + wc];
                mma_tf32(acc[0][f], a[0], bf);
                mma_tf32(acc[1][f], a[1], bf);
            }
        }
        __syncthreads();
    }

    // epilogue: add bias, store
#pragma unroll
    for (int rm = 0; rm < 2; rm++) {
#pragma unroll
        for (int f = 0; f < 4; f++) {
            int coA = co0 + co_base + rm * 16 + gid;
            int coB = coA + 8;
            int px  = px_base + f * 8 + 2 * ctid;
            int n   = (h0 + (px >> 6)) * WW + (px & 63);
            float bA = bias[coA], bB = bias[coB];
            float2 sA = {acc[rm][f][0] + bA, acc[rm][f][1] + bA};
            float2 sB = {acc[rm][f][2] + bB, acc[rm][f][3] + bB};
            *reinterpret_cast<float2*>(&out[((size_t)b * CCH + coA) * NN + n]) = sA;
            *reinterpret_cast<float2*>(&out[((size_t)b * CCH + coB) * NN + n]) = sB;
        }
    }
}

// ---------------------------------------------------------------------------
// 2x2 conv, stride 2, no pad (FFMA2 path, unchanged from R1).
// grid: (HK/2=16, 4, 8)
// ---------------------------------------------------------------------------
__global__ __launch_bounds__(256) void conv2_kernel(
    const float* __restrict__ y, const float* __restrict__ Wt,
    const float* __restrict__ bias, float* __restrict__ out)
{
    const int h0  = blockIdx.x * 2;
    const int co0 = blockIdx.y * 64;
    const int b   = blockIdx.z;
    const int tid = threadIdx.x;
    const int w0  = tid & 31;
    const int cg  = tid >> 5;
    const int cbase = cg * 8;

    __shared__ __align__(16) float sy[8][4][64];
    __shared__ __align__(16) float sw[8][4][64];

    u64 acc0[4], acc1[4];
#pragma unroll
    for (int j = 0; j < 4; j++) { acc0[j] = 0ULL; acc1[j] = 0ULL; }

    const float* yb = y + (size_t)b * CCH * (HH * WW);

    for (int c0 = 0; c0 < CCH; c0 += 8) {
        for (int i = tid; i < 8 * 4 * 64; i += 256) {
            int ci  = i >> 8;
            int r   = (i >> 6) & 3;
            int col = i & 63;
            sy[ci][r][col] = yb[(size_t)(c0 + ci) * (HH * WW) + (2 * h0 + r) * WW + col];
        }
        for (int i = tid; i < 8 * 4 * 64; i += 256) {
            int ci = i >> 8;
            int k  = (i >> 6) & 3;
            int co = i & 63;
            sw[ci][k][co] = Wt[((size_t)(co0 + co) * CCH + (c0 + ci)) * 4 + k];
        }
        __syncthreads();

        for (int ci = 0; ci < 8; ci++) {
#pragma unroll
            for (int k = 0; k < 4; k++) {
                const int kh = k >> 1, kw = k & 1;
                float xv0 = sy[ci][kh][2 * w0 + kw];
                float xv1 = sy[ci][2 + kh][2 * w0 + kw];
                const float4* wp = reinterpret_cast<const float4*>(&sw[ci][k][cbase]);
                float4 wA = wp[0], wB = wp[1];
                u64 w0p = pk2(wA.x, wA.y), w1p = pk2(wA.z, wA.w);
                u64 w2p = pk2(wB.x, wB.y), w3p = pk2(wB.z, wB.w);
                u64 x0 = pk2(xv0, xv0), x1 = pk2(xv1, xv1);
                acc0[0] = ffma2(x0, w0p, acc0[0]);
                acc0[1] = ffma2(x0, w1p, acc0[1]);
                acc0[2] = ffma2(x0, w2p, acc0[2]);
                acc0[3] = ffma2(x0, w3p, acc0[3]);
                acc1[0] = ffma2(x1, w0p, acc1[0]);
                acc1[1] = ffma2(x1, w1p, acc1[1]);
                acc1[2] = ffma2(x1, w2p, acc1[2]);
                acc1[3] = ffma2(x1, w3p, acc1[3]);
            }
        }
        __syncthreads();
    }

    float* ob = out + ((size_t)b * CCH + co0 + cbase) * MM + h0 * WK + w0;
#pragma unroll
    for (int j = 0; j < 4; j++) {
        float2 f0 = upk2(acc0[j]);
        float2 f1 = upk2(acc1[j]);
        float b0v = bias[co0 + cbase + 2 * j];
        float b1v = bias[co0 + cbase + 2 * j + 1];
        ob[(size_t)(2 * j) * MM]          = f0.x + b0v;
        ob[(size_t)(2 * j) * MM + WK]     = f1.x + b0v;
        ob[(size_t)(2 * j + 1) * MM]      = f0.y + b1v;
        ob[(size_t)(2 * j + 1) * MM + WK] = f1.y + b1v;
    }
}

// ---------------------------------------------------------------------------
// GroupNorm(32 groups of 8 ch) + affine + SiLU, in place. float4, 512 thr.
// ---------------------------------------------------------------------------
__global__ __launch_bounds__(512) void gn_silu_kernel(
    float* __restrict__ buf, const float* __restrict__ scale,
    const float* __restrict__ bias, int S)
{
    const int b = blockIdx.x >> 5;
    const int g = blockIdx.x & 31;
    float* base = buf + ((size_t)b * CCH + g * 8) * S;
    float4* p4 = reinterpret_cast<float4*>(base);
    const int tot4 = (8 * S) >> 2;
    const int tid = threadIdx.x;

    float s = 0.f, ss = 0.f;
    for (int i = tid; i < tot4; i += 512) {
        float4 v = p4[i];
        s += v.x + v.y + v.z + v.w;
        ss = fmaf(v.x, v.x, ss);
        ss = fmaf(v.y, v.y, ss);
        ss = fmaf(v.z, v.z, ss);
        ss = fmaf(v.w, v.w, ss);
    }
    __shared__ float r1[512], r2[512];
    r1[tid] = s; r2[tid] = ss;
    __syncthreads();
    for (int st = 256; st > 0; st >>= 1) {
        if (tid < st) { r1[tid] += r1[tid + st]; r2[tid] += r2[tid + st]; }
        __syncthreads();
    }
    const float tot = (float)(8 * S);
    const float mu   = r1[0] / tot;
    const float var  = r2[0] / tot - mu * mu;
    const float rstd = rsqrtf(var + 1e-5f);

    const int s4 = S >> 2;
    for (int i = tid; i < tot4; i += 512) {
        int c = g * 8 + i / s4;
        float sc = scale[c] * rstd, bi = bias[c] - mu * scale[c] * rstd;
        float4 v = p4[i];
        v.x = fmaf(v.x, sc, bi);
        v.y = fmaf(v.y, sc, bi);
        v.z = fmaf(v.z, sc, bi);
        v.w = fmaf(v.w, sc, bi);
        v.x = v.x / (1.f + __expf(-v.x));
        v.y = v.y / (1.f + __expf(-v.y));
        v.z = v.z / (1.f + __expf(-v.z));
        v.w = v.w / (1.f + __expf(-v.w));
        p4[i] = v;
    }
}

// ---------------------------------------------------------------------------
// E[b][n][m] = (1/16) * sum_c Q[b][c][n] * K[b][c][m]   (tensor cores, tf32)
// Block 128n x 128m, 8 warps (4n x 2m), warp tile 32n x 64m, k-chunk 16.
// grid: (MM/128=8, NN/128=32, B=8)
// ---------------------------------------------------------------------------
__global__ __launch_bounds__(256) void gemm_qk_mma(
    const float* __restrict__ Q, const float* __restrict__ K,
    float* __restrict__ E)
{
    const int mb = blockIdx.x * 128;
    const int nb = blockIdx.y * 128;
    const int b  = blockIdx.z;
    const int tid  = threadIdx.x;
    const int lane = tid & 31;
    const int w    = tid >> 5;
    const int gid  = lane >> 2;
    const int ctid = lane & 3;
    const int m_base = (w & 1) * 64;
    const int n_base = (w >> 1) * 32;

    __shared__ u32 sq[16 * 136];
    __shared__ u32 sk[16 * 136];

    float acc[2][8][4];
#pragma unroll
    for (int i = 0; i < 2; i++)
#pragma unroll
        for (int j = 0; j < 8; j++)
#pragma unroll
            for (int l = 0; l < 4; l++) acc[i][j][l] = 0.f;

    const float* Qb = Q + (size_t)b * CCH * NN + nb;
    const float* Kb = K + (size_t)b * CCH * MM + mb;

    for (int c0 = 0; c0 < CCH; c0 += 16) {
#pragma unroll
        for (int r = 0; r < 2; r++) {
            int s = tid + r * 256;
            int kc = s >> 5, col = (s & 31) * 4;
            float4 qv = *reinterpret_cast<const float4*>(&Qb[(size_t)(c0 + kc) * NN + col]);
            uint4 qo = {f2tf(qv.x), f2tf(qv.y), f2tf(qv.z), f2tf(qv.w)};
            *reinterpret_cast<uint4*>(&sq[kc * 136 + col]) = qo;
            float4 kv = *reinterpret_cast<const float4*>(&Kb[(size_t)(c0 + kc) * MM + col]);
            uint4 ko = {f2tf(kv.x), f2tf(kv.y), f2tf(kv.z), f2tf(kv.w)};
            *reinterpret_cast<uint4*>(&sk[kc * 136 + col]) = ko;
        }
        __syncthreads();
#pragma unroll
        for (int ks = 0; ks < 2; ks++) {
            const int k0 = ks * 8;
            u32 a[2][4];
#pragma unroll
            for (int rm = 0; rm < 2; rm++) {
                int n0 = n_base + rm * 16;
                a[rm][0] = sq[(k0 + ctid) * 136 + n0 + gid];
                a[rm][1] = sq[(k0 + ctid) * 136 + n0 + gid + 8];
                a[rm][2] = sq[(k0 + ctid + 4) * 136 + n0 + gid];
                a[rm][3] = sq[(k0 + ctid + 4) * 136 + n0 + gid + 8];
            }
#pragma unroll
            for (int f = 0; f < 8; f++) {
                u32 bf[2];
                bf[0] = sk[(k0 + ctid) * 136 + m_base + f * 8 + gid];
                bf[1] = sk[(k0 + ctid + 4) * 136 + m_base + f * 8 + gid];
                mma_tf32(acc[0][f], a[0], bf);
                mma_tf32(acc[1][f], a[1], bf);
            }
        }
        __syncthreads();
    }

    const float scale = 0.0625f;
    float* Eb = E + ((size_t)b * NN + nb) * MM + mb;
#pragma unroll
    for (int rm = 0; rm < 2; rm++) {
#pragma unroll
        for (int f = 0; f < 8; f++) {
            int r0 = n_base + rm * 16 + gid;
            int cc = m_base + f * 8 + 2 * ctid;
            float2 s0 = {acc[rm][f][0] * scale, acc[rm][f][1] * scale};
            float2 s1 = {acc[rm][f][2] * scale, acc[rm][f][3] * scale};
            *reinterpret_cast<float2*>(&Eb[(size_t)r0 * MM + cc])       = s0;
            *reinterpret_cast<float2*>(&Eb[(size_t)(r0 + 8) * MM + cc]) = s1;
        }
    }
}

// ---------------------------------------------------------------------------
// In-place softmax over last dim (M=1024). One block per row, float4.
// ---------------------------------------------------------------------------
__global__ __launch_bounds__(256) void softmax_kernel(float* __restrict__ E)
{
    float4* p = reinterpret_cast<float4*>(E + (size_t)blockIdx.x * MM);
    const int tid = threadIdx.x;

    float4 v = p[tid];
    float mx = fmaxf(fmaxf(v.x, v.y), fmaxf(v.z, v.w));
    __shared__ float red[256];
    red[tid] = mx;
    __syncthreads();
    for (int s = 128; s > 0; s >>= 1) {
        if (tid < s) red[tid] = fmaxf(red[tid], red[tid + s]);
        __syncthreads();
    }
    mx = red[0];
    __syncthreads();

    v.x = __expf(v.x - mx);
    v.y = __expf(v.y - mx);
    v.z = __expf(v.z - mx);
    v.w = __expf(v.w - mx);
    float sum = v.x + v.y + v.z + v.w;
    red[tid] = sum;
    __syncthreads();
    for (int s = 128; s > 0; s >>= 1) {
        if (tid < s) red[tid] += red[tid + s];
        __syncthreads();
    }
    float inv = 1.f / red[0];
    v.x *= inv; v.y *= inv; v.z *= inv; v.w *= inv;
    p[tid] = v;
}

// ---------------------------------------------------------------------------
// out[b][c][n] = gamma * sum_m V[b][c][m] * A[b][n][m]   (tensor cores, tf32)
// Block 128c x 128n, 8 warps (4c x 2n), warp tile 32c x 64n, m-chunk 16.
// Both operands staged transposed ([mk][c] / [mk][n]).
// grid: (NN/128=32, CCH/128=2, B=8)
// ---------------------------------------------------------------------------
__global__ __launch_bounds__(256) void gemm_av_mma(
    const float* __restrict__ V, const float* __restrict__ A,
    const float* __restrict__ gamma, float* __restrict__ out)
{
    const int nb = blockIdx.x * 128;
    const int cb = blockIdx.y * 128;
    const int b  = blockIdx.z;
    const int tid  = threadIdx.x;
    const int lane = tid & 31;
    const int w    = tid >> 5;
    const int gid  = lane >> 2;
    const int ctid = lane & 3;
    const int n_base = (w & 1) * 64;
    const int c_base = (w >> 1) * 32;

    __shared__ u32 sv[16 * 136];
    __shared__ u32 sa[16 * 136];

    float acc[2][8][4];
#pragma unroll
    for (int i = 0; i < 2; i++)
#pragma unroll
        for (int j = 0; j < 8; j++)
#pragma unroll
            for (int l = 0; l < 4; l++) acc[i][j][l] = 0.f;

    const float* Vb = V + (size_t)b * CCH * MM;
    const float* Ab = A + (size_t)b * NN * MM;

    for (int m0 = 0; m0 < MM; m0 += 16) {
#pragma unroll
        for (int r = 0; r < 2; r++) {
            int s = tid + r * 256;
            int row = s >> 2, f = s & 3;
            float4 vv = *reinterpret_cast<const float4*>(&Vb[(size_t)(cb + row) * MM + m0 + f * 4]);
            sv[(f * 4 + 0) * 136 + row] = f2tf(vv.x);
            sv[(f * 4 + 1) * 136 + row] = f2tf(vv.y);
            sv[(f * 4 + 2) * 136 + row] = f2tf(vv.z);
            sv[(f * 4 + 3) * 136 + row] = f2tf(vv.w);
            float4 av = *reinterpret_cast<const float4*>(&Ab[(size_t)(nb + row) * MM + m0 + f * 4]);
            sa[(f * 4 + 0) * 136 + row] = f2tf(av.x);
            sa[(f * 4 + 1) * 136 + row] = f2tf(av.y);
            sa[(f * 4 + 2) * 136 + row] = f2tf(av.z);
            sa[(f * 4 + 3) * 136 + row] = f2tf(av.w);
        }
        __syncthreads();
#pragma unroll
        for (int ks = 0; ks < 2; ks++) {
            const int k0 = ks * 8;
            u32 a[2][4];
#pragma unroll
            for (int rm = 0; rm < 2; rm++) {
                int c0 = c_base + rm * 16;
                a[rm][0] = sv[(k0 + ctid) * 136 + c0 + gid];
                a[rm][1] = sv[(k0 + ctid) * 136 + c0 + gid + 8];
                a[rm][2] = sv[(k0 + ctid + 4) * 136 + c0 + gid];
                a[rm][3] = sv[(k0 + ctid + 4) * 136 + c0 + gid + 8];
            }
#pragma unroll
            for (int f = 0; f < 8; f++) {
                u32 bf[2];
                bf[0] = sa[(k0 + ctid) * 136 + n_base + f * 8 + gid];
                bf[1] = sa[(k0 + ctid + 4) * 136 + n_base + f * 8 + gid];
                mma_tf32(acc[0][f], a[0], bf);
                mma_tf32(acc[1][f], a[1], bf);
            }
        }
        __syncthreads();
    }

    const float gm = gamma[0];
#pragma unroll
    for (int rm = 0; rm < 2; rm++) {
#pragma unroll
        for (int f = 0; f < 8; f++) {
            int c0 = cb + c_base + rm * 16 + gid;
            int nn2 = nb + n_base + f * 8 + 2 * ctid;
            float2 s0 = {gm * acc[rm][f][0], gm * acc[rm][f][1]};
            float2 s1 = {gm * acc[rm][f][2], gm * acc[rm][f][3]};
            *reinterpret_cast<float2*>(&out[((size_t)b * CCH + c0) * NN + nn2])     = s0;
            *reinterpret_cast<float2*>(&out[((size_t)b * CCH + c0 + 8) * NN + nn2]) = s1;
        }
    }
}

// ---------------------------------------------------------------------------
extern "C" void kernel_launch(void* const* d_in, const int* in_sizes, int n_in,
                              void* d_out, int out_size)
{
    const float* x        = (const float*)d_in[0];
    const float* y        = (const float*)d_in[1];
    const float* Wq       = (const float*)d_in[2];
    const float* bq       = (const float*)d_in[3];
    const float* gq_scale = (const float*)d_in[4];
    const float* gq_bias  = (const float*)d_in[5];
    const float* Wk       = (const float*)d_in[6];
    const float* bk       = (const float*)d_in[7];
    const float* gk_scale = (const float*)d_in[8];
    const float* gk_bias  = (const float*)d_in[9];
    const float* Wv       = (const float*)d_in[10];
    const float* bv       = (const float*)d_in[11];
    const float* gv_scale = (const float*)d_in[12];
    const float* gv_bias  = (const float*)d_in[13];
    const float* gamma    = (const float*)d_in[14];
    float* out = (float*)d_out;

    float *qp = nullptr, *kp = nullptr, *vp = nullptr, *ep = nullptr;
    u32* wtp = nullptr;
    cudaGetSymbolAddress((void**)&qp, g_q);
    cudaGetSymbolAddress((void**)&kp, g_k);
    cudaGetSymbolAddress((void**)&vp, g_v);
    cudaGetSymbolAddress((void**)&ep, g_e);
    cudaGetSymbolAddress((void**)&wtp, g_wt);

    transpose_w3<<<(9 * 256 * 256 + 255) / 256, 256>>>(Wq, wtp);
    conv3_mma<<<dim3(HH / 2, CCH / 64, BATCH), 256>>>(wtp, x, bq, qp);
    conv2_kernel<<<dim3(HK / 2, CCH / 64, BATCH), 256>>>(y, Wk, bk, kp);
    conv2_kernel<<<dim3(HK / 2, CCH / 64, BATCH), 256>>>(y, Wv, bv, vp);

    gn_silu_kernel<<<BATCH * 32, 512>>>(qp, gq_scale, gq_bias, NN);
    gn_silu_kernel<<<BATCH * 32, 512>>>(kp, gk_scale, gk_bias, MM);
    gn_silu_kernel<<<BATCH * 32, 512>>>(vp, gv_scale, gv_bias, MM);

    gemm_qk_mma<<<dim3(MM / 128, NN / 128, BATCH), 256>>>(qp, kp, ep);
    softmax_kernel<<<BATCH * NN, 256>>>(ep);
    gemm_av_mma<<<dim3(NN / 128, CCH / 128, BATCH), 256>>>(vp, ep, gamma, out);
}

// round 5
// speedup vs baseline: 4.8620x; 1.3422x over previous
#include <cuda_runtime.h>
#include <math.h>

#define BATCH 8
#define CCH   256
#define HH    64
#define WW    64
#define NN    4096   // HH*WW
#define MM    1024   // (HH/2)*(WW/2)
#define HK    32
#define WK    32

typedef unsigned long long u64;
typedef unsigned int u32;

__device__ __forceinline__ u32 f2tf(float f) {
    u32 u; asm("cvt.rna.tf32.f32 %0,%1;" : "=r"(u) : "f"(f)); return u;
}
__device__ __forceinline__ void mma_tf32(float* d, const u32* a, const u32* b) {
    asm volatile(
        "mma.sync.aligned.m16n8k8.row.col.f32.tf32.tf32.f32 "
        "{%0,%1,%2,%3},{%4,%5,%6,%7},{%8,%9},{%0,%1,%2,%3};"
        : "+f"(d[0]), "+f"(d[1]), "+f"(d[2]), "+f"(d[3])
        : "r"(a[0]), "r"(a[1]), "r"(a[2]), "r"(a[3]), "r"(b[0]), "r"(b[1]));
}

// Scratch
__device__ float g_q[(size_t)BATCH * CCH * NN];   // 32 MB
__device__ float g_k[(size_t)BATCH * CCH * MM];   // 8 MB
__device__ float g_v[(size_t)BATCH * CCH * MM];   // 8 MB
__device__ float g_e[(size_t)BATCH * NN * MM];    // 128 MB
__device__ u32   g_wt[9 * 256 * 256];             // Wq transposed, tf32
__device__ u32   g_wk2[4 * 256 * 256];            // Wk transposed, tf32
__device__ u32   g_wv2[4 * 256 * 256];            // Wv transposed, tf32

// ---------------------------------------------------------------------------
// Weight transposes: OIHW -> [k][ci][co] tf32.
// ---------------------------------------------------------------------------
__global__ __launch_bounds__(256) void transpose_w3(
    const float* __restrict__ Wt, u32* __restrict__ wt2)
{
    int i = blockIdx.x * 256 + threadIdx.x;
    if (i < 9 * 256 * 256) {
        int co = i & 255;
        int ci = (i >> 8) & 255;
        int k  = i >> 16;
        wt2[i] = f2tf(Wt[((size_t)co * 256 + ci) * 9 + k]);
    }
}

__global__ __launch_bounds__(256) void transpose_w2(
    const float* __restrict__ Wk, const float* __restrict__ Wv,
    u32* __restrict__ wk2, u32* __restrict__ wv2)
{
    int i = blockIdx.x * 256 + threadIdx.x;
    if (i < 4 * 256 * 256) {
        int co = i & 255;
        int ci = (i >> 8) & 255;
        int k  = i >> 16;
        wk2[i] = f2tf(Wk[((size_t)co * 256 + ci) * 4 + k]);
        wv2[i] = f2tf(Wv[((size_t)co * 256 + ci) * 4 + k]);
    }
}

// ---------------------------------------------------------------------------
// 3x3 conv s1 p1 as implicit GEMM on tensor cores (tf32).
// grid: (HH/2=32, CCH/64=4, B=8)
// ---------------------------------------------------------------------------
__global__ __launch_bounds__(256) void conv3_mma(
    const u32* __restrict__ wt2, const float* __restrict__ x,
    const float* __restrict__ bias, float* __restrict__ out)
{
    const int h0  = blockIdx.x * 2;
    const int co0 = blockIdx.y * 64;
    const int b   = blockIdx.z;
    const int tid  = threadIdx.x;
    const int lane = tid & 31;
    const int w    = tid >> 5;
    const int gid  = lane >> 2;
    const int ctid = lane & 3;
    const int co_base = (w >> 2) * 32;
    const int px_base = (w & 3) * 32;

    __shared__ u32 sxt[4 * 8 * 72];   // [r][ci][col pad 72]
    __shared__ u32 swt[8 * 9 * 72];   // [ci][k][co pad 72]

    float acc[2][4][4];
#pragma unroll
    for (int i = 0; i < 2; i++)
#pragma unroll
        for (int j = 0; j < 4; j++)
#pragma unroll
            for (int l = 0; l < 4; l++) acc[i][j][l] = 0.f;

    const float* xb = x + (size_t)b * CCH * (HH * WW);

    for (int ci0 = 0; ci0 < CCH; ci0 += 8) {
        for (int i = tid; i < 4 * 8 * 66; i += 256) {
            int r   = i / (8 * 66);
            int ci  = (i / 66) & 7;
            int col = i % 66;
            int gh = h0 - 1 + r;
            int gw = col - 1;
            float v = 0.f;
            if ((unsigned)gh < HH && (unsigned)gw < WW)
                v = xb[(size_t)(ci0 + ci) * (HH * WW) + gh * WW + gw];
            sxt[(r * 8 + ci) * 72 + col] = f2tf(v);
        }
        for (int i = tid; i < 8 * 9 * 16; i += 256) {
            int k   = i / 128;
            int ci  = (i >> 4) & 7;
            int co4 = (i & 15) * 4;
            uint4 v = *reinterpret_cast<const uint4*>(
                &wt2[((size_t)k * 256 + ci0 + ci) * 256 + co0 + co4]);
            *reinterpret_cast<uint4*>(&swt[(ci * 9 + k) * 72 + co4]) = v;
        }
        __syncthreads();

#pragma unroll
        for (int k = 0; k < 9; k++) {
            const int kh = k / 3, kw = k % 3;
            u32 a[2][4];
#pragma unroll
            for (int rm = 0; rm < 2; rm++) {
                int cof = co_base + rm * 16;
                a[rm][0] = swt[((ctid) * 9 + k) * 72 + cof + gid];
                a[rm][1] = swt[((ctid) * 9 + k) * 72 + cof + gid + 8];
                a[rm][2] = swt[((ctid + 4) * 9 + k) * 72 + cof + gid];
                a[rm][3] = swt[((ctid + 4) * 9 + k) * 72 + cof + gid + 8];
            }
#pragma unroll
            for (int f = 0; f < 4; f++) {
                int px = px_base + f * 8 + gid;
                int rl = px >> 6;
                int wc = (px & 63) + kw;
                u32 bf[2];
                bf[0] = sxt[((rl + kh) * 8 + ctid) * 72 + wc];
                bf[1] = sxt[((rl + kh) * 8 + ctid + 4) * 72 + wc];
                mma_tf32(acc[0][f], a[0], bf);
                mma_tf32(acc[1][f], a[1], bf);
            }
        }
        __syncthreads();
    }

#pragma unroll
    for (int rm = 0; rm < 2; rm++) {
#pragma unroll
        for (int f = 0; f < 4; f++) {
            int coA = co0 + co_base + rm * 16 + gid;
            int coB = coA + 8;
            int px  = px_base + f * 8 + 2 * ctid;
            int n   = (h0 + (px >> 6)) * WW + (px & 63);
            float bA = bias[coA], bB = bias[coB];
            float2 sA = {acc[rm][f][0] + bA, acc[rm][f][1] + bA};
            float2 sB = {acc[rm][f][2] + bB, acc[rm][f][3] + bB};
            *reinterpret_cast<float2*>(&out[((size_t)b * CCH + coA) * NN + n]) = sA;
            *reinterpret_cast<float2*>(&out[((size_t)b * CCH + coB) * NN + n]) = sB;
        }
    }
}

// ---------------------------------------------------------------------------
// 2x2 conv s2 p0 as implicit GEMM on tensor cores (tf32).
// Block: 64 co x 128 px (4 output rows x 32 cols). 8 warps (2co x 4px).
// Input staged de-interleaved by column parity: sy[kw][r][ci][w pad 40].
// Weight smem stride 74 keeps A-frag quad reads conflict-free; stores are
// SCALAR u32 (stride 74 breaks 16B alignment for uint4 stores).
// grid: (HK/4=8, CCH/64=4, B=8)
// ---------------------------------------------------------------------------
__global__ __launch_bounds__(256) void conv2_mma(
    const u32* __restrict__ wt2, const float* __restrict__ y,
    const float* __restrict__ bias, float* __restrict__ out)
{
    const int h0  = blockIdx.x * 4;    // first output row
    const int co0 = blockIdx.y * 64;
    const int b   = blockIdx.z;
    const int tid  = threadIdx.x;
    const int lane = tid & 31;
    const int w    = tid >> 5;
    const int gid  = lane >> 2;
    const int ctid = lane & 3;
    const int co_base = (w >> 2) * 32;
    const int px_base = (w & 3) * 32;

    __shared__ u32 sy[2 * 8 * 8 * 40];   // [kw][r][ci][w pad 40]  20 KB
    __shared__ u32 swt[8 * 4 * 74];      // [ci][k][co pad 74]     9.25 KB

    float acc[2][4][4];
#pragma unroll
    for (int i = 0; i < 2; i++)
#pragma unroll
        for (int j = 0; j < 4; j++)
#pragma unroll
            for (int l = 0; l < 4; l++) acc[i][j][l] = 0.f;

    const float* yb = y + (size_t)b * CCH * (HH * WW);
    const int ih0 = h0 * 2;

    for (int ci0 = 0; ci0 < CCH; ci0 += 8) {
        // stage 8 input rows x 8 ci x 64 cols, split by col parity
        for (int i = tid; i < 8 * 8 * 64; i += 256) {
            int r   = i >> 9;          // 0..7
            int ci  = (i >> 6) & 7;
            int col = i & 63;
            float v = yb[(size_t)(ci0 + ci) * (HH * WW) + (ih0 + r) * WW + col];
            sy[(((col & 1) * 8 + r) * 8 + ci) * 40 + (col >> 1)] = f2tf(v);
        }
        // stage weights: swt[ci][k][co]; uint4 gmem load, scalar smem stores
        for (int i = tid; i < 8 * 4 * 16; i += 256) {
            int k   = i / 128;         // 0..3
            int ci  = (i >> 4) & 7;
            int co4 = (i & 15) * 4;
            uint4 v = *reinterpret_cast<const uint4*>(
                &wt2[((size_t)k * 256 + ci0 + ci) * 256 + co0 + co4]);
            u32* dst = &swt[(ci * 4 + k) * 74 + co4];
            dst[0] = v.x; dst[1] = v.y; dst[2] = v.z; dst[3] = v.w;
        }
        __syncthreads();

#pragma unroll
        for (int k = 0; k < 4; k++) {
            const int kh = k >> 1, kw = k & 1;
            u32 a[2][4];
#pragma unroll
            for (int rm = 0; rm < 2; rm++) {
                int cof = co_base + rm * 16;
                a[rm][0] = swt[((ctid) * 4 + k) * 74 + cof + gid];
                a[rm][1] = swt[((ctid) * 4 + k) * 74 + cof + gid + 8];
                a[rm][2] = swt[((ctid + 4) * 4 + k) * 74 + cof + gid];
                a[rm][3] = swt[((ctid + 4) * 4 + k) * 74 + cof + gid + 8];
            }
#pragma unroll
            for (int f = 0; f < 4; f++) {
                int px = px_base + f * 8 + gid;
                int r  = 2 * (px >> 5) + kh;
                int wl = px & 31;
                u32 bf[2];
                bf[0] = sy[((kw * 8 + r) * 8 + ctid) * 40 + wl];
                bf[1] = sy[((kw * 8 + r) * 8 + ctid + 4) * 40 + wl];
                mma_tf32(acc[0][f], a[0], bf);
                mma_tf32(acc[1][f], a[1], bf);
            }
        }
        __syncthreads();
    }

#pragma unroll
    for (int rm = 0; rm < 2; rm++) {
#pragma unroll
        for (int f = 0; f < 4; f++) {
            int coA = co0 + co_base + rm * 16 + gid;
            int coB = coA + 8;
            int px  = px_base + f * 8 + 2 * ctid;
            int n   = (h0 + (px >> 5)) * WK + (px & 31);
            float bA = bias[coA], bB = bias[coB];
            float2 sA = {acc[rm][f][0] + bA, acc[rm][f][1] + bA};
            float2 sB = {acc[rm][f][2] + bB, acc[rm][f][3] + bB};
            *reinterpret_cast<float2*>(&out[((size_t)b * CCH + coA) * MM + n]) = sA;
            *reinterpret_cast<float2*>(&out[((size_t)b * CCH + coB) * MM + n]) = sB;
        }
    }
}

// ---------------------------------------------------------------------------
// GroupNorm(32 groups of 8 ch) + affine + SiLU, in place. float4, 512 thr.
// ---------------------------------------------------------------------------
__global__ __launch_bounds__(512) void gn_silu_kernel(
    float* __restrict__ buf, const float* __restrict__ scale,
    const float* __restrict__ bias, int S)
{
    const int b = blockIdx.x >> 5;
    const int g = blockIdx.x & 31;
    float* base = buf + ((size_t)b * CCH + g * 8) * S;
    float4* p4 = reinterpret_cast<float4*>(base);
    const int tot4 = (8 * S) >> 2;
    const int tid = threadIdx.x;

    float s = 0.f, ss = 0.f;
    for (int i = tid; i < tot4; i += 512) {
        float4 v = p4[i];
        s += v.x + v.y + v.z + v.w;
        ss = fmaf(v.x, v.x, ss);
        ss = fmaf(v.y, v.y, ss);
        ss = fmaf(v.z, v.z, ss);
        ss = fmaf(v.w, v.w, ss);
    }
    __shared__ float r1[512], r2[512];
    r1[tid] = s; r2[tid] = ss;
    __syncthreads();
    for (int st = 256; st > 0; st >>= 1) {
        if (tid < st) { r1[tid] += r1[tid + st]; r2[tid] += r2[tid + st]; }
        __syncthreads();
    }
    const float tot = (float)(8 * S);
    const float mu   = r1[0] / tot;
    const float var  = r2[0] / tot - mu * mu;
    const float rstd = rsqrtf(var + 1e-5f);

    const int s4 = S >> 2;
    for (int i = tid; i < tot4; i += 512) {
        int c = g * 8 + i / s4;
        float sc = scale[c] * rstd, bi = bias[c] - mu * scale[c] * rstd;
        float4 v = p4[i];
        v.x = fmaf(v.x, sc, bi);
        v.y = fmaf(v.y, sc, bi);
        v.z = fmaf(v.z, sc, bi);
        v.w = fmaf(v.w, sc, bi);
        v.x = v.x / (1.f + __expf(-v.x));
        v.y = v.y / (1.f + __expf(-v.y));
        v.z = v.z / (1.f + __expf(-v.z));
        v.w = v.w / (1.f + __expf(-v.w));
        p4[i] = v;
    }
}

// ---------------------------------------------------------------------------
// E = (1/16) Q^T K  (tensor cores, tf32). Block 128n x 128m.
// grid: (MM/128=8, NN/128=32, B=8)
// ---------------------------------------------------------------------------
__global__ __launch_bounds__(256) void gemm_qk_mma(
    const float* __restrict__ Q, const float* __restrict__ K,
    float* __restrict__ E)
{
    const int mb = blockIdx.x * 128;
    const int nb = blockIdx.y * 128;
    const int b  = blockIdx.z;
    const int tid  = threadIdx.x;
    const int lane = tid & 31;
    const int w    = tid >> 5;
    const int gid  = lane >> 2;
    const int ctid = lane & 3;
    const int m_base = (w & 1) * 64;
    const int n_base = (w >> 1) * 32;

    __shared__ u32 sq[16 * 136];
    __shared__ u32 sk[16 * 136];

    float acc[2][8][4];
#pragma unroll
    for (int i = 0; i < 2; i++)
#pragma unroll
        for (int j = 0; j < 8; j++)
#pragma unroll
            for (int l = 0; l < 4; l++) acc[i][j][l] = 0.f;

    const float* Qb = Q + (size_t)b * CCH * NN + nb;
    const float* Kb = K + (size_t)b * CCH * MM + mb;

    for (int c0 = 0; c0 < CCH; c0 += 16) {
#pragma unroll
        for (int r = 0; r < 2; r++) {
            int s = tid + r * 256;
            int kc = s >> 5, col = (s & 31) * 4;
            float4 qv = *reinterpret_cast<const float4*>(&Qb[(size_t)(c0 + kc) * NN + col]);
            uint4 qo = {f2tf(qv.x), f2tf(qv.y), f2tf(qv.z), f2tf(qv.w)};
            *reinterpret_cast<uint4*>(&sq[kc * 136 + col]) = qo;
            float4 kv = *reinterpret_cast<const float4*>(&Kb[(size_t)(c0 + kc) * MM + col]);
            uint4 ko = {f2tf(kv.x), f2tf(kv.y), f2tf(kv.z), f2tf(kv.w)};
            *reinterpret_cast<uint4*>(&sk[kc * 136 + col]) = ko;
        }
        __syncthreads();
#pragma unroll
        for (int ks = 0; ks < 2; ks++) {
            const int k0 = ks * 8;
            u32 a[2][4];
#pragma unroll
            for (int rm = 0; rm < 2; rm++) {
                int n0 = n_base + rm * 16;
                a[rm][0] = sq[(k0 + ctid) * 136 + n0 + gid];
                a[rm][1] = sq[(k0 + ctid) * 136 + n0 + gid + 8];
                a[rm][2] = sq[(k0 + ctid + 4) * 136 + n0 + gid];
                a[rm][3] = sq[(k0 + ctid + 4) * 136 + n0 + gid + 8];
            }
#pragma unroll
            for (int f = 0; f < 8; f++) {
                u32 bf[2];
                bf[0] = sk[(k0 + ctid) * 136 + m_base + f * 8 + gid];
                bf[1] = sk[(k0 + ctid + 4) * 136 + m_base + f * 8 + gid];
                mma_tf32(acc[0][f], a[0], bf);
                mma_tf32(acc[1][f], a[1], bf);
            }
        }
        __syncthreads();
    }

    const float scale = 0.0625f;
    float* Eb = E + ((size_t)b * NN + nb) * MM + mb;
#pragma unroll
    for (int rm = 0; rm < 2; rm++) {
#pragma unroll
        for (int f = 0; f < 8; f++) {
            int r0 = n_base + rm * 16 + gid;
            int cc = m_base + f * 8 + 2 * ctid;
            float2 s0 = {acc[rm][f][0] * scale, acc[rm][f][1] * scale};
            float2 s1 = {acc[rm][f][2] * scale, acc[rm][f][3] * scale};
            *reinterpret_cast<float2*>(&Eb[(size_t)r0 * MM + cc])       = s0;
            *reinterpret_cast<float2*>(&Eb[(size_t)(r0 + 8) * MM + cc]) = s1;
        }
    }
}

// ---------------------------------------------------------------------------
// In-place softmax over last dim (M=1024). One block per row, float4.
// ---------------------------------------------------------------------------
__global__ __launch_bounds__(256) void softmax_kernel(float* __restrict__ E)
{
    float4* p = reinterpret_cast<float4*>(E + (size_t)blockIdx.x * MM);
    const int tid = threadIdx.x;

    float4 v = p[tid];
    float mx = fmaxf(fmaxf(v.x, v.y), fmaxf(v.z, v.w));
    __shared__ float red[256];
    red[tid] = mx;
    __syncthreads();
    for (int s = 128; s > 0; s >>= 1) {
        if (tid < s) red[tid] = fmaxf(red[tid], red[tid + s]);
        __syncthreads();
    }
    mx = red[0];
    __syncthreads();

    v.x = __expf(v.x - mx);
    v.y = __expf(v.y - mx);
    v.z = __expf(v.z - mx);
    v.w = __expf(v.w - mx);
    float sum = v.x + v.y + v.z + v.w;
    red[tid] = sum;
    __syncthreads();
    for (int s = 128; s > 0; s >>= 1) {
        if (tid < s) red[tid] += red[tid + s];
        __syncthreads();
    }
    float inv = 1.f / red[0];
    v.x *= inv; v.y *= inv; v.z *= inv; v.w *= inv;
    p[tid] = v;
}

// ---------------------------------------------------------------------------
// out = gamma * V A^T (tensor cores, tf32). Block 128c x 128n.
// grid: (NN/128=32, CCH/128=2, B=8)
// ---------------------------------------------------------------------------
__global__ __launch_bounds__(256) void gemm_av_mma(
    const float* __restrict__ V, const float* __restrict__ A,
    const float* __restrict__ gamma, float* __restrict__ out)
{
    const int nb = blockIdx.x * 128;
    const int cb = blockIdx.y * 128;
    const int b  = blockIdx.z;
    const int tid  = threadIdx.x;
    const int lane = tid & 31;
    const int w    = tid >> 5;
    const int gid  = lane >> 2;
    const int ctid = lane & 3;
    const int n_base = (w & 1) * 64;
    const int c_base = (w >> 1) * 32;

    __shared__ u32 sv[16 * 136];
    __shared__ u32 sa[16 * 136];

    float acc[2][8][4];
#pragma unroll
    for (int i = 0; i < 2; i++)
#pragma unroll
        for (int j = 0; j < 8; j++)
#pragma unroll
            for (int l = 0; l < 4; l++) acc[i][j][l] = 0.f;

    const float* Vb = V + (size_t)b * CCH * MM;
    const float* Ab = A + (size_t)b * NN * MM;

    for (int m0 = 0; m0 < MM; m0 += 16) {
#pragma unroll
        for (int r = 0; r < 2; r++) {
            int s = tid + r * 256;
            int row = s >> 2, f = s & 3;
            float4 vv = *reinterpret_cast<const float4*>(&Vb[(size_t)(cb + row) * MM + m0 + f * 4]);
            sv[(f * 4 + 0) * 136 + row] = f2tf(vv.x);
            sv[(f * 4 + 1) * 136 + row] = f2tf(vv.y);
            sv[(f * 4 + 2) * 136 + row] = f2tf(vv.z);
            sv[(f * 4 + 3) * 136 + row] = f2tf(vv.w);
            float4 av = *reinterpret_cast<const float4*>(&Ab[(size_t)(nb + row) * MM + m0 + f * 4]);
            sa[(f * 4 + 0) * 136 + row] = f2tf(av.x);
            sa[(f * 4 + 1) * 136 + row] = f2tf(av.y);
            sa[(f * 4 + 2) * 136 + row] = f2tf(av.z);
            sa[(f * 4 + 3) * 136 + row] = f2tf(av.w);
        }
        __syncthreads();
#pragma unroll
        for (int ks = 0; ks < 2; ks++) {
            const int k0 = ks * 8;
            u32 a[2][4];
#pragma unroll
            for (int rm = 0; rm < 2; rm++) {
                int c0 = c_base + rm * 16;
                a[rm][0] = sv[(k0 + ctid) * 136 + c0 + gid];
                a[rm][1] = sv[(k0 + ctid) * 136 + c0 + gid + 8];
                a[rm][2] = sv[(k0 + ctid + 4) * 136 + c0 + gid];
                a[rm][3] = sv[(k0 + ctid + 4) * 136 + c0 + gid + 8];
            }
#pragma unroll
            for (int f = 0; f < 8; f++) {
                u32 bf[2];
                bf[0] = sa[(k0 + ctid) * 136 + n_base + f * 8 + gid];
                bf[1] = sa[(k0 + ctid + 4) * 136 + n_base + f * 8 + gid];
                mma_tf32(acc[0][f], a[0], bf);
                mma_tf32(acc[1][f], a[1], bf);
            }
        }
        __syncthreads();
    }

    const float gm = gamma[0];
#pragma unroll
    for (int rm = 0; rm < 2; rm++) {
#pragma unroll
        for (int f = 0; f < 8; f++) {
            int c0 = cb + c_base + rm * 16 + gid;
            int nn2 = nb + n_base + f * 8 + 2 * ctid;
            float2 s0 = {gm * acc[rm][f][0], gm * acc[rm][f][1]};
            float2 s1 = {gm * acc[rm][f][2], gm * acc[rm][f][3]};
            *reinterpret_cast<float2*>(&out[((size_t)b * CCH + c0) * NN + nn2])     = s0;
            *reinterpret_cast<float2*>(&out[((size_t)b * CCH + c0 + 8) * NN + nn2]) = s1;
        }
    }
}

// ---------------------------------------------------------------------------
extern "C" void kernel_launch(void* const* d_in, const int* in_sizes, int n_in,
                              void* d_out, int out_size)
{
    const float* x        = (const float*)d_in[0];
    const float* y        = (const float*)d_in[1];
    const float* Wq       = (const float*)d_in[2];
    const float* bq       = (const float*)d_in[3];
    const float* gq_scale = (const float*)d_in[4];
    const float* gq_bias  = (const float*)d_in[5];
    const float* Wk       = (const float*)d_in[6];
    const float* bk       = (const float*)d_in[7];
    const float* gk_scale = (const float*)d_in[8];
    const float* gk_bias  = (const float*)d_in[9];
    const float* Wv       = (const float*)d_in[10];
    const float* bv       = (const float*)d_in[11];
    const float* gv_scale = (const float*)d_in[12];
    const float* gv_bias  = (const float*)d_in[13];
    const float* gamma    = (const float*)d_in[14];
    float* out = (float*)d_out;

    float *qp = nullptr, *kp = nullptr, *vp = nullptr, *ep = nullptr;
    u32 *wtp = nullptr, *wkp = nullptr, *wvp = nullptr;
    cudaGetSymbolAddress((void**)&qp, g_q);
    cudaGetSymbolAddress((void**)&kp, g_k);
    cudaGetSymbolAddress((void**)&vp, g_v);
    cudaGetSymbolAddress((void**)&ep, g_e);
    cudaGetSymbolAddress((void**)&wtp, g_wt);
    cudaGetSymbolAddress((void**)&wkp, g_wk2);
    cudaGetSymbolAddress((void**)&wvp, g_wv2);

    transpose_w3<<<(9 * 256 * 256 + 255) / 256, 256>>>(Wq, wtp);
    transpose_w2<<<(4 * 256 * 256 + 255) / 256, 256>>>(Wk, Wv, wkp, wvp);

    conv3_mma<<<dim3(HH / 2, CCH / 64, BATCH), 256>>>(wtp, x, bq, qp);
    conv2_mma<<<dim3(HK / 4, CCH / 64, BATCH), 256>>>(wkp, y, bk, kp);
    conv2_mma<<<dim3(HK / 4, CCH / 64, BATCH), 256>>>(wvp, y, bv, vp);

    gn_silu_kernel<<<BATCH * 32, 512>>>(qp, gq_scale, gq_bias, NN);
    gn_silu_kernel<<<BATCH * 32, 512>>>(kp, gk_scale, gk_bias, MM);
    gn_silu_kernel<<<BATCH * 32, 512>>>(vp, gv_scale, gv_bias, MM);

    gemm_qk_mma<<<dim3(MM / 128, NN / 128, BATCH), 256>>>(qp, kp, ep);
    softmax_kernel<<<BATCH * NN, 256>>>(ep);
    gemm_av_mma<<<dim3(NN / 128, CCH / 128, BATCH), 256>>>(vp, ep, gamma, out);
}

// round 6
// speedup vs baseline: 5.1700x; 1.0633x over previous
#include <cuda_runtime.h>
#include <math.h>

#define BATCH 8
#define CCH   256
#define HH    64
#define WW    64
#define NN    4096   // HH*WW
#define MM    1024   // (HH/2)*(WW/2)
#define HK    32
#define WK    32

typedef unsigned long long u64;
typedef unsigned int u32;

__device__ __forceinline__ u32 f2tf(float f) {
    u32 u; asm("cvt.rna.tf32.f32 %0,%1;" : "=r"(u) : "f"(f)); return u;
}
__device__ __forceinline__ void mma_tf32(float* d, const u32* a, const u32* b) {
    asm volatile(
        "mma.sync.aligned.m16n8k8.row.col.f32.tf32.tf32.f32 "
        "{%0,%1,%2,%3},{%4,%5,%6,%7},{%8,%9},{%0,%1,%2,%3};"
        : "+f"(d[0]), "+f"(d[1]), "+f"(d[2]), "+f"(d[3])
        : "r"(a[0]), "r"(a[1]), "r"(a[2]), "r"(a[3]), "r"(b[0]), "r"(b[1]));
}

// Scratch
__device__ float g_q[(size_t)BATCH * CCH * NN];   // 32 MB
__device__ float g_k[(size_t)BATCH * CCH * MM];   // 8 MB
__device__ float g_v[(size_t)BATCH * CCH * MM];   // 8 MB
__device__ float g_e[(size_t)BATCH * NN * MM];    // 128 MB
__device__ u32   g_wt[9 * 256 * 256];             // Wq transposed, tf32
__device__ u32   g_wk2[4 * 256 * 256];            // Wk transposed, tf32
__device__ u32   g_wv2[4 * 256 * 256];            // Wv transposed, tf32

// ---------------------------------------------------------------------------
// Weight transposes: OIHW -> [k][ci][co] tf32.
// ---------------------------------------------------------------------------
__global__ __launch_bounds__(256) void transpose_w3(
    const float* __restrict__ Wt, u32* __restrict__ wt2)
{
    int i = blockIdx.x * 256 + threadIdx.x;
    if (i < 9 * 256 * 256) {
        int co = i & 255;
        int ci = (i >> 8) & 255;
        int k  = i >> 16;
        wt2[i] = f2tf(Wt[((size_t)co * 256 + ci) * 9 + k]);
    }
}

__global__ __launch_bounds__(256) void transpose_w2(
    const float* __restrict__ Wk, const float* __restrict__ Wv,
    u32* __restrict__ wk2, u32* __restrict__ wv2)
{
    int i = blockIdx.x * 256 + threadIdx.x;
    if (i < 4 * 256 * 256) {
        int co = i & 255;
        int ci = (i >> 8) & 255;
        int k  = i >> 16;
        wk2[i] = f2tf(Wk[((size_t)co * 256 + ci) * 4 + k]);
        wv2[i] = f2tf(Wv[((size_t)co * 256 + ci) * 4 + k]);
    }
}

// ---------------------------------------------------------------------------
// 3x3 conv s1 p1 as implicit GEMM on tensor cores (tf32).
// grid: (HH/2=32, CCH/64=4, B=8)
// ---------------------------------------------------------------------------
__global__ __launch_bounds__(256) void conv3_mma(
    const u32* __restrict__ wt2, const float* __restrict__ x,
    const float* __restrict__ bias, float* __restrict__ out)
{
    const int h0  = blockIdx.x * 2;
    const int co0 = blockIdx.y * 64;
    const int b   = blockIdx.z;
    const int tid  = threadIdx.x;
    const int lane = tid & 31;
    const int w    = tid >> 5;
    const int gid  = lane >> 2;
    const int ctid = lane & 3;
    const int co_base = (w >> 2) * 32;
    const int px_base = (w & 3) * 32;

    __shared__ u32 sxt[4 * 8 * 72];   // [r][ci][col pad 72]
    __shared__ u32 swt[8 * 9 * 72];   // [ci][k][co pad 72]

    float acc[2][4][4];
#pragma unroll
    for (int i = 0; i < 2; i++)
#pragma unroll
        for (int j = 0; j < 4; j++)
#pragma unroll
            for (int l = 0; l < 4; l++) acc[i][j][l] = 0.f;

    const float* xb = x + (size_t)b * CCH * (HH * WW);

    for (int ci0 = 0; ci0 < CCH; ci0 += 8) {
        for (int i = tid; i < 4 * 8 * 66; i += 256) {
            int r   = i / (8 * 66);
            int ci  = (i / 66) & 7;
            int col = i % 66;
            int gh = h0 - 1 + r;
            int gw = col - 1;
            float v = 0.f;
            if ((unsigned)gh < HH && (unsigned)gw < WW)
                v = xb[(size_t)(ci0 + ci) * (HH * WW) + gh * WW + gw];
            sxt[(r * 8 + ci) * 72 + col] = f2tf(v);
        }
        for (int i = tid; i < 8 * 9 * 16; i += 256) {
            int k   = i / 128;
            int ci  = (i >> 4) & 7;
            int co4 = (i & 15) * 4;
            uint4 v = *reinterpret_cast<const uint4*>(
                &wt2[((size_t)k * 256 + ci0 + ci) * 256 + co0 + co4]);
            *reinterpret_cast<uint4*>(&swt[(ci * 9 + k) * 72 + co4]) = v;
        }
        __syncthreads();

#pragma unroll
        for (int k = 0; k < 9; k++) {
            const int kh = k / 3, kw = k % 3;
            u32 a[2][4];
#pragma unroll
            for (int rm = 0; rm < 2; rm++) {
                int cof = co_base + rm * 16;
                a[rm][0] = swt[((ctid) * 9 + k) * 72 + cof + gid];
                a[rm][1] = swt[((ctid) * 9 + k) * 72 + cof + gid + 8];
                a[rm][2] = swt[((ctid + 4) * 9 + k) * 72 + cof + gid];
                a[rm][3] = swt[((ctid + 4) * 9 + k) * 72 + cof + gid + 8];
            }
#pragma unroll
            for (int f = 0; f < 4; f++) {
                int px = px_base + f * 8 + gid;
                int rl = px >> 6;
                int wc = (px & 63) + kw;
                u32 bf[2];
                bf[0] = sxt[((rl + kh) * 8 + ctid) * 72 + wc];
                bf[1] = sxt[((rl + kh) * 8 + ctid + 4) * 72 + wc];
                mma_tf32(acc[0][f], a[0], bf);
                mma_tf32(acc[1][f], a[1], bf);
            }
        }
        __syncthreads();
    }

#pragma unroll
    for (int rm = 0; rm < 2; rm++) {
#pragma unroll
        for (int f = 0; f < 4; f++) {
            int coA = co0 + co_base + rm * 16 + gid;
            int coB = coA + 8;
            int px  = px_base + f * 8 + 2 * ctid;
            int n   = (h0 + (px >> 6)) * WW + (px & 63);
            float bA = bias[coA], bB = bias[coB];
            float2 sA = {acc[rm][f][0] + bA, acc[rm][f][1] + bA};
            float2 sB = {acc[rm][f][2] + bB, acc[rm][f][3] + bB};
            *reinterpret_cast<float2*>(&out[((size_t)b * CCH + coA) * NN + n]) = sA;
            *reinterpret_cast<float2*>(&out[((size_t)b * CCH + coB) * NN + n]) = sB;
        }
    }
}

// ---------------------------------------------------------------------------
// FUSED K+V 2x2 conv s2 p0, implicit GEMM (tf32). One staging of y feeds
// both weight sets. Block: 64 co x 128 px, 8 warps (2co x 4px).
// Input: vectorized float4 LDG, parity-split into sy[kw][r][ci][w pad 40].
// grid: (HK/4=8, CCH/64=4, B=8)
// ---------------------------------------------------------------------------
__global__ __launch_bounds__(256) void conv2kv_mma(
    const u32* __restrict__ wtK, const u32* __restrict__ wtV,
    const float* __restrict__ y,
    const float* __restrict__ bK, const float* __restrict__ bV,
    float* __restrict__ outK, float* __restrict__ outV)
{
    const int h0  = blockIdx.x * 4;
    const int co0 = blockIdx.y * 64;
    const int b   = blockIdx.z;
    const int tid  = threadIdx.x;
    const int lane = tid & 31;
    const int w    = tid >> 5;
    const int gid  = lane >> 2;
    const int ctid = lane & 3;
    const int co_base = (w >> 2) * 32;
    const int px_base = (w & 3) * 32;

    __shared__ u32 sy[2 * 8 * 8 * 40];     // [kw][r][ci][w pad 40] 20 KB
    __shared__ u32 swK[8 * 4 * 74];        // 9.25 KB
    __shared__ u32 swV[8 * 4 * 74];        // 9.25 KB

    float accK[2][4][4], accV[2][4][4];
#pragma unroll
    for (int i = 0; i < 2; i++)
#pragma unroll
        for (int j = 0; j < 4; j++)
#pragma unroll
            for (int l = 0; l < 4; l++) { accK[i][j][l] = 0.f; accV[i][j][l] = 0.f; }

    const float* yb = y + (size_t)b * CCH * (HH * WW);
    const int ih0 = h0 * 2;

    for (int ci0 = 0; ci0 < CCH; ci0 += 8) {
        // stage input: 8 rows x 8 ci x 64 cols as float4 loads, parity split
        for (int i = tid; i < 8 * 8 * 16; i += 256) {
            int r  = i >> 7;            // 0..7
            int ci = (i >> 4) & 7;
            int c4 = (i & 15) * 4;
            float4 v = *reinterpret_cast<const float4*>(
                &yb[(size_t)(ci0 + ci) * (HH * WW) + (ih0 + r) * WW + c4]);
            u32* even = &sy[((0 * 8 + r) * 8 + ci) * 40 + (c4 >> 1)];
            u32* odd  = &sy[((8 + r) * 8 + ci) * 40 + (c4 >> 1)];
            even[0] = f2tf(v.x); odd[0] = f2tf(v.y);
            even[1] = f2tf(v.z); odd[1] = f2tf(v.w);
        }
        // stage both weight sets (scalar smem stores: stride 74 not 16B-aligned)
        for (int i = tid; i < 8 * 4 * 16; i += 256) {
            int k   = i / 128;
            int ci  = (i >> 4) & 7;
            int co4 = (i & 15) * 4;
            size_t off = ((size_t)k * 256 + ci0 + ci) * 256 + co0 + co4;
            uint4 vk = *reinterpret_cast<const uint4*>(&wtK[off]);
            uint4 vv = *reinterpret_cast<const uint4*>(&wtV[off]);
            u32* dk = &swK[(ci * 4 + k) * 74 + co4];
            dk[0] = vk.x; dk[1] = vk.y; dk[2] = vk.z; dk[3] = vk.w;
            u32* dv = &swV[(ci * 4 + k) * 74 + co4];
            dv[0] = vv.x; dv[1] = vv.y; dv[2] = vv.z; dv[3] = vv.w;
        }
        __syncthreads();

#pragma unroll
        for (int k = 0; k < 4; k++) {
            const int kh = k >> 1, kw = k & 1;
            u32 aK[2][4], aV[2][4];
#pragma unroll
            for (int rm = 0; rm < 2; rm++) {
                int cof = co_base + rm * 16;
                int r0 = (ctid * 4 + k) * 74 + cof;
                int r1 = ((ctid + 4) * 4 + k) * 74 + cof;
                aK[rm][0] = swK[r0 + gid];     aK[rm][1] = swK[r0 + gid + 8];
                aK[rm][2] = swK[r1 + gid];     aK[rm][3] = swK[r1 + gid + 8];
                aV[rm][0] = swV[r0 + gid];     aV[rm][1] = swV[r0 + gid + 8];
                aV[rm][2] = swV[r1 + gid];     aV[rm][3] = swV[r1 + gid + 8];
            }
#pragma unroll
            for (int f = 0; f < 4; f++) {
                int px = px_base + f * 8 + gid;
                int r  = 2 * (px >> 5) + kh;
                int wl = px & 31;
                u32 bf[2];
                bf[0] = sy[((kw * 8 + r) * 8 + ctid) * 40 + wl];
                bf[1] = sy[((kw * 8 + r) * 8 + ctid + 4) * 40 + wl];
                mma_tf32(accK[0][f], aK[0], bf);
                mma_tf32(accK[1][f], aK[1], bf);
                mma_tf32(accV[0][f], aV[0], bf);
                mma_tf32(accV[1][f], aV[1], bf);
            }
        }
        __syncthreads();
    }

#pragma unroll
    for (int rm = 0; rm < 2; rm++) {
#pragma unroll
        for (int f = 0; f < 4; f++) {
            int coA = co0 + co_base + rm * 16 + gid;
            int coB = coA + 8;
            int px  = px_base + f * 8 + 2 * ctid;
            int n   = (h0 + (px >> 5)) * WK + (px & 31);
            size_t oA = ((size_t)b * CCH + coA) * MM + n;
            size_t oB = ((size_t)b * CCH + coB) * MM + n;
            float bkA = bK[coA], bkB = bK[coB];
            float bvA = bV[coA], bvB = bV[coB];
            float2 kA = {accK[rm][f][0] + bkA, accK[rm][f][1] + bkA};
            float2 kB = {accK[rm][f][2] + bkB, accK[rm][f][3] + bkB};
            float2 vA = {accV[rm][f][0] + bvA, accV[rm][f][1] + bvA};
            float2 vB = {accV[rm][f][2] + bvB, accV[rm][f][3] + bvB};
            *reinterpret_cast<float2*>(&outK[oA]) = kA;
            *reinterpret_cast<float2*>(&outK[oB]) = kB;
            *reinterpret_cast<float2*>(&outV[oA]) = vA;
            *reinterpret_cast<float2*>(&outV[oB]) = vB;
        }
    }
}

// ---------------------------------------------------------------------------
// GroupNorm(32 groups of 8 ch) + affine + SiLU, in place. float4, 512 thr.
// ---------------------------------------------------------------------------
__global__ __launch_bounds__(512) void gn_silu_kernel(
    float* __restrict__ buf, const float* __restrict__ scale,
    const float* __restrict__ bias, int S)
{
    const int b = blockIdx.x >> 5;
    const int g = blockIdx.x & 31;
    float* base = buf + ((size_t)b * CCH + g * 8) * S;
    float4* p4 = reinterpret_cast<float4*>(base);
    const int tot4 = (8 * S) >> 2;
    const int tid = threadIdx.x;

    float s = 0.f, ss = 0.f;
    for (int i = tid; i < tot4; i += 512) {
        float4 v = p4[i];
        s += v.x + v.y + v.z + v.w;
        ss = fmaf(v.x, v.x, ss);
        ss = fmaf(v.y, v.y, ss);
        ss = fmaf(v.z, v.z, ss);
        ss = fmaf(v.w, v.w, ss);
    }
    __shared__ float r1[512], r2[512];
    r1[tid] = s; r2[tid] = ss;
    __syncthreads();
    for (int st = 256; st > 0; st >>= 1) {
        if (tid < st) { r1[tid] += r1[tid + st]; r2[tid] += r2[tid + st]; }
        __syncthreads();
    }
    const float tot = (float)(8 * S);
    const float mu   = r1[0] / tot;
    const float var  = r2[0] / tot - mu * mu;
    const float rstd = rsqrtf(var + 1e-5f);

    const int s4 = S >> 2;
    for (int i = tid; i < tot4; i += 512) {
        int c = g * 8 + i / s4;
        float sc = scale[c] * rstd, bi = bias[c] - mu * scale[c] * rstd;
        float4 v = p4[i];
        v.x = fmaf(v.x, sc, bi);
        v.y = fmaf(v.y, sc, bi);
        v.z = fmaf(v.z, sc, bi);
        v.w = fmaf(v.w, sc, bi);
        v.x = v.x / (1.f + __expf(-v.x));
        v.y = v.y / (1.f + __expf(-v.y));
        v.z = v.z / (1.f + __expf(-v.z));
        v.w = v.w / (1.f + __expf(-v.w));
        p4[i] = v;
    }
}

// ---------------------------------------------------------------------------
// E = (1/16) Q^T K  (tensor cores, tf32). Block 128n x 128m.
// grid: (MM/128=8, NN/128=32, B=8)
// ---------------------------------------------------------------------------
__global__ __launch_bounds__(256) void gemm_qk_mma(
    const float* __restrict__ Q, const float* __restrict__ K,
    float* __restrict__ E)
{
    const int mb = blockIdx.x * 128;
    const int nb = blockIdx.y * 128;
    const int b  = blockIdx.z;
    const int tid  = threadIdx.x;
    const int lane = tid & 31;
    const int w    = tid >> 5;
    const int gid  = lane >> 2;
    const int ctid = lane & 3;
    const int m_base = (w & 1) * 64;
    const int n_base = (w >> 1) * 32;

    __shared__ u32 sq[16 * 136];
    __shared__ u32 sk[16 * 136];

    float acc[2][8][4];
#pragma unroll
    for (int i = 0; i < 2; i++)
#pragma unroll
        for (int j = 0; j < 8; j++)
#pragma unroll
            for (int l = 0; l < 4; l++) acc[i][j][l] = 0.f;

    const float* Qb = Q + (size_t)b * CCH * NN + nb;
    const float* Kb = K + (size_t)b * CCH * MM + mb;

    for (int c0 = 0; c0 < CCH; c0 += 16) {
#pragma unroll
        for (int r = 0; r < 2; r++) {
            int s = tid + r * 256;
            int kc = s >> 5, col = (s & 31) * 4;
            float4 qv = *reinterpret_cast<const float4*>(&Qb[(size_t)(c0 + kc) * NN + col]);
            uint4 qo = {f2tf(qv.x), f2tf(qv.y), f2tf(qv.z), f2tf(qv.w)};
            *reinterpret_cast<uint4*>(&sq[kc * 136 + col]) = qo;
            float4 kv = *reinterpret_cast<const float4*>(&Kb[(size_t)(c0 + kc) * MM + col]);
            uint4 ko = {f2tf(kv.x), f2tf(kv.y), f2tf(kv.z), f2tf(kv.w)};
            *reinterpret_cast<uint4*>(&sk[kc * 136 + col]) = ko;
        }
        __syncthreads();
#pragma unroll
        for (int ks = 0; ks < 2; ks++) {
            const int k0 = ks * 8;
            u32 a[2][4];
#pragma unroll
            for (int rm = 0; rm < 2; rm++) {
                int n0 = n_base + rm * 16;
                a[rm][0] = sq[(k0 + ctid) * 136 + n0 + gid];
                a[rm][1] = sq[(k0 + ctid) * 136 + n0 + gid + 8];
                a[rm][2] = sq[(k0 + ctid + 4) * 136 + n0 + gid];
                a[rm][3] = sq[(k0 + ctid + 4) * 136 + n0 + gid + 8];
            }
#pragma unroll
            for (int f = 0; f < 8; f++) {
                u32 bf[2];
                bf[0] = sk[(k0 + ctid) * 136 + m_base + f * 8 + gid];
                bf[1] = sk[(k0 + ctid + 4) * 136 + m_base + f * 8 + gid];
                mma_tf32(acc[0][f], a[0], bf);
                mma_tf32(acc[1][f], a[1], bf);
            }
        }
        __syncthreads();
    }

    const float scale = 0.0625f;
    float* Eb = E + ((size_t)b * NN + nb) * MM + mb;
#pragma unroll
    for (int rm = 0; rm < 2; rm++) {
#pragma unroll
        for (int f = 0; f < 8; f++) {
            int r0 = n_base + rm * 16 + gid;
            int cc = m_base + f * 8 + 2 * ctid;
            float2 s0 = {acc[rm][f][0] * scale, acc[rm][f][1] * scale};
            float2 s1 = {acc[rm][f][2] * scale, acc[rm][f][3] * scale};
            *reinterpret_cast<float2*>(&Eb[(size_t)r0 * MM + cc])       = s0;
            *reinterpret_cast<float2*>(&Eb[(size_t)(r0 + 8) * MM + cc]) = s1;
        }
    }
}

// ---------------------------------------------------------------------------
// In-place softmax over last dim (M=1024). One block per row, float4.
// ---------------------------------------------------------------------------
__global__ __launch_bounds__(256) void softmax_kernel(float* __restrict__ E)
{
    float4* p = reinterpret_cast<float4*>(E + (size_t)blockIdx.x * MM);
    const int tid = threadIdx.x;

    float4 v = p[tid];
    float mx = fmaxf(fmaxf(v.x, v.y), fmaxf(v.z, v.w));
    __shared__ float red[256];
    red[tid] = mx;
    __syncthreads();
    for (int s = 128; s > 0; s >>= 1) {
        if (tid < s) red[tid] = fmaxf(red[tid], red[tid + s]);
        __syncthreads();
    }
    mx = red[0];
    __syncthreads();

    v.x = __expf(v.x - mx);
    v.y = __expf(v.y - mx);
    v.z = __expf(v.z - mx);
    v.w = __expf(v.w - mx);
    float sum = v.x + v.y + v.z + v.w;
    red[tid] = sum;
    __syncthreads();
    for (int s = 128; s > 0; s >>= 1) {
        if (tid < s) red[tid] += red[tid + s];
        __syncthreads();
    }
    float inv = 1.f / red[0];
    v.x *= inv; v.y *= inv; v.z *= inv; v.w *= inv;
    p[tid] = v;
}

// ---------------------------------------------------------------------------
// out = gamma * V A^T (tensor cores, tf32). Block 128c x 128n.
// grid: (NN/128=32, CCH/128=2, B=8)
// ---------------------------------------------------------------------------
__global__ __launch_bounds__(256) void gemm_av_mma(
    const float* __restrict__ V, const float* __restrict__ A,
    const float* __restrict__ gamma, float* __restrict__ out)
{
    const int nb = blockIdx.x * 128;
    const int cb = blockIdx.y * 128;
    const int b  = blockIdx.z;
    const int tid  = threadIdx.x;
    const int lane = tid & 31;
    const int w    = tid >> 5;
    const int gid  = lane >> 2;
    const int ctid = lane & 3;
    const int n_base = (w & 1) * 64;
    const int c_base = (w >> 1) * 32;

    __shared__ u32 sv[16 * 136];
    __shared__ u32 sa[16 * 136];

    float acc[2][8][4];
#pragma unroll
    for (int i = 0; i < 2; i++)
#pragma unroll
        for (int j = 0; j < 8; j++)
#pragma unroll
            for (int l = 0; l < 4; l++) acc[i][j][l] = 0.f;

    const float* Vb = V + (size_t)b * CCH * MM;
    const float* Ab = A + (size_t)b * NN * MM;

    for (int m0 = 0; m0 < MM; m0 += 16) {
#pragma unroll
        for (int r = 0; r < 2; r++) {
            int s = tid + r * 256;
            int row = s >> 2, f = s & 3;
            float4 vv = *reinterpret_cast<const float4*>(&Vb[(size_t)(cb + row) * MM + m0 + f * 4]);
            sv[(f * 4 + 0) * 136 + row] = f2tf(vv.x);
            sv[(f * 4 + 1) * 136 + row] = f2tf(vv.y);
            sv[(f * 4 + 2) * 136 + row] = f2tf(vv.z);
            sv[(f * 4 + 3) * 136 + row] = f2tf(vv.w);
            float4 av = *reinterpret_cast<const float4*>(&Ab[(size_t)(nb + row) * MM + m0 + f * 4]);
            sa[(f * 4 + 0) * 136 + row] = f2tf(av.x);
            sa[(f * 4 + 1) * 136 + row] = f2tf(av.y);
            sa[(f * 4 + 2) * 136 + row] = f2tf(av.z);
            sa[(f * 4 + 3) * 136 + row] = f2tf(av.w);
        }
        __syncthreads();
#pragma unroll
        for (int ks = 0; ks < 2; ks++) {
            const int k0 = ks * 8;
            u32 a[2][4];
#pragma unroll
            for (int rm = 0; rm < 2; rm++) {
                int c0 = c_base + rm * 16;
                a[rm][0] = sv[(k0 + ctid) * 136 + c0 + gid];
                a[rm][1] = sv[(k0 + ctid) * 136 + c0 + gid + 8];
                a[rm][2] = sv[(k0 + ctid + 4) * 136 + c0 + gid];
                a[rm][3] = sv[(k0 + ctid + 4) * 136 + c0 + gid + 8];
            }
#pragma unroll
            for (int f = 0; f < 8; f++) {
                u32 bf[2];
                bf[0] = sa[(k0 + ctid) * 136 + n_base + f * 8 + gid];
                bf[1] = sa[(k0 + ctid + 4) * 136 + n_base + f * 8 + gid];
                mma_tf32(acc[0][f], a[0], bf);
                mma_tf32(acc[1][f], a[1], bf);
            }
        }
        __syncthreads();
    }

    const float gm = gamma[0];
#pragma unroll
    for (int rm = 0; rm < 2; rm++) {
#pragma unroll
        for (int f = 0; f < 8; f++) {
            int c0 = cb + c_base + rm * 16 + gid;
            int nn2 = nb + n_base + f * 8 + 2 * ctid;
            float2 s0 = {gm * acc[rm][f][0], gm * acc[rm][f][1]};
            float2 s1 = {gm * acc[rm][f][2], gm * acc[rm][f][3]};
            *reinterpret_cast<float2*>(&out[((size_t)b * CCH + c0) * NN + nn2])     = s0;
            *reinterpret_cast<float2*>(&out[((size_t)b * CCH + c0 + 8) * NN + nn2]) = s1;
        }
    }
}

// ---------------------------------------------------------------------------
extern "C" void kernel_launch(void* const* d_in, const int* in_sizes, int n_in,
                              void* d_out, int out_size)
{
    const float* x        = (const float*)d_in[0];
    const float* y        = (const float*)d_in[1];
    const float* Wq       = (const float*)d_in[2];
    const float* bq       = (const float*)d_in[3];
    const float* gq_scale = (const float*)d_in[4];
    const float* gq_bias  = (const float*)d_in[5];
    const float* Wk       = (const float*)d_in[6];
    const float* bk       = (const float*)d_in[7];
    const float* gk_scale = (const float*)d_in[8];
    const float* gk_bias  = (const float*)d_in[9];
    const float* Wv       = (const float*)d_in[10];
    const float* bv       = (const float*)d_in[11];
    const float* gv_scale = (const float*)d_in[12];
    const float* gv_bias  = (const float*)d_in[13];
    const float* gamma    = (const float*)d_in[14];
    float* out = (float*)d_out;

    float *qp = nullptr, *kp = nullptr, *vp = nullptr, *ep = nullptr;
    u32 *wtp = nullptr, *wkp = nullptr, *wvp = nullptr;
    cudaGetSymbolAddress((void**)&qp, g_q);
    cudaGetSymbolAddress((void**)&kp, g_k);
    cudaGetSymbolAddress((void**)&vp, g_v);
    cudaGetSymbolAddress((void**)&ep, g_e);
    cudaGetSymbolAddress((void**)&wtp, g_wt);
    cudaGetSymbolAddress((void**)&wkp, g_wk2);
    cudaGetSymbolAddress((void**)&wvp, g_wv2);

    transpose_w3<<<(9 * 256 * 256 + 255) / 256, 256>>>(Wq, wtp);
    transpose_w2<<<(4 * 256 * 256 + 255) / 256, 256>>>(Wk, Wv, wkp, wvp);

    conv3_mma<<<dim3(HH / 2, CCH / 64, BATCH), 256>>>(wtp, x, bq, qp);
    conv2kv_mma<<<dim3(HK / 4, CCH / 64, BATCH), 256>>>(wkp, wvp, y, bk, bv, kp, vp);

    gn_silu_kernel<<<BATCH * 32, 512>>>(qp, gq_scale, gq_bias, NN);
    gn_silu_kernel<<<BATCH * 32, 512>>>(kp, gk_scale, gk_bias, MM);
    gn_silu_kernel<<<BATCH * 32, 512>>>(vp, gv_scale, gv_bias, MM);

    gemm_qk_mma<<<dim3(MM / 128, NN / 128, BATCH), 256>>>(qp, kp, ep);
    softmax_kernel<<<BATCH * NN, 256>>>(ep);
    gemm_av_mma<<<dim3(NN / 128, CCH / 128, BATCH), 256>>>(vp, ep, gamma, out);
}

// round 7
// speedup vs baseline: 5.7440x; 1.1110x over previous
#include <cuda_runtime.h>
#include <math.h>

#define BATCH 8
#define CCH   256
#define HH    64
#define WW    64
#define NN    4096   // HH*WW
#define MM    1024   // (HH/2)*(WW/2)
#define HK    32
#define WK    32

typedef unsigned long long u64;
typedef unsigned int u32;

__device__ __forceinline__ u32 f2tf(float f) {
    u32 u; asm("cvt.rna.tf32.f32 %0,%1;" : "=r"(u) : "f"(f)); return u;
}
__device__ __forceinline__ void mma_tf32(float* d, const u32* a, const u32* b) {
    asm volatile(
        "mma.sync.aligned.m16n8k8.row.col.f32.tf32.tf32.f32 "
        "{%0,%1,%2,%3},{%4,%5,%6,%7},{%8,%9},{%0,%1,%2,%3};"
        : "+f"(d[0]), "+f"(d[1]), "+f"(d[2]), "+f"(d[3])
        : "r"(a[0]), "r"(a[1]), "r"(a[2]), "r"(a[3]), "r"(b[0]), "r"(b[1]));
}

// Scratch
__device__ float g_q[(size_t)BATCH * CCH * NN];   // 32 MB
__device__ float g_k[(size_t)BATCH * CCH * MM];   // 8 MB
__device__ float g_v[(size_t)BATCH * CCH * MM];   // 8 MB
__device__ float g_e[(size_t)BATCH * NN * MM];    // 128 MB
__device__ u32   g_wt[9 * 256 * 256];             // Wq transposed, tf32
__device__ u32   g_wk2[4 * 256 * 256];            // Wk transposed, tf32
__device__ u32   g_wv2[4 * 256 * 256];            // Wv transposed, tf32

// ---------------------------------------------------------------------------
__global__ __launch_bounds__(256) void transpose_w3(
    const float* __restrict__ Wt, u32* __restrict__ wt2)
{
    int i = blockIdx.x * 256 + threadIdx.x;
    if (i < 9 * 256 * 256) {
        int co = i & 255;
        int ci = (i >> 8) & 255;
        int k  = i >> 16;
        wt2[i] = f2tf(Wt[((size_t)co * 256 + ci) * 9 + k]);
    }
}

__global__ __launch_bounds__(256) void transpose_w2(
    const float* __restrict__ Wk, const float* __restrict__ Wv,
    u32* __restrict__ wk2, u32* __restrict__ wv2)
{
    int i = blockIdx.x * 256 + threadIdx.x;
    if (i < 4 * 256 * 256) {
        int co = i & 255;
        int ci = (i >> 8) & 255;
        int k  = i >> 16;
        wk2[i] = f2tf(Wk[((size_t)co * 256 + ci) * 4 + k]);
        wv2[i] = f2tf(Wv[((size_t)co * 256 + ci) * 4 + k]);
    }
}

// ---------------------------------------------------------------------------
// 3x3 conv s1 p1, implicit GEMM tf32, input prefetch double-buffered.
// grid: (HH/2=32, CCH/64=4, B=8)
// ---------------------------------------------------------------------------
__global__ __launch_bounds__(256, 2) void conv3_mma(
    const u32* __restrict__ wt2, const float* __restrict__ x,
    const float* __restrict__ bias, float* __restrict__ out)
{
    const int h0  = blockIdx.x * 2;
    const int co0 = blockIdx.y * 64;
    const int b   = blockIdx.z;
    const int tid  = threadIdx.x;
    const int lane = tid & 31;
    const int w    = tid >> 5;
    const int gid  = lane >> 2;
    const int ctid = lane & 3;
    const int co_base = (w >> 2) * 32;
    const int px_base = (w & 3) * 32;

    __shared__ u32 sxt[4 * 8 * 72];   // [r][ci][col pad 72]
    __shared__ u32 swt[8 * 9 * 72];   // [ci][k][co pad 72]

    float acc[2][4][4];
#pragma unroll
    for (int i = 0; i < 2; i++)
#pragma unroll
        for (int j = 0; j < 4; j++)
#pragma unroll
            for (int l = 0; l < 4; l++) acc[i][j][l] = 0.f;

    const float* xb = x + (size_t)b * CCH * (HH * WW);

    // prefetch regs: 2112 elems / 256 thr = 9 predicated loads
    float pin[9], pin2[9];

#define C3_LOAD(dst, CI0)                                                  \
    {                                                                      \
        _Pragma("unroll")                                                  \
        for (int j = 0; j < 9; j++) {                                      \
            int i = tid + j * 256;                                         \
            if (i < 2112) {                                                \
                int r   = i / (8 * 66);                                    \
                int ci  = (i / 66) & 7;                                    \
                int col = i % 66;                                          \
                int gh = h0 - 1 + r;                                       \
                int gw = col - 1;                                          \
                float v = 0.f;                                             \
                if ((unsigned)gh < HH && (unsigned)gw < WW)                \
                    v = xb[(size_t)((CI0) + ci) * (HH * WW) + gh * WW + gw];\
                dst[j] = v;                                                \
            }                                                              \
        }                                                                  \
    }

    C3_LOAD(pin, 0);

    for (int ci0 = 0; ci0 < CCH; ci0 += 8) {
        // store prefetched input
#pragma unroll
        for (int j = 0; j < 9; j++) {
            int i = tid + j * 256;
            if (i < 2112) {
                int r   = i / (8 * 66);
                int ci  = (i / 66) & 7;
                int col = i % 66;
                sxt[(r * 8 + ci) * 72 + col] = f2tf(pin[j]);
            }
        }
        // stage weights (L2-hot)
        for (int i = tid; i < 8 * 9 * 16; i += 256) {
            int k   = i / 128;
            int ci  = (i >> 4) & 7;
            int co4 = (i & 15) * 4;
            uint4 v = *reinterpret_cast<const uint4*>(
                &wt2[((size_t)k * 256 + ci0 + ci) * 256 + co0 + co4]);
            *reinterpret_cast<uint4*>(&swt[(ci * 9 + k) * 72 + co4]) = v;
        }
        __syncthreads();

        if (ci0 + 8 < CCH) C3_LOAD(pin2, ci0 + 8);

#pragma unroll
        for (int k = 0; k < 9; k++) {
            const int kh = k / 3, kw = k % 3;
            u32 a[2][4];
#pragma unroll
            for (int rm = 0; rm < 2; rm++) {
                int cof = co_base + rm * 16;
                a[rm][0] = swt[((ctid) * 9 + k) * 72 + cof + gid];
                a[rm][1] = swt[((ctid) * 9 + k) * 72 + cof + gid + 8];
                a[rm][2] = swt[((ctid + 4) * 9 + k) * 72 + cof + gid];
                a[rm][3] = swt[((ctid + 4) * 9 + k) * 72 + cof + gid + 8];
            }
#pragma unroll
            for (int f = 0; f < 4; f++) {
                int px = px_base + f * 8 + gid;
                int rl = px >> 6;
                int wc = (px & 63) + kw;
                u32 bf[2];
                bf[0] = sxt[((rl + kh) * 8 + ctid) * 72 + wc];
                bf[1] = sxt[((rl + kh) * 8 + ctid + 4) * 72 + wc];
                mma_tf32(acc[0][f], a[0], bf);
                mma_tf32(acc[1][f], a[1], bf);
            }
        }
        __syncthreads();

#pragma unroll
        for (int j = 0; j < 9; j++) pin[j] = pin2[j];
    }

#pragma unroll
    for (int rm = 0; rm < 2; rm++) {
#pragma unroll
        for (int f = 0; f < 4; f++) {
            int coA = co0 + co_base + rm * 16 + gid;
            int coB = coA + 8;
            int px  = px_base + f * 8 + 2 * ctid;
            int n   = (h0 + (px >> 6)) * WW + (px & 63);
            float bA = bias[coA], bB = bias[coB];
            float2 sA = {acc[rm][f][0] + bA, acc[rm][f][1] + bA};
            float2 sB = {acc[rm][f][2] + bB, acc[rm][f][3] + bB};
            *reinterpret_cast<float2*>(&out[((size_t)b * CCH + coA) * NN + n]) = sA;
            *reinterpret_cast<float2*>(&out[((size_t)b * CCH + coB) * NN + n]) = sB;
        }
    }
}

// ---------------------------------------------------------------------------
// FUSED K+V 2x2 conv s2 p0, implicit GEMM tf32, input prefetch double-buffered.
// grid: (HK/4=8, CCH/64=4, B=8)
// ---------------------------------------------------------------------------
__global__ __launch_bounds__(256, 2) void conv2kv_mma(
    const u32* __restrict__ wtK, const u32* __restrict__ wtV,
    const float* __restrict__ y,
    const float* __restrict__ bK, const float* __restrict__ bV,
    float* __restrict__ outK, float* __restrict__ outV)
{
    const int h0  = blockIdx.x * 4;
    const int co0 = blockIdx.y * 64;
    const int b   = blockIdx.z;
    const int tid  = threadIdx.x;
    const int lane = tid & 31;
    const int w    = tid >> 5;
    const int gid  = lane >> 2;
    const int ctid = lane & 3;
    const int co_base = (w >> 2) * 32;
    const int px_base = (w & 3) * 32;

    __shared__ u32 sy[2 * 8 * 8 * 40];     // [kw][r][ci][w pad 40] 20 KB
    __shared__ u32 swK[8 * 4 * 74];        // 9.25 KB
    __shared__ u32 swV[8 * 4 * 74];        // 9.25 KB

    float accK[2][4][4], accV[2][4][4];
#pragma unroll
    for (int i = 0; i < 2; i++)
#pragma unroll
        for (int j = 0; j < 4; j++)
#pragma unroll
            for (int l = 0; l < 4; l++) { accK[i][j][l] = 0.f; accV[i][j][l] = 0.f; }

    const float* yb = y + (size_t)b * CCH * (HH * WW);
    const int ih0 = h0 * 2;

    float4 pin[4], pin2[4];

#define C2_LOAD(dst, CI0)                                                   \
    {                                                                       \
        _Pragma("unroll")                                                   \
        for (int j = 0; j < 4; j++) {                                       \
            int i  = tid + j * 256;                                         \
            int r  = i >> 7;                                                \
            int ci = (i >> 4) & 7;                                          \
            int c4 = (i & 15) * 4;                                          \
            dst[j] = *reinterpret_cast<const float4*>(                      \
                &yb[(size_t)((CI0) + ci) * (HH * WW) + (ih0 + r) * WW + c4]);\
        }                                                                   \
    }

    C2_LOAD(pin, 0);

    for (int ci0 = 0; ci0 < CCH; ci0 += 8) {
        // store prefetched input (parity split)
#pragma unroll
        for (int j = 0; j < 4; j++) {
            int i  = tid + j * 256;
            int r  = i >> 7;
            int ci = (i >> 4) & 7;
            int c4 = (i & 15) * 4;
            float4 v = pin[j];
            u32* even = &sy[((0 * 8 + r) * 8 + ci) * 40 + (c4 >> 1)];
            u32* odd  = &sy[((8 + r) * 8 + ci) * 40 + (c4 >> 1)];
            even[0] = f2tf(v.x); odd[0] = f2tf(v.y);
            even[1] = f2tf(v.z); odd[1] = f2tf(v.w);
        }
        // stage both weight sets (L2-hot; scalar stores due to stride 74)
        for (int i = tid; i < 8 * 4 * 16; i += 256) {
            int k   = i / 128;
            int ci  = (i >> 4) & 7;
            int co4 = (i & 15) * 4;
            size_t off = ((size_t)k * 256 + ci0 + ci) * 256 + co0 + co4;
            uint4 vk = *reinterpret_cast<const uint4*>(&wtK[off]);
            uint4 vv = *reinterpret_cast<const uint4*>(&wtV[off]);
            u32* dk = &swK[(ci * 4 + k) * 74 + co4];
            dk[0] = vk.x; dk[1] = vk.y; dk[2] = vk.z; dk[3] = vk.w;
            u32* dv = &swV[(ci * 4 + k) * 74 + co4];
            dv[0] = vv.x; dv[1] = vv.y; dv[2] = vv.z; dv[3] = vv.w;
        }
        __syncthreads();

        if (ci0 + 8 < CCH) C2_LOAD(pin2, ci0 + 8);

#pragma unroll
        for (int k = 0; k < 4; k++) {
            const int kh = k >> 1, kw = k & 1;
            u32 aK[2][4], aV[2][4];
#pragma unroll
            for (int rm = 0; rm < 2; rm++) {
                int cof = co_base + rm * 16;
                int r0 = (ctid * 4 + k) * 74 + cof;
                int r1 = ((ctid + 4) * 4 + k) * 74 + cof;
                aK[rm][0] = swK[r0 + gid];     aK[rm][1] = swK[r0 + gid + 8];
                aK[rm][2] = swK[r1 + gid];     aK[rm][3] = swK[r1 + gid + 8];
                aV[rm][0] = swV[r0 + gid];     aV[rm][1] = swV[r0 + gid + 8];
                aV[rm][2] = swV[r1 + gid];     aV[rm][3] = swV[r1 + gid + 8];
            }
#pragma unroll
            for (int f = 0; f < 4; f++) {
                int px = px_base + f * 8 + gid;
                int r  = 2 * (px >> 5) + kh;
                int wl = px & 31;
                u32 bf[2];
                bf[0] = sy[((kw * 8 + r) * 8 + ctid) * 40 + wl];
                bf[1] = sy[((kw * 8 + r) * 8 + ctid + 4) * 40 + wl];
                mma_tf32(accK[0][f], aK[0], bf);
                mma_tf32(accK[1][f], aK[1], bf);
                mma_tf32(accV[0][f], aV[0], bf);
                mma_tf32(accV[1][f], aV[1], bf);
            }
        }
        __syncthreads();

#pragma unroll
        for (int j = 0; j < 4; j++) pin[j] = pin2[j];
    }

#pragma unroll
    for (int rm = 0; rm < 2; rm++) {
#pragma unroll
        for (int f = 0; f < 4; f++) {
            int coA = co0 + co_base + rm * 16 + gid;
            int coB = coA + 8;
            int px  = px_base + f * 8 + 2 * ctid;
            int n   = (h0 + (px >> 5)) * WK + (px & 31);
            size_t oA = ((size_t)b * CCH + coA) * MM + n;
            size_t oB = ((size_t)b * CCH + coB) * MM + n;
            float bkA = bK[coA], bkB = bK[coB];
            float bvA = bV[coA], bvB = bV[coB];
            float2 kA = {accK[rm][f][0] + bkA, accK[rm][f][1] + bkA};
            float2 kB = {accK[rm][f][2] + bkB, accK[rm][f][3] + bkB};
            float2 vA = {accV[rm][f][0] + bvA, accV[rm][f][1] + bvA};
            float2 vB = {accV[rm][f][2] + bvB, accV[rm][f][3] + bvB};
            *reinterpret_cast<float2*>(&outK[oA]) = kA;
            *reinterpret_cast<float2*>(&outK[oB]) = kB;
            *reinterpret_cast<float2*>(&outV[oA]) = vA;
            *reinterpret_cast<float2*>(&outV[oB]) = vB;
        }
    }
}

// ---------------------------------------------------------------------------
// GroupNorm(32 groups of 8 ch) + affine + SiLU, in place. float4, 512 thr.
// ---------------------------------------------------------------------------
__global__ __launch_bounds__(512) void gn_silu_kernel(
    float* __restrict__ buf, const float* __restrict__ scale,
    const float* __restrict__ bias, int S)
{
    const int b = blockIdx.x >> 5;
    const int g = blockIdx.x & 31;
    float* base = buf + ((size_t)b * CCH + g * 8) * S;
    float4* p4 = reinterpret_cast<float4*>(base);
    const int tot4 = (8 * S) >> 2;
    const int tid = threadIdx.x;

    float s = 0.f, ss = 0.f;
    for (int i = tid; i < tot4; i += 512) {
        float4 v = p4[i];
        s += v.x + v.y + v.z + v.w;
        ss = fmaf(v.x, v.x, ss);
        ss = fmaf(v.y, v.y, ss);
        ss = fmaf(v.z, v.z, ss);
        ss = fmaf(v.w, v.w, ss);
    }
    __shared__ float r1[512], r2[512];
    r1[tid] = s; r2[tid] = ss;
    __syncthreads();
    for (int st = 256; st > 0; st >>= 1) {
        if (tid < st) { r1[tid] += r1[tid + st]; r2[tid] += r2[tid + st]; }
        __syncthreads();
    }
    const float tot = (float)(8 * S);
    const float mu   = r1[0] / tot;
    const float var  = r2[0] / tot - mu * mu;
    const float rstd = rsqrtf(var + 1e-5f);

    const int s4 = S >> 2;
    for (int i = tid; i < tot4; i += 512) {
        int c = g * 8 + i / s4;
        float sc = scale[c] * rstd, bi = bias[c] - mu * scale[c] * rstd;
        float4 v = p4[i];
        v.x = fmaf(v.x, sc, bi);
        v.y = fmaf(v.y, sc, bi);
        v.z = fmaf(v.z, sc, bi);
        v.w = fmaf(v.w, sc, bi);
        v.x = v.x / (1.f + __expf(-v.x));
        v.y = v.y / (1.f + __expf(-v.y));
        v.z = v.z / (1.f + __expf(-v.z));
        v.w = v.w / (1.f + __expf(-v.w));
        p4[i] = v;
    }
}

// ---------------------------------------------------------------------------
// E = (1/16) Q^T K  tf32, staged loads double-buffered.
// grid: (MM/128=8, NN/128=32, B=8)
// ---------------------------------------------------------------------------
__global__ __launch_bounds__(256, 2) void gemm_qk_mma(
    const float* __restrict__ Q, const float* __restrict__ K,
    float* __restrict__ E)
{
    const int mb = blockIdx.x * 128;
    const int nb = blockIdx.y * 128;
    const int b  = blockIdx.z;
    const int tid  = threadIdx.x;
    const int lane = tid & 31;
    const int w    = tid >> 5;
    const int gid  = lane >> 2;
    const int ctid = lane & 3;
    const int m_base = (w & 1) * 64;
    const int n_base = (w >> 1) * 32;

    __shared__ u32 sq[16 * 136];
    __shared__ u32 sk[16 * 136];

    float acc[2][8][4];
#pragma unroll
    for (int i = 0; i < 2; i++)
#pragma unroll
        for (int j = 0; j < 8; j++)
#pragma unroll
            for (int l = 0; l < 4; l++) acc[i][j][l] = 0.f;

    const float* Qb = Q + (size_t)b * CCH * NN + nb;
    const float* Kb = K + (size_t)b * CCH * MM + mb;

    const int kc0 = tid >> 5, col0 = (tid & 31) * 4;
    const int kc1 = (tid + 256) >> 5, col1 = ((tid + 256) & 31) * 4;

    float4 pq[2], pk[2], pq2[2], pk2[2];

#define QK_LOAD(dq, dk, C0)                                                         \
    {                                                                               \
        dq[0] = *reinterpret_cast<const float4*>(&Qb[(size_t)((C0) + kc0) * NN + col0]); \
        dq[1] = *reinterpret_cast<const float4*>(&Qb[(size_t)((C0) + kc1) * NN + col1]); \
        dk[0] = *reinterpret_cast<const float4*>(&Kb[(size_t)((C0) + kc0) * MM + col0]); \
        dk[1] = *reinterpret_cast<const float4*>(&Kb[(size_t)((C0) + kc1) * MM + col1]); \
    }

    QK_LOAD(pq, pk, 0);

    for (int c0 = 0; c0 < CCH; c0 += 16) {
        uint4 q0 = {f2tf(pq[0].x), f2tf(pq[0].y), f2tf(pq[0].z), f2tf(pq[0].w)};
        uint4 q1 = {f2tf(pq[1].x), f2tf(pq[1].y), f2tf(pq[1].z), f2tf(pq[1].w)};
        uint4 k0v = {f2tf(pk[0].x), f2tf(pk[0].y), f2tf(pk[0].z), f2tf(pk[0].w)};
        uint4 k1v = {f2tf(pk[1].x), f2tf(pk[1].y), f2tf(pk[1].z), f2tf(pk[1].w)};
        *reinterpret_cast<uint4*>(&sq[kc0 * 136 + col0]) = q0;
        *reinterpret_cast<uint4*>(&sq[kc1 * 136 + col1]) = q1;
        *reinterpret_cast<uint4*>(&sk[kc0 * 136 + col0]) = k0v;
        *reinterpret_cast<uint4*>(&sk[kc1 * 136 + col1]) = k1v;
        __syncthreads();

        if (c0 + 16 < CCH) QK_LOAD(pq2, pk2, c0 + 16);

#pragma unroll
        for (int ks = 0; ks < 2; ks++) {
            const int k0 = ks * 8;
            u32 a[2][4];
#pragma unroll
            for (int rm = 0; rm < 2; rm++) {
                int n0 = n_base + rm * 16;
                a[rm][0] = sq[(k0 + ctid) * 136 + n0 + gid];
                a[rm][1] = sq[(k0 + ctid) * 136 + n0 + gid + 8];
                a[rm][2] = sq[(k0 + ctid + 4) * 136 + n0 + gid];
                a[rm][3] = sq[(k0 + ctid + 4) * 136 + n0 + gid + 8];
            }
#pragma unroll
            for (int f = 0; f < 8; f++) {
                u32 bf[2];
                bf[0] = sk[(k0 + ctid) * 136 + m_base + f * 8 + gid];
                bf[1] = sk[(k0 + ctid + 4) * 136 + m_base + f * 8 + gid];
                mma_tf32(acc[0][f], a[0], bf);
                mma_tf32(acc[1][f], a[1], bf);
            }
        }
        __syncthreads();

        pq[0] = pq2[0]; pq[1] = pq2[1]; pk[0] = pk2[0]; pk[1] = pk2[1];
    }

    const float scale = 0.0625f;
    float* Eb = E + ((size_t)b * NN + nb) * MM + mb;
#pragma unroll
    for (int rm = 0; rm < 2; rm++) {
#pragma unroll
        for (int f = 0; f < 8; f++) {
            int r0 = n_base + rm * 16 + gid;
            int cc = m_base + f * 8 + 2 * ctid;
            float2 s0 = {acc[rm][f][0] * scale, acc[rm][f][1] * scale};
            float2 s1 = {acc[rm][f][2] * scale, acc[rm][f][3] * scale};
            *reinterpret_cast<float2*>(&Eb[(size_t)r0 * MM + cc])       = s0;
            *reinterpret_cast<float2*>(&Eb[(size_t)(r0 + 8) * MM + cc]) = s1;
        }
    }
}

// ---------------------------------------------------------------------------
// In-place softmax over last dim (M=1024). One block per row, float4.
// ---------------------------------------------------------------------------
__global__ __launch_bounds__(256) void softmax_kernel(float* __restrict__ E)
{
    float4* p = reinterpret_cast<float4*>(E + (size_t)blockIdx.x * MM);
    const int tid = threadIdx.x;

    float4 v = p[tid];
    float mx = fmaxf(fmaxf(v.x, v.y), fmaxf(v.z, v.w));
    __shared__ float red[256];
    red[tid] = mx;
    __syncthreads();
    for (int s = 128; s > 0; s >>= 1) {
        if (tid < s) red[tid] = fmaxf(red[tid], red[tid + s]);
        __syncthreads();
    }
    mx = red[0];
    __syncthreads();

    v.x = __expf(v.x - mx);
    v.y = __expf(v.y - mx);
    v.z = __expf(v.z - mx);
    v.w = __expf(v.w - mx);
    float sum = v.x + v.y + v.z + v.w;
    red[tid] = sum;
    __syncthreads();
    for (int s = 128; s > 0; s >>= 1) {
        if (tid < s) red[tid] += red[tid + s];
        __syncthreads();
    }
    float inv = 1.f / red[0];
    v.x *= inv; v.y *= inv; v.z *= inv; v.w *= inv;
    p[tid] = v;
}

// ---------------------------------------------------------------------------
// out = gamma * V A^T tf32, staged loads double-buffered.
// grid: (NN/128=32, CCH/128=2, B=8)
// ---------------------------------------------------------------------------
__global__ __launch_bounds__(256, 2) void gemm_av_mma(
    const float* __restrict__ V, const float* __restrict__ A,
    const float* __restrict__ gamma, float* __restrict__ out)
{
    const int nb = blockIdx.x * 128;
    const int cb = blockIdx.y * 128;
    const int b  = blockIdx.z;
    const int tid  = threadIdx.x;
    const int lane = tid & 31;
    const int w    = tid >> 5;
    const int gid  = lane >> 2;
    const int ctid = lane & 3;
    const int n_base = (w & 1) * 64;
    const int c_base = (w >> 1) * 32;

    __shared__ u32 sv[16 * 136];
    __shared__ u32 sa[16 * 136];

    float acc[2][8][4];
#pragma unroll
    for (int i = 0; i < 2; i++)
#pragma unroll
        for (int j = 0; j < 8; j++)
#pragma unroll
            for (int l = 0; l < 4; l++) acc[i][j][l] = 0.f;

    const float* Vb = V + (size_t)b * CCH * MM;
    const float* Ab = A + (size_t)b * NN * MM;

    const int row0 = tid >> 2, f0 = tid & 3;
    const int row1 = (tid + 256) >> 2, f1 = (tid + 256) & 3;

    float4 pv[2], pa[2], pv2[2], pa2[2];

#define AV_LOAD(dv, da, M0)                                                               \
    {                                                                                     \
        dv[0] = *reinterpret_cast<const float4*>(&Vb[(size_t)(cb + row0) * MM + (M0) + f0 * 4]); \
        dv[1] = *reinterpret_cast<const float4*>(&Vb[(size_t)(cb + row1) * MM + (M0) + f1 * 4]); \
        da[0] = *reinterpret_cast<const float4*>(&Ab[(size_t)(nb + row0) * MM + (M0) + f0 * 4]); \
        da[1] = *reinterpret_cast<const float4*>(&Ab[(size_t)(nb + row1) * MM + (M0) + f1 * 4]); \
    }

    AV_LOAD(pv, pa, 0);

    for (int m0 = 0; m0 < MM; m0 += 16) {
        sv[(f0 * 4 + 0) * 136 + row0] = f2tf(pv[0].x);
        sv[(f0 * 4 + 1) * 136 + row0] = f2tf(pv[0].y);
        sv[(f0 * 4 + 2) * 136 + row0] = f2tf(pv[0].z);
        sv[(f0 * 4 + 3) * 136 + row0] = f2tf(pv[0].w);
        sv[(f1 * 4 + 0) * 136 + row1] = f2tf(pv[1].x);
        sv[(f1 * 4 + 1) * 136 + row1] = f2tf(pv[1].y);
        sv[(f1 * 4 + 2) * 136 + row1] = f2tf(pv[1].z);
        sv[(f1 * 4 + 3) * 136 + row1] = f2tf(pv[1].w);
        sa[(f0 * 4 + 0) * 136 + row0] = f2tf(pa[0].x);
        sa[(f0 * 4 + 1) * 136 + row0] = f2tf(pa[0].y);
        sa[(f0 * 4 + 2) * 136 + row0] = f2tf(pa[0].z);
        sa[(f0 * 4 + 3) * 136 + row0] = f2tf(pa[0].w);
        sa[(f1 * 4 + 0) * 136 + row1] = f2tf(pa[1].x);
        sa[(f1 * 4 + 1) * 136 + row1] = f2tf(pa[1].y);
        sa[(f1 * 4 + 2) * 136 + row1] = f2tf(pa[1].z);
        sa[(f1 * 4 + 3) * 136 + row1] = f2tf(pa[1].w);
        __syncthreads();

        if (m0 + 16 < MM) AV_LOAD(pv2, pa2, m0 + 16);

#pragma unroll
        for (int ks = 0; ks < 2; ks++) {
            const int k0 = ks * 8;
            u32 a[2][4];
#pragma unroll
            for (int rm = 0; rm < 2; rm++) {
                int c0 = c_base + rm * 16;
                a[rm][0] = sv[(k0 + ctid) * 136 + c0 + gid];
                a[rm][1] = sv[(k0 + ctid) * 136 + c0 + gid + 8];
                a[rm][2] = sv[(k0 + ctid + 4) * 136 + c0 + gid];
                a[rm][3] = sv[(k0 + ctid + 4) * 136 + c0 + gid + 8];
            }
#pragma unroll
            for (int f = 0; f < 8; f++) {
                u32 bf[2];
                bf[0] = sa[(k0 + ctid) * 136 + n_base + f * 8 + gid];
                bf[1] = sa[(k0 + ctid + 4) * 136 + n_base + f * 8 + gid];
                mma_tf32(acc[0][f], a[0], bf);
                mma_tf32(acc[1][f], a[1], bf);
            }
        }
        __syncthreads();

        pv[0] = pv2[0]; pv[1] = pv2[1]; pa[0] = pa2[0]; pa[1] = pa2[1];
    }

    const float gm = gamma[0];
#pragma unroll
    for (int rm = 0; rm < 2; rm++) {
#pragma unroll
        for (int f = 0; f < 8; f++) {
            int c0 = cb + c_base + rm * 16 + gid;
            int nn2 = nb + n_base + f * 8 + 2 * ctid;
            float2 s0 = {gm * acc[rm][f][0], gm * acc[rm][f][1]};
            float2 s1 = {gm * acc[rm][f][2], gm * acc[rm][f][3]};
            *reinterpret_cast<float2*>(&out[((size_t)b * CCH + c0) * NN + nn2])     = s0;
            *reinterpret_cast<float2*>(&out[((size_t)b * CCH + c0 + 8) * NN + nn2]) = s1;
        }
    }
}

// ---------------------------------------------------------------------------
extern "C" void kernel_launch(void* const* d_in, const int* in_sizes, int n_in,
                              void* d_out, int out_size)
{
    const float* x        = (const float*)d_in[0];
    const float* y        = (const float*)d_in[1];
    const float* Wq       = (const float*)d_in[2];
    const float* bq       = (const float*)d_in[3];
    const float* gq_scale = (const float*)d_in[4];
    const float* gq_bias  = (const float*)d_in[5];
    const float* Wk       = (const float*)d_in[6];
    const float* bk       = (const float*)d_in[7];
    const float* gk_scale = (const float*)d_in[8];
    const float* gk_bias  = (const float*)d_in[9];
    const float* Wv       = (const float*)d_in[10];
    const float* bv       = (const float*)d_in[11];
    const float* gv_scale = (const float*)d_in[12];
    const float* gv_bias  = (const float*)d_in[13];
    const float* gamma    = (const float*)d_in[14];
    float* out = (float*)d_out;

    float *qp = nullptr, *kp = nullptr, *vp = nullptr, *ep = nullptr;
    u32 *wtp = nullptr, *wkp = nullptr, *wvp = nullptr;
    cudaGetSymbolAddress((void**)&qp, g_q);
    cudaGetSymbolAddress((void**)&kp, g_k);
    cudaGetSymbolAddress((void**)&vp, g_v);
    cudaGetSymbolAddress((void**)&ep, g_e);
    cudaGetSymbolAddress((void**)&wtp, g_wt);
    cudaGetSymbolAddress((void**)&wkp, g_wk2);
    cudaGetSymbolAddress((void**)&wvp, g_wv2);

    transpose_w3<<<(9 * 256 * 256 + 255) / 256, 256>>>(Wq, wtp);
    transpose_w2<<<(4 * 256 * 256 + 255) / 256, 256>>>(Wk, Wv, wkp, wvp);

    conv3_mma<<<dim3(HH / 2, CCH / 64, BATCH), 256>>>(wtp, x, bq, qp);
    conv2kv_mma<<<dim3(HK / 4, CCH / 64, BATCH), 256>>>(wkp, wvp, y, bk, bv, kp, vp);

    gn_silu_kernel<<<BATCH * 32, 512>>>(qp, gq_scale, gq_bias, NN);
    gn_silu_kernel<<<BATCH * 32, 512>>>(kp, gk_scale, gk_bias, MM);
    gn_silu_kernel<<<BATCH * 32, 512>>>(vp, gv_scale, gv_bias, MM);

    gemm_qk_mma<<<dim3(MM / 128, NN / 128, BATCH), 256>>>(qp, kp, ep);
    softmax_kernel<<<BATCH * NN, 256>>>(ep);
    gemm_av_mma<<<dim3(NN / 128, CCH / 128, BATCH), 256>>>(vp, ep, gamma, out);
}

// round 8
// speedup vs baseline: 6.1130x; 1.0642x over previous
#include <cuda_runtime.h>
#include <math.h>

#define BATCH 8
#define CCH   256
#define HH    64
#define WW    64
#define NN    4096   // HH*WW
#define MM    1024   // (HH/2)*(WW/2)
#define HK    32
#define WK    32

typedef unsigned long long u64;
typedef unsigned int u32;

__device__ __forceinline__ u32 f2tf(float f) {
    u32 u; asm("cvt.rna.tf32.f32 %0,%1;" : "=r"(u) : "f"(f)); return u;
}
__device__ __forceinline__ void mma_tf32(float* d, const u32* a, const u32* b) {
    asm volatile(
        "mma.sync.aligned.m16n8k8.row.col.f32.tf32.tf32.f32 "
        "{%0,%1,%2,%3},{%4,%5,%6,%7},{%8,%9},{%0,%1,%2,%3};"
        : "+f"(d[0]), "+f"(d[1]), "+f"(d[2]), "+f"(d[3])
        : "r"(a[0]), "r"(a[1]), "r"(a[2]), "r"(a[3]), "r"(b[0]), "r"(b[1]));
}

// Scratch
__device__ float g_q[(size_t)BATCH * CCH * NN];   // 32 MB
__device__ float g_k[(size_t)BATCH * CCH * MM];   // 8 MB
__device__ float g_v[(size_t)BATCH * CCH * MM];   // 8 MB
__device__ float g_e[(size_t)BATCH * NN * MM];    // 128 MB
__device__ u32   g_wt[9 * 256 * 256];             // Wq transposed, tf32
__device__ u32   g_wk2[4 * 256 * 256];            // Wk transposed, tf32
__device__ u32   g_wv2[4 * 256 * 256];            // Wv transposed, tf32

// ---------------------------------------------------------------------------
__global__ __launch_bounds__(256) void transpose_w3(
    const float* __restrict__ Wt, u32* __restrict__ wt2)
{
    int i = blockIdx.x * 256 + threadIdx.x;
    if (i < 9 * 256 * 256) {
        int co = i & 255;
        int ci = (i >> 8) & 255;
        int k  = i >> 16;
        wt2[i] = f2tf(Wt[((size_t)co * 256 + ci) * 9 + k]);
    }
}

__global__ __launch_bounds__(256) void transpose_w2(
    const float* __restrict__ Wk, const float* __restrict__ Wv,
    u32* __restrict__ wk2, u32* __restrict__ wv2)
{
    int i = blockIdx.x * 256 + threadIdx.x;
    if (i < 4 * 256 * 256) {
        int co = i & 255;
        int ci = (i >> 8) & 255;
        int k  = i >> 16;
        wk2[i] = f2tf(Wk[((size_t)co * 256 + ci) * 4 + k]);
        wv2[i] = f2tf(Wv[((size_t)co * 256 + ci) * 4 + k]);
    }
}

// ---------------------------------------------------------------------------
// 3x3 conv s1 p1, implicit GEMM tf32, 4 output rows per block, prefetched.
// Block: 64 co x 256 px. 8 warps (2co x 4px), warp tile 32co x 64px.
// grid: (HH/4=16, CCH/64=4, B=8)
// ---------------------------------------------------------------------------
__global__ __launch_bounds__(256, 2) void conv3_mma(
    const u32* __restrict__ wt2, const float* __restrict__ x,
    const float* __restrict__ bias, float* __restrict__ out)
{
    const int h0  = blockIdx.x * 4;
    const int co0 = blockIdx.y * 64;
    const int b   = blockIdx.z;
    const int tid  = threadIdx.x;
    const int lane = tid & 31;
    const int w    = tid >> 5;
    const int gid  = lane >> 2;
    const int ctid = lane & 3;
    const int co_base = (w >> 2) * 32;
    const int px_base = (w & 3) * 64;

    __shared__ u32 sxt[6 * 8 * 72];   // rows h0-1..h0+4, [r][ci][col pad 72]
    __shared__ u32 swt[8 * 9 * 72];   // [ci][k][co pad 72]

    float acc[2][8][4];
#pragma unroll
    for (int i = 0; i < 2; i++)
#pragma unroll
        for (int j = 0; j < 8; j++)
#pragma unroll
            for (int l = 0; l < 4; l++) acc[i][j][l] = 0.f;

    const float* xb = x + (size_t)b * CCH * (HH * WW);

    // staging: 6 rows x 8 ci x 66 cols = 3168 elems -> 13 predicated loads
    float pin[13], pin2[13];

#define C3_LOAD(dst, CI0)                                                  \
    {                                                                      \
        _Pragma("unroll")                                                  \
        for (int j = 0; j < 13; j++) {                                     \
            int i = tid + j * 256;                                         \
            if (i < 3168) {                                                \
                int r   = i / 528;                                         \
                int ci  = (i / 66) & 7;                                    \
                int col = i % 66;                                          \
                int gh = h0 - 1 + r;                                       \
                int gw = col - 1;                                          \
                float v = 0.f;                                             \
                if ((unsigned)gh < HH && (unsigned)gw < WW)                \
                    v = xb[(size_t)((CI0) + ci) * (HH * WW) + gh * WW + gw];\
                dst[j] = v;                                                \
            }                                                              \
        }                                                                  \
    }

    C3_LOAD(pin, 0);

    for (int ci0 = 0; ci0 < CCH; ci0 += 8) {
#pragma unroll
        for (int j = 0; j < 13; j++) {
            int i = tid + j * 256;
            if (i < 3168) {
                int r   = i / 528;
                int ci  = (i / 66) & 7;
                int col = i % 66;
                sxt[(r * 8 + ci) * 72 + col] = f2tf(pin[j]);
            }
        }
        for (int i = tid; i < 8 * 9 * 16; i += 256) {
            int k   = i / 128;
            int ci  = (i >> 4) & 7;
            int co4 = (i & 15) * 4;
            uint4 v = *reinterpret_cast<const uint4*>(
                &wt2[((size_t)k * 256 + ci0 + ci) * 256 + co0 + co4]);
            *reinterpret_cast<uint4*>(&swt[(ci * 9 + k) * 72 + co4]) = v;
        }
        __syncthreads();

        if (ci0 + 8 < CCH) C3_LOAD(pin2, ci0 + 8);

#pragma unroll
        for (int k = 0; k < 9; k++) {
            const int kh = k / 3, kw = k % 3;
            u32 a[2][4];
#pragma unroll
            for (int rm = 0; rm < 2; rm++) {
                int cof = co_base + rm * 16;
                a[rm][0] = swt[((ctid) * 9 + k) * 72 + cof + gid];
                a[rm][1] = swt[((ctid) * 9 + k) * 72 + cof + gid + 8];
                a[rm][2] = swt[((ctid + 4) * 9 + k) * 72 + cof + gid];
                a[rm][3] = swt[((ctid + 4) * 9 + k) * 72 + cof + gid + 8];
            }
#pragma unroll
            for (int f = 0; f < 8; f++) {
                int px = px_base + f * 8 + gid;
                int rl = px >> 6;            // 0..3
                int wc = (px & 63) + kw;
                u32 bf[2];
                bf[0] = sxt[((rl + kh) * 8 + ctid) * 72 + wc];
                bf[1] = sxt[((rl + kh) * 8 + ctid + 4) * 72 + wc];
                mma_tf32(acc[0][f], a[0], bf);
                mma_tf32(acc[1][f], a[1], bf);
            }
        }
        __syncthreads();

#pragma unroll
        for (int j = 0; j < 13; j++) pin[j] = pin2[j];
    }

#pragma unroll
    for (int rm = 0; rm < 2; rm++) {
#pragma unroll
        for (int f = 0; f < 8; f++) {
            int coA = co0 + co_base + rm * 16 + gid;
            int coB = coA + 8;
            int px  = px_base + f * 8 + 2 * ctid;
            int n   = (h0 + (px >> 6)) * WW + (px & 63);
            float bA = bias[coA], bB = bias[coB];
            float2 sA = {acc[rm][f][0] + bA, acc[rm][f][1] + bA};
            float2 sB = {acc[rm][f][2] + bB, acc[rm][f][3] + bB};
            *reinterpret_cast<float2*>(&out[((size_t)b * CCH + coA) * NN + n]) = sA;
            *reinterpret_cast<float2*>(&out[((size_t)b * CCH + coB) * NN + n]) = sB;
        }
    }
}

// ---------------------------------------------------------------------------
// FUSED K+V 2x2 conv s2 p0, implicit GEMM tf32, prefetched (unchanged R6).
// grid: (HK/4=8, CCH/64=4, B=8)
// ---------------------------------------------------------------------------
__global__ __launch_bounds__(256, 2) void conv2kv_mma(
    const u32* __restrict__ wtK, const u32* __restrict__ wtV,
    const float* __restrict__ y,
    const float* __restrict__ bK, const float* __restrict__ bV,
    float* __restrict__ outK, float* __restrict__ outV)
{
    const int h0  = blockIdx.x * 4;
    const int co0 = blockIdx.y * 64;
    const int b   = blockIdx.z;
    const int tid  = threadIdx.x;
    const int lane = tid & 31;
    const int w    = tid >> 5;
    const int gid  = lane >> 2;
    const int ctid = lane & 3;
    const int co_base = (w >> 2) * 32;
    const int px_base = (w & 3) * 32;

    __shared__ u32 sy[2 * 8 * 8 * 40];
    __shared__ u32 swK[8 * 4 * 74];
    __shared__ u32 swV[8 * 4 * 74];

    float accK[2][4][4], accV[2][4][4];
#pragma unroll
    for (int i = 0; i < 2; i++)
#pragma unroll
        for (int j = 0; j < 4; j++)
#pragma unroll
            for (int l = 0; l < 4; l++) { accK[i][j][l] = 0.f; accV[i][j][l] = 0.f; }

    const float* yb = y + (size_t)b * CCH * (HH * WW);
    const int ih0 = h0 * 2;

    float4 pin[4], pin2[4];

#define C2_LOAD(dst, CI0)                                                   \
    {                                                                       \
        _Pragma("unroll")                                                   \
        for (int j = 0; j < 4; j++) {                                       \
            int i  = tid + j * 256;                                         \
            int r  = i >> 7;                                                \
            int ci = (i >> 4) & 7;                                          \
            int c4 = (i & 15) * 4;                                          \
            dst[j] = *reinterpret_cast<const float4*>(                      \
                &yb[(size_t)((CI0) + ci) * (HH * WW) + (ih0 + r) * WW + c4]);\
        }                                                                   \
    }

    C2_LOAD(pin, 0);

    for (int ci0 = 0; ci0 < CCH; ci0 += 8) {
#pragma unroll
        for (int j = 0; j < 4; j++) {
            int i  = tid + j * 256;
            int r  = i >> 7;
            int ci = (i >> 4) & 7;
            int c4 = (i & 15) * 4;
            float4 v = pin[j];
            u32* even = &sy[((0 * 8 + r) * 8 + ci) * 40 + (c4 >> 1)];
            u32* odd  = &sy[((8 + r) * 8 + ci) * 40 + (c4 >> 1)];
            even[0] = f2tf(v.x); odd[0] = f2tf(v.y);
            even[1] = f2tf(v.z); odd[1] = f2tf(v.w);
        }
        for (int i = tid; i < 8 * 4 * 16; i += 256) {
            int k   = i / 128;
            int ci  = (i >> 4) & 7;
            int co4 = (i & 15) * 4;
            size_t off = ((size_t)k * 256 + ci0 + ci) * 256 + co0 + co4;
            uint4 vk = *reinterpret_cast<const uint4*>(&wtK[off]);
            uint4 vv = *reinterpret_cast<const uint4*>(&wtV[off]);
            u32* dk = &swK[(ci * 4 + k) * 74 + co4];
            dk[0] = vk.x; dk[1] = vk.y; dk[2] = vk.z; dk[3] = vk.w;
            u32* dv = &swV[(ci * 4 + k) * 74 + co4];
            dv[0] = vv.x; dv[1] = vv.y; dv[2] = vv.z; dv[3] = vv.w;
        }
        __syncthreads();

        if (ci0 + 8 < CCH) C2_LOAD(pin2, ci0 + 8);

#pragma unroll
        for (int k = 0; k < 4; k++) {
            const int kh = k >> 1, kw = k & 1;
            u32 aK[2][4], aV[2][4];
#pragma unroll
            for (int rm = 0; rm < 2; rm++) {
                int cof = co_base + rm * 16;
                int r0 = (ctid * 4 + k) * 74 + cof;
                int r1 = ((ctid + 4) * 4 + k) * 74 + cof;
                aK[rm][0] = swK[r0 + gid];     aK[rm][1] = swK[r0 + gid + 8];
                aK[rm][2] = swK[r1 + gid];     aK[rm][3] = swK[r1 + gid + 8];
                aV[rm][0] = swV[r0 + gid];     aV[rm][1] = swV[r0 + gid + 8];
                aV[rm][2] = swV[r1 + gid];     aV[rm][3] = swV[r1 + gid + 8];
            }
#pragma unroll
            for (int f = 0; f < 4; f++) {
                int px = px_base + f * 8 + gid;
                int r  = 2 * (px >> 5) + kh;
                int wl = px & 31;
                u32 bf[2];
                bf[0] = sy[((kw * 8 + r) * 8 + ctid) * 40 + wl];
                bf[1] = sy[((kw * 8 + r) * 8 + ctid + 4) * 40 + wl];
                mma_tf32(accK[0][f], aK[0], bf);
                mma_tf32(accK[1][f], aK[1], bf);
                mma_tf32(accV[0][f], aV[0], bf);
                mma_tf32(accV[1][f], aV[1], bf);
            }
        }
        __syncthreads();

#pragma unroll
        for (int j = 0; j < 4; j++) pin[j] = pin2[j];
    }

#pragma unroll
    for (int rm = 0; rm < 2; rm++) {
#pragma unroll
        for (int f = 0; f < 4; f++) {
            int coA = co0 + co_base + rm * 16 + gid;
            int coB = coA + 8;
            int px  = px_base + f * 8 + 2 * ctid;
            int n   = (h0 + (px >> 5)) * WK + (px & 31);
            size_t oA = ((size_t)b * CCH + coA) * MM + n;
            size_t oB = ((size_t)b * CCH + coB) * MM + n;
            float bkA = bK[coA], bkB = bK[coB];
            float bvA = bV[coA], bvB = bV[coB];
            float2 kA = {accK[rm][f][0] + bkA, accK[rm][f][1] + bkA};
            float2 kB = {accK[rm][f][2] + bkB, accK[rm][f][3] + bkB};
            float2 vA = {accV[rm][f][0] + bvA, accV[rm][f][1] + bvA};
            float2 vB = {accV[rm][f][2] + bvB, accV[rm][f][3] + bvB};
            *reinterpret_cast<float2*>(&outK[oA]) = kA;
            *reinterpret_cast<float2*>(&outK[oB]) = kB;
            *reinterpret_cast<float2*>(&outV[oA]) = vA;
            *reinterpret_cast<float2*>(&outV[oB]) = vB;
        }
    }
}

// ---------------------------------------------------------------------------
// GroupNorm(32 groups of 8 ch) + affine + SiLU, in place. float4, 512 thr.
// ---------------------------------------------------------------------------
__global__ __launch_bounds__(512) void gn_silu_kernel(
    float* __restrict__ buf, const float* __restrict__ scale,
    const float* __restrict__ bias, int S)
{
    const int b = blockIdx.x >> 5;
    const int g = blockIdx.x & 31;
    float* base = buf + ((size_t)b * CCH + g * 8) * S;
    float4* p4 = reinterpret_cast<float4*>(base);
    const int tot4 = (8 * S) >> 2;
    const int tid = threadIdx.x;

    float s = 0.f, ss = 0.f;
    for (int i = tid; i < tot4; i += 512) {
        float4 v = p4[i];
        s += v.x + v.y + v.z + v.w;
        ss = fmaf(v.x, v.x, ss);
        ss = fmaf(v.y, v.y, ss);
        ss = fmaf(v.z, v.z, ss);
        ss = fmaf(v.w, v.w, ss);
    }
    __shared__ float r1[512], r2[512];
    r1[tid] = s; r2[tid] = ss;
    __syncthreads();
    for (int st = 256; st > 0; st >>= 1) {
        if (tid < st) { r1[tid] += r1[tid + st]; r2[tid] += r2[tid + st]; }
        __syncthreads();
    }
    const float tot = (float)(8 * S);
    const float mu   = r1[0] / tot;
    const float var  = r2[0] / tot - mu * mu;
    const float rstd = rsqrtf(var + 1e-5f);

    const int s4 = S >> 2;
    for (int i = tid; i < tot4; i += 512) {
        int c = g * 8 + i / s4;
        float sc = scale[c] * rstd, bi = bias[c] - mu * scale[c] * rstd;
        float4 v = p4[i];
        v.x = fmaf(v.x, sc, bi);
        v.y = fmaf(v.y, sc, bi);
        v.z = fmaf(v.z, sc, bi);
        v.w = fmaf(v.w, sc, bi);
        v.x = v.x / (1.f + __expf(-v.x));
        v.y = v.y / (1.f + __expf(-v.y));
        v.z = v.z / (1.f + __expf(-v.z));
        v.w = v.w / (1.f + __expf(-v.w));
        p4[i] = v;
    }
}

// ---------------------------------------------------------------------------
// E = (1/16) Q^T K  tf32, staged loads double-buffered.
// grid: (MM/128=8, NN/128=32, B=8)
// ---------------------------------------------------------------------------
__global__ __launch_bounds__(256, 2) void gemm_qk_mma(
    const float* __restrict__ Q, const float* __restrict__ K,
    float* __restrict__ E)
{
    const int mb = blockIdx.x * 128;
    const int nb = blockIdx.y * 128;
    const int b  = blockIdx.z;
    const int tid  = threadIdx.x;
    const int lane = tid & 31;
    const int w    = tid >> 5;
    const int gid  = lane >> 2;
    const int ctid = lane & 3;
    const int m_base = (w & 1) * 64;
    const int n_base = (w >> 1) * 32;

    __shared__ u32 sq[16 * 136];
    __shared__ u32 sk[16 * 136];

    float acc[2][8][4];
#pragma unroll
    for (int i = 0; i < 2; i++)
#pragma unroll
        for (int j = 0; j < 8; j++)
#pragma unroll
            for (int l = 0; l < 4; l++) acc[i][j][l] = 0.f;

    const float* Qb = Q + (size_t)b * CCH * NN + nb;
    const float* Kb = K + (size_t)b * CCH * MM + mb;

    const int kc0 = tid >> 5, col0 = (tid & 31) * 4;
    const int kc1 = (tid + 256) >> 5, col1 = ((tid + 256) & 31) * 4;

    float4 pq[2], pk[2], pq2[2], pk2[2];

#define QK_LOAD(dq, dk, C0)                                                         \
    {                                                                               \
        dq[0] = *reinterpret_cast<const float4*>(&Qb[(size_t)((C0) + kc0) * NN + col0]); \
        dq[1] = *reinterpret_cast<const float4*>(&Qb[(size_t)((C0) + kc1) * NN + col1]); \
        dk[0] = *reinterpret_cast<const float4*>(&Kb[(size_t)((C0) + kc0) * MM + col0]); \
        dk[1] = *reinterpret_cast<const float4*>(&Kb[(size_t)((C0) + kc1) * MM + col1]); \
    }

    QK_LOAD(pq, pk, 0);

    for (int c0 = 0; c0 < CCH; c0 += 16) {
        uint4 q0 = {f2tf(pq[0].x), f2tf(pq[0].y), f2tf(pq[0].z), f2tf(pq[0].w)};
        uint4 q1 = {f2tf(pq[1].x), f2tf(pq[1].y), f2tf(pq[1].z), f2tf(pq[1].w)};
        uint4 k0v = {f2tf(pk[0].x), f2tf(pk[0].y), f2tf(pk[0].z), f2tf(pk[0].w)};
        uint4 k1v = {f2tf(pk[1].x), f2tf(pk[1].y), f2tf(pk[1].z), f2tf(pk[1].w)};
        *reinterpret_cast<uint4*>(&sq[kc0 * 136 + col0]) = q0;
        *reinterpret_cast<uint4*>(&sq[kc1 * 136 + col1]) = q1;
        *reinterpret_cast<uint4*>(&sk[kc0 * 136 + col0]) = k0v;
        *reinterpret_cast<uint4*>(&sk[kc1 * 136 + col1]) = k1v;
        __syncthreads();

        if (c0 + 16 < CCH) QK_LOAD(pq2, pk2, c0 + 16);

#pragma unroll
        for (int ks = 0; ks < 2; ks++) {
            const int k0 = ks * 8;
            u32 a[2][4];
#pragma unroll
            for (int rm = 0; rm < 2; rm++) {
                int n0 = n_base + rm * 16;
                a[rm][0] = sq[(k0 + ctid) * 136 + n0 + gid];
                a[rm][1] = sq[(k0 + ctid) * 136 + n0 + gid + 8];
                a[rm][2] = sq[(k0 + ctid + 4) * 136 + n0 + gid];
                a[rm][3] = sq[(k0 + ctid + 4) * 136 + n0 + gid + 8];
            }
#pragma unroll
            for (int f = 0; f < 8; f++) {
                u32 bf[2];
                bf[0] = sk[(k0 + ctid) * 136 + m_base + f * 8 + gid];
                bf[1] = sk[(k0 + ctid + 4) * 136 + m_base + f * 8 + gid];
                mma_tf32(acc[0][f], a[0], bf);
                mma_tf32(acc[1][f], a[1], bf);
            }
        }
        __syncthreads();

        pq[0] = pq2[0]; pq[1] = pq2[1]; pk[0] = pk2[0]; pk[1] = pk2[1];
    }

    const float scale = 0.0625f;
    float* Eb = E + ((size_t)b * NN + nb) * MM + mb;
#pragma unroll
    for (int rm = 0; rm < 2; rm++) {
#pragma unroll
        for (int f = 0; f < 8; f++) {
            int r0 = n_base + rm * 16 + gid;
            int cc = m_base + f * 8 + 2 * ctid;
            float2 s0 = {acc[rm][f][0] * scale, acc[rm][f][1] * scale};
            float2 s1 = {acc[rm][f][2] * scale, acc[rm][f][3] * scale};
            *reinterpret_cast<float2*>(&Eb[(size_t)r0 * MM + cc])       = s0;
            *reinterpret_cast<float2*>(&Eb[(size_t)(r0 + 8) * MM + cc]) = s1;
        }
    }
}

// ---------------------------------------------------------------------------
// In-place softmax over last dim (M=1024). One WARP per row, shuffle
// reductions, no smem. 8 rows per block. grid: B*NN/8 = 4096.
// ---------------------------------------------------------------------------
__global__ __launch_bounds__(256) void softmax_kernel(float* __restrict__ E)
{
    const int warp = threadIdx.x >> 5;
    const int lane = threadIdx.x & 31;
    const size_t row = (size_t)blockIdx.x * 8 + warp;
    float4* p = reinterpret_cast<float4*>(E + row * MM);

    float4 v[8];
    float mx = -1e30f;
#pragma unroll
    for (int i = 0; i < 8; i++) {
        v[i] = p[lane + 32 * i];
        mx = fmaxf(mx, fmaxf(fmaxf(v[i].x, v[i].y), fmaxf(v[i].z, v[i].w)));
    }
#pragma unroll
    for (int o = 16; o > 0; o >>= 1)
        mx = fmaxf(mx, __shfl_xor_sync(0xFFFFFFFFu, mx, o));

    float sum = 0.f;
#pragma unroll
    for (int i = 0; i < 8; i++) {
        v[i].x = __expf(v[i].x - mx);
        v[i].y = __expf(v[i].y - mx);
        v[i].z = __expf(v[i].z - mx);
        v[i].w = __expf(v[i].w - mx);
        sum += v[i].x + v[i].y + v[i].z + v[i].w;
    }
#pragma unroll
    for (int o = 16; o > 0; o >>= 1)
        sum += __shfl_xor_sync(0xFFFFFFFFu, sum, o);

    float inv = 1.f / sum;
#pragma unroll
    for (int i = 0; i < 8; i++) {
        v[i].x *= inv; v[i].y *= inv; v[i].z *= inv; v[i].w *= inv;
        p[lane + 32 * i] = v[i];
    }
}

// ---------------------------------------------------------------------------
// out = gamma * V A^T tf32, staged loads double-buffered.
// grid: (NN/128=32, CCH/128=2, B=8)
// ---------------------------------------------------------------------------
__global__ __launch_bounds__(256, 2) void gemm_av_mma(
    const float* __restrict__ V, const float* __restrict__ A,
    const float* __restrict__ gamma, float* __restrict__ out)
{
    const int nb = blockIdx.x * 128;
    const int cb = blockIdx.y * 128;
    const int b  = blockIdx.z;
    const int tid  = threadIdx.x;
    const int lane = tid & 31;
    const int w    = tid >> 5;
    const int gid  = lane >> 2;
    const int ctid = lane & 3;
    const int n_base = (w & 1) * 64;
    const int c_base = (w >> 1) * 32;

    __shared__ u32 sv[16 * 136];
    __shared__ u32 sa[16 * 136];

    float acc[2][8][4];
#pragma unroll
    for (int i = 0; i < 2; i++)
#pragma unroll
        for (int j = 0; j < 8; j++)
#pragma unroll
            for (int l = 0; l < 4; l++) acc[i][j][l] = 0.f;

    const float* Vb = V + (size_t)b * CCH * MM;
    const float* Ab = A + (size_t)b * NN * MM;

    const int row0 = tid >> 2, f0 = tid & 3;
    const int row1 = (tid + 256) >> 2, f1 = (tid + 256) & 3;

    float4 pv[2], pa[2], pv2[2], pa2[2];

#define AV_LOAD(dv, da, M0)                                                               \
    {                                                                                     \
        dv[0] = *reinterpret_cast<const float4*>(&Vb[(size_t)(cb + row0) * MM + (M0) + f0 * 4]); \
        dv[1] = *reinterpret_cast<const float4*>(&Vb[(size_t)(cb + row1) * MM + (M0) + f1 * 4]); \
        da[0] = *reinterpret_cast<const float4*>(&Ab[(size_t)(nb + row0) * MM + (M0) + f0 * 4]); \
        da[1] = *reinterpret_cast<const float4*>(&Ab[(size_t)(nb + row1) * MM + (M0) + f1 * 4]); \
    }

    AV_LOAD(pv, pa, 0);

    for (int m0 = 0; m0 < MM; m0 += 16) {
        sv[(f0 * 4 + 0) * 136 + row0] = f2tf(pv[0].x);
        sv[(f0 * 4 + 1) * 136 + row0] = f2tf(pv[0].y);
        sv[(f0 * 4 + 2) * 136 + row0] = f2tf(pv[0].z);
        sv[(f0 * 4 + 3) * 136 + row0] = f2tf(pv[0].w);
        sv[(f1 * 4 + 0) * 136 + row1] = f2tf(pv[1].x);
        sv[(f1 * 4 + 1) * 136 + row1] = f2tf(pv[1].y);
        sv[(f1 * 4 + 2) * 136 + row1] = f2tf(pv[1].z);
        sv[(f1 * 4 + 3) * 136 + row1] = f2tf(pv[1].w);
        sa[(f0 * 4 + 0) * 136 + row0] = f2tf(pa[0].x);
        sa[(f0 * 4 + 1) * 136 + row0] = f2tf(pa[0].y);
        sa[(f0 * 4 + 2) * 136 + row0] = f2tf(pa[0].z);
        sa[(f0 * 4 + 3) * 136 + row0] = f2tf(pa[0].w);
        sa[(f1 * 4 + 0) * 136 + row1] = f2tf(pa[1].x);
        sa[(f1 * 4 + 1) * 136 + row1] = f2tf(pa[1].y);
        sa[(f1 * 4 + 2) * 136 + row1] = f2tf(pa[1].z);
        sa[(f1 * 4 + 3) * 136 + row1] = f2tf(pa[1].w);
        __syncthreads();

        if (m0 + 16 < MM) AV_LOAD(pv2, pa2, m0 + 16);

#pragma unroll
        for (int ks = 0; ks < 2; ks++) {
            const int k0 = ks * 8;
            u32 a[2][4];
#pragma unroll
            for (int rm = 0; rm < 2; rm++) {
                int c0 = c_base + rm * 16;
                a[rm][0] = sv[(k0 + ctid) * 136 + c0 + gid];
                a[rm][1] = sv[(k0 + ctid) * 136 + c0 + gid + 8];
                a[rm][2] = sv[(k0 + ctid + 4) * 136 + c0 + gid];
                a[rm][3] = sv[(k0 + ctid + 4) * 136 + c0 + gid + 8];
            }
#pragma unroll
            for (int f = 0; f < 8; f++) {
                u32 bf[2];
                bf[0] = sa[(k0 + ctid) * 136 + n_base + f * 8 + gid];
                bf[1] = sa[(k0 + ctid + 4) * 136 + n_base + f * 8 + gid];
                mma_tf32(acc[0][f], a[0], bf);
                mma_tf32(acc[1][f], a[1], bf);
            }
        }
        __syncthreads();

        pv[0] = pv2[0]; pv[1] = pv2[1]; pa[0] = pa2[0]; pa[1] = pa2[1];
    }

    const float gm = gamma[0];
#pragma unroll
    for (int rm = 0; rm < 2; rm++) {
#pragma unroll
        for (int f = 0; f < 8; f++) {
            int c0 = cb + c_base + rm * 16 + gid;
            int nn2 = nb + n_base + f * 8 + 2 * ctid;
            float2 s0 = {gm * acc[rm][f][0], gm * acc[rm][f][1]};
            float2 s1 = {gm * acc[rm][f][2], gm * acc[rm][f][3]};
            *reinterpret_cast<float2*>(&out[((size_t)b * CCH + c0) * NN + nn2])     = s0;
            *reinterpret_cast<float2*>(&out[((size_t)b * CCH + c0 + 8) * NN + nn2]) = s1;
        }
    }
}

// ---------------------------------------------------------------------------
extern "C" void kernel_launch(void* const* d_in, const int* in_sizes, int n_in,
                              void* d_out, int out_size)
{
    const float* x        = (const float*)d_in[0];
    const float* y        = (const float*)d_in[1];
    const float* Wq       = (const float*)d_in[2];
    const float* bq       = (const float*)d_in[3];
    const float* gq_scale = (const float*)d_in[4];
    const float* gq_bias  = (const float*)d_in[5];
    const float* Wk       = (const float*)d_in[6];
    const float* bk       = (const float*)d_in[7];
    const float* gk_scale = (const float*)d_in[8];
    const float* gk_bias  = (const float*)d_in[9];
    const float* Wv       = (const float*)d_in[10];
    const float* bv       = (const float*)d_in[11];
    const float* gv_scale = (const float*)d_in[12];
    const float* gv_bias  = (const float*)d_in[13];
    const float* gamma    = (const float*)d_in[14];
    float* out = (float*)d_out;

    float *qp = nullptr, *kp = nullptr, *vp = nullptr, *ep = nullptr;
    u32 *wtp = nullptr, *wkp = nullptr, *wvp = nullptr;
    cudaGetSymbolAddress((void**)&qp, g_q);
    cudaGetSymbolAddress((void**)&kp, g_k);
    cudaGetSymbolAddress((void**)&vp, g_v);
    cudaGetSymbolAddress((void**)&ep, g_e);
    cudaGetSymbolAddress((void**)&wtp, g_wt);
    cudaGetSymbolAddress((void**)&wkp, g_wk2);
    cudaGetSymbolAddress((void**)&wvp, g_wv2);

    transpose_w3<<<(9 * 256 * 256 + 255) / 256, 256>>>(Wq, wtp);
    transpose_w2<<<(4 * 256 * 256 + 255) / 256, 256>>>(Wk, Wv, wkp, wvp);

    conv3_mma<<<dim3(HH / 4, CCH / 64, BATCH), 256>>>(wtp, x, bq, qp);
    conv2kv_mma<<<dim3(HK / 4, CCH / 64, BATCH), 256>>>(wkp, wvp, y, bk, bv, kp, vp);

    gn_silu_kernel<<<BATCH * 32, 512>>>(qp, gq_scale, gq_bias, NN);
    gn_silu_kernel<<<BATCH * 32, 512>>>(kp, gk_scale, gk_bias, MM);
    gn_silu_kernel<<<BATCH * 32, 512>>>(vp, gv_scale, gv_bias, MM);

    gemm_qk_mma<<<dim3(MM / 128, NN / 128, BATCH), 256>>>(qp, kp, ep);
    softmax_kernel<<<BATCH * NN / 8, 256>>>(ep);
    gemm_av_mma<<<dim3(NN / 128, CCH / 128, BATCH), 256>>>(vp, ep, gamma, out);
}

// round 9
// speedup vs baseline: 7.2105x; 1.1795x over previous
#include <cuda_runtime.h>
#include <math.h>

#define BATCH 8
#define CCH   256
#define HH    64
#define WW    64
#define NN    4096   // HH*WW
#define MM    1024   // (HH/2)*(WW/2)
#define HK    32
#define WK    32

typedef unsigned long long u64;
typedef unsigned int u32;

__device__ __forceinline__ u32 f2tf(float f) {
    u32 u; asm("cvt.rna.tf32.f32 %0,%1;" : "=r"(u) : "f"(f)); return u;
}
// pack (lo, hi) floats -> bf16x2 word (lo in low half)
__device__ __forceinline__ u32 pkbf(float lo, float hi) {
    u32 d; asm("cvt.rn.bf16x2.f32 %0,%1,%2;" : "=r"(d) : "f"(hi), "f"(lo)); return d;
}
__device__ __forceinline__ void mma_tf32(float* d, const u32* a, const u32* b) {
    asm volatile(
        "mma.sync.aligned.m16n8k8.row.col.f32.tf32.tf32.f32 "
        "{%0,%1,%2,%3},{%4,%5,%6,%7},{%8,%9},{%0,%1,%2,%3};"
        : "+f"(d[0]), "+f"(d[1]), "+f"(d[2]), "+f"(d[3])
        : "r"(a[0]), "r"(a[1]), "r"(a[2]), "r"(a[3]), "r"(b[0]), "r"(b[1]));
}
__device__ __forceinline__ void mma_bf16(float* d, const u32* a, const u32* b) {
    asm volatile(
        "mma.sync.aligned.m16n8k16.row.col.f32.bf16.bf16.f32 "
        "{%0,%1,%2,%3},{%4,%5,%6,%7},{%8,%9},{%0,%1,%2,%3};"
        : "+f"(d[0]), "+f"(d[1]), "+f"(d[2]), "+f"(d[3])
        : "r"(a[0]), "r"(a[1]), "r"(a[2]), "r"(a[3]), "r"(b[0]), "r"(b[1]));
}

// Scratch
__device__ float g_q[(size_t)BATCH * CCH * NN];   // 32 MB
__device__ float g_k[(size_t)BATCH * CCH * MM];   // 8 MB
__device__ float g_v[(size_t)BATCH * CCH * MM];   // 8 MB
__device__ float g_e[(size_t)BATCH * NN * MM];    // 128 MB
__device__ u32   g_wt[9 * 256 * 256];             // Wq transposed, tf32
__device__ u32   g_wk2[4 * 256 * 256];            // Wk transposed, tf32
__device__ u32   g_wv2[4 * 256 * 256];            // Wv transposed, tf32

// ---------------------------------------------------------------------------
__global__ __launch_bounds__(256) void transpose_w3(
    const float* __restrict__ Wt, u32* __restrict__ wt2)
{
    int i = blockIdx.x * 256 + threadIdx.x;
    if (i < 9 * 256 * 256) {
        int co = i & 255;
        int ci = (i >> 8) & 255;
        int k  = i >> 16;
        wt2[i] = f2tf(Wt[((size_t)co * 256 + ci) * 9 + k]);
    }
}

__global__ __launch_bounds__(256) void transpose_w2(
    const float* __restrict__ Wk, const float* __restrict__ Wv,
    u32* __restrict__ wk2, u32* __restrict__ wv2)
{
    int i = blockIdx.x * 256 + threadIdx.x;
    if (i < 4 * 256 * 256) {
        int co = i & 255;
        int ci = (i >> 8) & 255;
        int k  = i >> 16;
        wk2[i] = f2tf(Wk[((size_t)co * 256 + ci) * 4 + k]);
        wv2[i] = f2tf(Wv[((size_t)co * 256 + ci) * 4 + k]);
    }
}

// ---------------------------------------------------------------------------
// 3x3 conv s1 p1, implicit GEMM tf32, 4 output rows per block, prefetched.
// grid: (HH/4=16, CCH/64=4, B=8)
// ---------------------------------------------------------------------------
__global__ __launch_bounds__(256, 2) void conv3_mma(
    const u32* __restrict__ wt2, const float* __restrict__ x,
    const float* __restrict__ bias, float* __restrict__ out)
{
    const int h0  = blockIdx.x * 4;
    const int co0 = blockIdx.y * 64;
    const int b   = blockIdx.z;
    const int tid  = threadIdx.x;
    const int lane = tid & 31;
    const int w    = tid >> 5;
    const int gid  = lane >> 2;
    const int ctid = lane & 3;
    const int co_base = (w >> 2) * 32;
    const int px_base = (w & 3) * 64;

    __shared__ u32 sxt[6 * 8 * 72];   // rows h0-1..h0+4, [r][ci][col pad 72]
    __shared__ u32 swt[8 * 9 * 72];   // [ci][k][co pad 72]

    float acc[2][8][4];
#pragma unroll
    for (int i = 0; i < 2; i++)
#pragma unroll
        for (int j = 0; j < 8; j++)
#pragma unroll
            for (int l = 0; l < 4; l++) acc[i][j][l] = 0.f;

    const float* xb = x + (size_t)b * CCH * (HH * WW);

    float pin[13], pin2[13];

#define C3_LOAD(dst, CI0)                                                  \
    {                                                                      \
        _Pragma("unroll")                                                  \
        for (int j = 0; j < 13; j++) {                                     \
            int i = tid + j * 256;                                         \
            if (i < 3168) {                                                \
                int r   = i / 528;                                         \
                int ci  = (i / 66) & 7;                                    \
                int col = i % 66;                                          \
                int gh = h0 - 1 + r;                                       \
                int gw = col - 1;                                          \
                float v = 0.f;                                             \
                if ((unsigned)gh < HH && (unsigned)gw < WW)                \
                    v = xb[(size_t)((CI0) + ci) * (HH * WW) + gh * WW + gw];\
                dst[j] = v;                                                \
            }                                                              \
        }                                                                  \
    }

    C3_LOAD(pin, 0);

    for (int ci0 = 0; ci0 < CCH; ci0 += 8) {
#pragma unroll
        for (int j = 0; j < 13; j++) {
            int i = tid + j * 256;
            if (i < 3168) {
                int r   = i / 528;
                int ci  = (i / 66) & 7;
                int col = i % 66;
                sxt[(r * 8 + ci) * 72 + col] = f2tf(pin[j]);
            }
        }
        for (int i = tid; i < 8 * 9 * 16; i += 256) {
            int k   = i / 128;
            int ci  = (i >> 4) & 7;
            int co4 = (i & 15) * 4;
            uint4 v = *reinterpret_cast<const uint4*>(
                &wt2[((size_t)k * 256 + ci0 + ci) * 256 + co0 + co4]);
            *reinterpret_cast<uint4*>(&swt[(ci * 9 + k) * 72 + co4]) = v;
        }
        __syncthreads();

        if (ci0 + 8 < CCH) C3_LOAD(pin2, ci0 + 8);

#pragma unroll
        for (int k = 0; k < 9; k++) {
            const int kh = k / 3, kw = k % 3;
            u32 a[2][4];
#pragma unroll
            for (int rm = 0; rm < 2; rm++) {
                int cof = co_base + rm * 16;
                a[rm][0] = swt[((ctid) * 9 + k) * 72 + cof + gid];
                a[rm][1] = swt[((ctid) * 9 + k) * 72 + cof + gid + 8];
                a[rm][2] = swt[((ctid + 4) * 9 + k) * 72 + cof + gid];
                a[rm][3] = swt[((ctid + 4) * 9 + k) * 72 + cof + gid + 8];
            }
#pragma unroll
            for (int f = 0; f < 8; f++) {
                int px = px_base + f * 8 + gid;
                int rl = px >> 6;            // 0..3
                int wc = (px & 63) + kw;
                u32 bf[2];
                bf[0] = sxt[((rl + kh) * 8 + ctid) * 72 + wc];
                bf[1] = sxt[((rl + kh) * 8 + ctid + 4) * 72 + wc];
                mma_tf32(acc[0][f], a[0], bf);
                mma_tf32(acc[1][f], a[1], bf);
            }
        }
        __syncthreads();

#pragma unroll
        for (int j = 0; j < 13; j++) pin[j] = pin2[j];
    }

#pragma unroll
    for (int rm = 0; rm < 2; rm++) {
#pragma unroll
        for (int f = 0; f < 8; f++) {
            int coA = co0 + co_base + rm * 16 + gid;
            int coB = coA + 8;
            int px  = px_base + f * 8 + 2 * ctid;
            int n   = (h0 + (px >> 6)) * WW + (px & 63);
            float bA = bias[coA], bB = bias[coB];
            float2 sA = {acc[rm][f][0] + bA, acc[rm][f][1] + bA};
            float2 sB = {acc[rm][f][2] + bB, acc[rm][f][3] + bB};
            *reinterpret_cast<float2*>(&out[((size_t)b * CCH + coA) * NN + n]) = sA;
            *reinterpret_cast<float2*>(&out[((size_t)b * CCH + coB) * NN + n]) = sB;
        }
    }
}

// ---------------------------------------------------------------------------
// FUSED K+V 2x2 conv s2 p0, implicit GEMM tf32, prefetched.
// grid: (HK/4=8, CCH/64=4, B=8)
// ---------------------------------------------------------------------------
__global__ __launch_bounds__(256, 2) void conv2kv_mma(
    const u32* __restrict__ wtK, const u32* __restrict__ wtV,
    const float* __restrict__ y,
    const float* __restrict__ bK, const float* __restrict__ bV,
    float* __restrict__ outK, float* __restrict__ outV)
{
    const int h0  = blockIdx.x * 4;
    const int co0 = blockIdx.y * 64;
    const int b   = blockIdx.z;
    const int tid  = threadIdx.x;
    const int lane = tid & 31;
    const int w    = tid >> 5;
    const int gid  = lane >> 2;
    const int ctid = lane & 3;
    const int co_base = (w >> 2) * 32;
    const int px_base = (w & 3) * 32;

    __shared__ u32 sy[2 * 8 * 8 * 40];
    __shared__ u32 swK[8 * 4 * 74];
    __shared__ u32 swV[8 * 4 * 74];

    float accK[2][4][4], accV[2][4][4];
#pragma unroll
    for (int i = 0; i < 2; i++)
#pragma unroll
        for (int j = 0; j < 4; j++)
#pragma unroll
            for (int l = 0; l < 4; l++) { accK[i][j][l] = 0.f; accV[i][j][l] = 0.f; }

    const float* yb = y + (size_t)b * CCH * (HH * WW);
    const int ih0 = h0 * 2;

    float4 pin[4], pin2[4];

#define C2_LOAD(dst, CI0)                                                   \
    {                                                                       \
        _Pragma("unroll")                                                   \
        for (int j = 0; j < 4; j++) {                                       \
            int i  = tid + j * 256;                                         \
            int r  = i >> 7;                                                \
            int ci = (i >> 4) & 7;                                          \
            int c4 = (i & 15) * 4;                                          \
            dst[j] = *reinterpret_cast<const float4*>(                      \
                &yb[(size_t)((CI0) + ci) * (HH * WW) + (ih0 + r) * WW + c4]);\
        }                                                                   \
    }

    C2_LOAD(pin, 0);

    for (int ci0 = 0; ci0 < CCH; ci0 += 8) {
#pragma unroll
        for (int j = 0; j < 4; j++) {
            int i  = tid + j * 256;
            int r  = i >> 7;
            int ci = (i >> 4) & 7;
            int c4 = (i & 15) * 4;
            float4 v = pin[j];
            u32* even = &sy[((0 * 8 + r) * 8 + ci) * 40 + (c4 >> 1)];
            u32* odd  = &sy[((8 + r) * 8 + ci) * 40 + (c4 >> 1)];
            even[0] = f2tf(v.x); odd[0] = f2tf(v.y);
            even[1] = f2tf(v.z); odd[1] = f2tf(v.w);
        }
        for (int i = tid; i < 8 * 4 * 16; i += 256) {
            int k   = i / 128;
            int ci  = (i >> 4) & 7;
            int co4 = (i & 15) * 4;
            size_t off = ((size_t)k * 256 + ci0 + ci) * 256 + co0 + co4;
            uint4 vk = *reinterpret_cast<const uint4*>(&wtK[off]);
            uint4 vv = *reinterpret_cast<const uint4*>(&wtV[off]);
            u32* dk = &swK[(ci * 4 + k) * 74 + co4];
            dk[0] = vk.x; dk[1] = vk.y; dk[2] = vk.z; dk[3] = vk.w;
            u32* dv = &swV[(ci * 4 + k) * 74 + co4];
            dv[0] = vv.x; dv[1] = vv.y; dv[2] = vv.z; dv[3] = vv.w;
        }
        __syncthreads();

        if (ci0 + 8 < CCH) C2_LOAD(pin2, ci0 + 8);

#pragma unroll
        for (int k = 0; k < 4; k++) {
            const int kh = k >> 1, kw = k & 1;
            u32 aK[2][4], aV[2][4];
#pragma unroll
            for (int rm = 0; rm < 2; rm++) {
                int cof = co_base + rm * 16;
                int r0 = (ctid * 4 + k) * 74 + cof;
                int r1 = ((ctid + 4) * 4 + k) * 74 + cof;
                aK[rm][0] = swK[r0 + gid];     aK[rm][1] = swK[r0 + gid + 8];
                aK[rm][2] = swK[r1 + gid];     aK[rm][3] = swK[r1 + gid + 8];
                aV[rm][0] = swV[r0 + gid];     aV[rm][1] = swV[r0 + gid + 8];
                aV[rm][2] = swV[r1 + gid];     aV[rm][3] = swV[r1 + gid + 8];
            }
#pragma unroll
            for (int f = 0; f < 4; f++) {
                int px = px_base + f * 8 + gid;
                int r  = 2 * (px >> 5) + kh;
                int wl = px & 31;
                u32 bf[2];
                bf[0] = sy[((kw * 8 + r) * 8 + ctid) * 40 + wl];
                bf[1] = sy[((kw * 8 + r) * 8 + ctid + 4) * 40 + wl];
                mma_tf32(accK[0][f], aK[0], bf);
                mma_tf32(accK[1][f], aK[1], bf);
                mma_tf32(accV[0][f], aV[0], bf);
                mma_tf32(accV[1][f], aV[1], bf);
            }
        }
        __syncthreads();

#pragma unroll
        for (int j = 0; j < 4; j++) pin[j] = pin2[j];
    }

#pragma unroll
    for (int rm = 0; rm < 2; rm++) {
#pragma unroll
        for (int f = 0; f < 4; f++) {
            int coA = co0 + co_base + rm * 16 + gid;
            int coB = coA + 8;
            int px  = px_base + f * 8 + 2 * ctid;
            int n   = (h0 + (px >> 5)) * WK + (px & 31);
            size_t oA = ((size_t)b * CCH + coA) * MM + n;
            size_t oB = ((size_t)b * CCH + coB) * MM + n;
            float bkA = bK[coA], bkB = bK[coB];
            float bvA = bV[coA], bvB = bV[coB];
            float2 kA = {accK[rm][f][0] + bkA, accK[rm][f][1] + bkA};
            float2 kB = {accK[rm][f][2] + bkB, accK[rm][f][3] + bkB};
            float2 vA = {accV[rm][f][0] + bvA, accV[rm][f][1] + bvA};
            float2 vB = {accV[rm][f][2] + bvB, accV[rm][f][3] + bvB};
            *reinterpret_cast<float2*>(&outK[oA]) = kA;
            *reinterpret_cast<float2*>(&outK[oB]) = kB;
            *reinterpret_cast<float2*>(&outV[oA]) = vA;
            *reinterpret_cast<float2*>(&outV[oB]) = vB;
        }
    }
}

// ---------------------------------------------------------------------------
// GroupNorm(32 groups of 8 ch) + affine + SiLU, in place. float4, 512 thr.
// ---------------------------------------------------------------------------
__global__ __launch_bounds__(512) void gn_silu_kernel(
    float* __restrict__ buf, const float* __restrict__ scale,
    const float* __restrict__ bias, int S)
{
    const int b = blockIdx.x >> 5;
    const int g = blockIdx.x & 31;
    float* base = buf + ((size_t)b * CCH + g * 8) * S;
    float4* p4 = reinterpret_cast<float4*>(base);
    const int tot4 = (8 * S) >> 2;
    const int tid = threadIdx.x;

    float s = 0.f, ss = 0.f;
    for (int i = tid; i < tot4; i += 512) {
        float4 v = p4[i];
        s += v.x + v.y + v.z + v.w;
        ss = fmaf(v.x, v.x, ss);
        ss = fmaf(v.y, v.y, ss);
        ss = fmaf(v.z, v.z, ss);
        ss = fmaf(v.w, v.w, ss);
    }
    __shared__ float r1[512], r2[512];
    r1[tid] = s; r2[tid] = ss;
    __syncthreads();
    for (int st = 256; st > 0; st >>= 1) {
        if (tid < st) { r1[tid] += r1[tid + st]; r2[tid] += r2[tid + st]; }
        __syncthreads();
    }
    const float tot = (float)(8 * S);
    const float mu   = r1[0] / tot;
    const float var  = r2[0] / tot - mu * mu;
    const float rstd = rsqrtf(var + 1e-5f);

    const int s4 = S >> 2;
    for (int i = tid; i < tot4; i += 512) {
        int c = g * 8 + i / s4;
        float sc = scale[c] * rstd, bi = bias[c] - mu * scale[c] * rstd;
        float4 v = p4[i];
        v.x = fmaf(v.x, sc, bi);
        v.y = fmaf(v.y, sc, bi);
        v.z = fmaf(v.z, sc, bi);
        v.w = fmaf(v.w, sc, bi);
        v.x = v.x / (1.f + __expf(-v.x));
        v.y = v.y / (1.f + __expf(-v.y));
        v.z = v.z / (1.f + __expf(-v.z));
        v.w = v.w / (1.f + __expf(-v.w));
        p4[i] = v;
    }
}

// ---------------------------------------------------------------------------
// E = (1/16) Q^T K  (bf16 m16n8k16), staged loads double-buffered.
// k-pairs (c, c+1) packed into bf16x2 words: sq2[c2][n], sk2[c2][m].
// grid: (MM/128=8, NN/128=32, B=8)
// ---------------------------------------------------------------------------
__global__ __launch_bounds__(256, 2) void gemm_qk_mma(
    const float* __restrict__ Q, const float* __restrict__ K,
    float* __restrict__ E)
{
    const int mb = blockIdx.x * 128;
    const int nb = blockIdx.y * 128;
    const int b  = blockIdx.z;
    const int tid  = threadIdx.x;
    const int lane = tid & 31;
    const int w    = tid >> 5;
    const int gid  = lane >> 2;
    const int ctid = lane & 3;
    const int m_base = (w & 1) * 64;
    const int n_base = (w >> 1) * 32;

    __shared__ u32 sq2[8 * 136];   // [c2][n pad 136]
    __shared__ u32 sk2[8 * 136];   // [c2][m pad 136]

    float acc[2][8][4];
#pragma unroll
    for (int i = 0; i < 2; i++)
#pragma unroll
        for (int j = 0; j < 8; j++)
#pragma unroll
            for (int l = 0; l < 4; l++) acc[i][j][l] = 0.f;

    const float* Qb = Q + (size_t)b * CCH * NN + nb;
    const float* Kb = K + (size_t)b * CCH * MM + mb;

    const int kc  = tid >> 5;          // c2-row 0..7 (warp id)
    const int col = (lane) * 4;        // 0..124

    float4 pq0, pq1, pk0, pk1, nq0, nq1, nk0, nk1;

#define QK_LOAD(q0, q1, k0, k1, C0)                                                        \
    {                                                                                      \
        q0 = *reinterpret_cast<const float4*>(&Qb[(size_t)((C0) + 2 * kc) * NN + col]);     \
        q1 = *reinterpret_cast<const float4*>(&Qb[(size_t)((C0) + 2 * kc + 1) * NN + col]); \
        k0 = *reinterpret_cast<const float4*>(&Kb[(size_t)((C0) + 2 * kc) * MM + col]);     \
        k1 = *reinterpret_cast<const float4*>(&Kb[(size_t)((C0) + 2 * kc + 1) * MM + col]); \
    }

    QK_LOAD(pq0, pq1, pk0, pk1, 0);

    for (int c0 = 0; c0 < CCH; c0 += 16) {
        uint4 qs = {pkbf(pq0.x, pq1.x), pkbf(pq0.y, pq1.y),
                    pkbf(pq0.z, pq1.z), pkbf(pq0.w, pq1.w)};
        uint4 ks = {pkbf(pk0.x, pk1.x), pkbf(pk0.y, pk1.y),
                    pkbf(pk0.z, pk1.z), pkbf(pk0.w, pk1.w)};
        *reinterpret_cast<uint4*>(&sq2[kc * 136 + col]) = qs;
        *reinterpret_cast<uint4*>(&sk2[kc * 136 + col]) = ks;
        __syncthreads();

        if (c0 + 16 < CCH) QK_LOAD(nq0, nq1, nk0, nk1, c0 + 16);

        u32 a[2][4];
#pragma unroll
        for (int rm = 0; rm < 2; rm++) {
            int n0 = n_base + rm * 16;
            a[rm][0] = sq2[ctid * 136 + n0 + gid];
            a[rm][1] = sq2[ctid * 136 + n0 + gid + 8];
            a[rm][2] = sq2[(ctid + 4) * 136 + n0 + gid];
            a[rm][3] = sq2[(ctid + 4) * 136 + n0 + gid + 8];
        }
#pragma unroll
        for (int f = 0; f < 8; f++) {
            u32 bf[2];
            bf[0] = sk2[ctid * 136 + m_base + f * 8 + gid];
            bf[1] = sk2[(ctid + 4) * 136 + m_base + f * 8 + gid];
            mma_bf16(acc[0][f], a[0], bf);
            mma_bf16(acc[1][f], a[1], bf);
        }
        __syncthreads();

        pq0 = nq0; pq1 = nq1; pk0 = nk0; pk1 = nk1;
    }

    const float scale = 0.0625f;
    float* Eb = E + ((size_t)b * NN + nb) * MM + mb;
#pragma unroll
    for (int rm = 0; rm < 2; rm++) {
#pragma unroll
        for (int f = 0; f < 8; f++) {
            int r0 = n_base + rm * 16 + gid;
            int cc = m_base + f * 8 + 2 * ctid;
            float2 s0 = {acc[rm][f][0] * scale, acc[rm][f][1] * scale};
            float2 s1 = {acc[rm][f][2] * scale, acc[rm][f][3] * scale};
            *reinterpret_cast<float2*>(&Eb[(size_t)r0 * MM + cc])       = s0;
            *reinterpret_cast<float2*>(&Eb[(size_t)(r0 + 8) * MM + cc]) = s1;
        }
    }
}

// ---------------------------------------------------------------------------
// In-place softmax over last dim (M=1024). One WARP per row, shuffle
// reductions, no smem. 8 rows per block. grid: B*NN/8 = 4096.
// ---------------------------------------------------------------------------
__global__ __launch_bounds__(256) void softmax_kernel(float* __restrict__ E)
{
    const int warp = threadIdx.x >> 5;
    const int lane = threadIdx.x & 31;
    const size_t row = (size_t)blockIdx.x * 8 + warp;
    float4* p = reinterpret_cast<float4*>(E + row * MM);

    float4 v[8];
    float mx = -1e30f;
#pragma unroll
    for (int i = 0; i < 8; i++) {
        v[i] = p[lane + 32 * i];
        mx = fmaxf(mx, fmaxf(fmaxf(v[i].x, v[i].y), fmaxf(v[i].z, v[i].w)));
    }
#pragma unroll
    for (int o = 16; o > 0; o >>= 1)
        mx = fmaxf(mx, __shfl_xor_sync(0xFFFFFFFFu, mx, o));

    float sum = 0.f;
#pragma unroll
    for (int i = 0; i < 8; i++) {
        v[i].x = __expf(v[i].x - mx);
        v[i].y = __expf(v[i].y - mx);
        v[i].z = __expf(v[i].z - mx);
        v[i].w = __expf(v[i].w - mx);
        sum += v[i].x + v[i].y + v[i].z + v[i].w;
    }
#pragma unroll
    for (int o = 16; o > 0; o >>= 1)
        sum += __shfl_xor_sync(0xFFFFFFFFu, sum, o);

    float inv = 1.f / sum;
#pragma unroll
    for (int i = 0; i < 8; i++) {
        v[i].x *= inv; v[i].y *= inv; v[i].z *= inv; v[i].w *= inv;
        p[lane + 32 * i] = v[i];
    }
}

// ---------------------------------------------------------------------------
// out = gamma * V A^T (bf16 m16n8k16), staged loads double-buffered.
// m-pairs packed into bf16x2: sv2[m2][c], sa2[m2][n].
// grid: (NN/128=32, CCH/128=2, B=8)
// ---------------------------------------------------------------------------
__global__ __launch_bounds__(256, 2) void gemm_av_mma(
    const float* __restrict__ V, const float* __restrict__ A,
    const float* __restrict__ gamma, float* __restrict__ out)
{
    const int nb = blockIdx.x * 128;
    const int cb = blockIdx.y * 128;
    const int b  = blockIdx.z;
    const int tid  = threadIdx.x;
    const int lane = tid & 31;
    const int w    = tid >> 5;
    const int gid  = lane >> 2;
    const int ctid = lane & 3;
    const int n_base = (w & 1) * 64;
    const int c_base = (w >> 1) * 32;

    __shared__ u32 sv2[8 * 136];   // [m2][c pad 136]
    __shared__ u32 sa2[8 * 136];   // [m2][n pad 136]

    float acc[2][8][4];
#pragma unroll
    for (int i = 0; i < 2; i++)
#pragma unroll
        for (int j = 0; j < 8; j++)
#pragma unroll
            for (int l = 0; l < 4; l++) acc[i][j][l] = 0.f;

    const float* Vb = V + (size_t)b * CCH * MM;
    const float* Ab = A + (size_t)b * NN * MM;

    const int row0 = tid >> 2, f0 = tid & 3;
    const int row1 = row0 + 64;

    float4 pv0, pv1, pa0, pa1, nv0, nv1, na0, na1;

#define AV_LOAD(v0, v1, a0v, a1v, M0)                                                         \
    {                                                                                         \
        v0  = *reinterpret_cast<const float4*>(&Vb[(size_t)(cb + row0) * MM + (M0) + f0 * 4]); \
        v1  = *reinterpret_cast<const float4*>(&Vb[(size_t)(cb + row1) * MM + (M0) + f0 * 4]); \
        a0v = *reinterpret_cast<const float4*>(&Ab[(size_t)(nb + row0) * MM + (M0) + f0 * 4]); \
        a1v = *reinterpret_cast<const float4*>(&Ab[(size_t)(nb + row1) * MM + (M0) + f0 * 4]); \
    }

    AV_LOAD(pv0, pv1, pa0, pa1, 0);

    for (int m0 = 0; m0 < MM; m0 += 16) {
        sv2[(f0 * 2) * 136 + row0]     = pkbf(pv0.x, pv0.y);
        sv2[(f0 * 2 + 1) * 136 + row0] = pkbf(pv0.z, pv0.w);
        sv2[(f0 * 2) * 136 + row1]     = pkbf(pv1.x, pv1.y);
        sv2[(f0 * 2 + 1) * 136 + row1] = pkbf(pv1.z, pv1.w);
        sa2[(f0 * 2) * 136 + row0]     = pkbf(pa0.x, pa0.y);
        sa2[(f0 * 2 + 1) * 136 + row0] = pkbf(pa0.z, pa0.w);
        sa2[(f0 * 2) * 136 + row1]     = pkbf(pa1.x, pa1.y);
        sa2[(f0 * 2 + 1) * 136 + row1] = pkbf(pa1.z, pa1.w);
        __syncthreads();

        if (m0 + 16 < MM) AV_LOAD(nv0, nv1, na0, na1, m0 + 16);

        u32 a[2][4];
#pragma unroll
        for (int rm = 0; rm < 2; rm++) {
            int c0 = c_base + rm * 16;
            a[rm][0] = sv2[ctid * 136 + c0 + gid];
            a[rm][1] = sv2[ctid * 136 + c0 + gid + 8];
            a[rm][2] = sv2[(ctid + 4) * 136 + c0 + gid];
            a[rm][3] = sv2[(ctid + 4) * 136 + c0 + gid + 8];
        }
#pragma unroll
        for (int f = 0; f < 8; f++) {
            u32 bf[2];
            bf[0] = sa2[ctid * 136 + n_base + f * 8 + gid];
            bf[1] = sa2[(ctid + 4) * 136 + n_base + f * 8 + gid];
            mma_bf16(acc[0][f], a[0], bf);
            mma_bf16(acc[1][f], a[1], bf);
        }
        __syncthreads();

        pv0 = nv0; pv1 = nv1; pa0 = na0; pa1 = na1;
    }

    const float gm = gamma[0];
#pragma unroll
    for (int rm = 0; rm < 2; rm++) {
#pragma unroll
        for (int f = 0; f < 8; f++) {
            int c0 = cb + c_base + rm * 16 + gid;
            int nn2 = nb + n_base + f * 8 + 2 * ctid;
            float2 s0 = {gm * acc[rm][f][0], gm * acc[rm][f][1]};
            float2 s1 = {gm * acc[rm][f][2], gm * acc[rm][f][3]};
            *reinterpret_cast<float2*>(&out[((size_t)b * CCH + c0) * NN + nn2])     = s0;
            *reinterpret_cast<float2*>(&out[((size_t)b * CCH + c0 + 8) * NN + nn2]) = s1;
        }
    }
}

// ---------------------------------------------------------------------------
extern "C" void kernel_launch(void* const* d_in, const int* in_sizes, int n_in,
                              void* d_out, int out_size)
{
    const float* x        = (const float*)d_in[0];
    const float* y        = (const float*)d_in[1];
    const float* Wq       = (const float*)d_in[2];
    const float* bq       = (const float*)d_in[3];
    const float* gq_scale = (const float*)d_in[4];
    const float* gq_bias  = (const float*)d_in[5];
    const float* Wk       = (const float*)d_in[6];
    const float* bk       = (const float*)d_in[7];
    const float* gk_scale = (const float*)d_in[8];
    const float* gk_bias  = (const float*)d_in[9];
    const float* Wv       = (const float*)d_in[10];
    const float* bv       = (const float*)d_in[11];
    const float* gv_scale = (const float*)d_in[12];
    const float* gv_bias  = (const float*)d_in[13];
    const float* gamma    = (const float*)d_in[14];
    float* out = (float*)d_out;

    float *qp = nullptr, *kp = nullptr, *vp = nullptr, *ep = nullptr;
    u32 *wtp = nullptr, *wkp = nullptr, *wvp = nullptr;
    cudaGetSymbolAddress((void**)&qp, g_q);
    cudaGetSymbolAddress((void**)&kp, g_k);
    cudaGetSymbolAddress((void**)&vp, g_v);
    cudaGetSymbolAddress((void**)&ep, g_e);
    cudaGetSymbolAddress((void**)&wtp, g_wt);
    cudaGetSymbolAddress((void**)&wkp, g_wk2);
    cudaGetSymbolAddress((void**)&wvp, g_wv2);

    transpose_w3<<<(9 * 256 * 256 + 255) / 256, 256>>>(Wq, wtp);
    transpose_w2<<<(4 * 256 * 256 + 255) / 256, 256>>>(Wk, Wv, wkp, wvp);

    conv3_mma<<<dim3(HH / 4, CCH / 64, BATCH), 256>>>(wtp, x, bq, qp);
    conv2kv_mma<<<dim3(HK / 4, CCH / 64, BATCH), 256>>>(wkp, wvp, y, bk, bv, kp, vp);

    gn_silu_kernel<<<BATCH * 32, 512>>>(qp, gq_scale, gq_bias, NN);
    gn_silu_kernel<<<BATCH * 32, 512>>>(kp, gk_scale, gk_bias, MM);
    gn_silu_kernel<<<BATCH * 32, 512>>>(vp, gv_scale, gv_bias, MM);

    gemm_qk_mma<<<dim3(MM / 128, NN / 128, BATCH), 256>>>(qp, kp, ep);
    softmax_kernel<<<BATCH * NN / 8, 256>>>(ep);
    gemm_av_mma<<<dim3(NN / 128, CCH / 128, BATCH), 256>>>(vp, ep, gamma, out);
}

// round 10
// speedup vs baseline: 8.8858x; 1.2323x over previous
#include <cuda_runtime.h>
#include <math.h>

#define BATCH 8
#define CCH   256
#define HH    64
#define WW    64
#define NN    4096   // HH*WW
#define MM    1024   // (HH/2)*(WW/2)
#define HK    32
#define WK    32

typedef unsigned long long u64;
typedef unsigned int u32;

__device__ __forceinline__ u32 f2tf(float f) {
    u32 u; asm("cvt.rna.tf32.f32 %0,%1;" : "=r"(u) : "f"(f)); return u;
}
// pack (lo, hi) floats -> bf16x2 word (lo in low half)
__device__ __forceinline__ u32 pkbf(float lo, float hi) {
    u32 d; asm("cvt.rn.bf16x2.f32 %0,%1,%2;" : "=r"(d) : "f"(hi), "f"(lo)); return d;
}
__device__ __forceinline__ void mma_tf32(float* d, const u32* a, const u32* b) {
    asm volatile(
        "mma.sync.aligned.m16n8k8.row.col.f32.tf32.tf32.f32 "
        "{%0,%1,%2,%3},{%4,%5,%6,%7},{%8,%9},{%0,%1,%2,%3};"
        : "+f"(d[0]), "+f"(d[1]), "+f"(d[2]), "+f"(d[3])
        : "r"(a[0]), "r"(a[1]), "r"(a[2]), "r"(a[3]), "r"(b[0]), "r"(b[1]));
}
__device__ __forceinline__ void mma_bf16(float* d, const u32* a, const u32* b) {
    asm volatile(
        "mma.sync.aligned.m16n8k16.row.col.f32.bf16.bf16.f32 "
        "{%0,%1,%2,%3},{%4,%5,%6,%7},{%8,%9},{%0,%1,%2,%3};"
        : "+f"(d[0]), "+f"(d[1]), "+f"(d[2]), "+f"(d[3])
        : "r"(a[0]), "r"(a[1]), "r"(a[2]), "r"(a[3]), "r"(b[0]), "r"(b[1]));
}

// Scratch
__device__ float g_q[(size_t)BATCH * CCH * NN];   // 32 MB
__device__ float g_k[(size_t)BATCH * CCH * MM];   // 8 MB
__device__ float g_v[(size_t)BATCH * CCH * MM];   // 8 MB
__device__ float g_e[(size_t)BATCH * NN * MM];    // 128 MB
__device__ u32   g_wt3[9 * 128 * 256];            // Wq [k][ci2][co] bf16x2
__device__ u32   g_wk2[4 * 256 * 256];            // Wk transposed, tf32
__device__ u32   g_wv2[4 * 256 * 256];            // Wv transposed, tf32

// ---------------------------------------------------------------------------
// Wq OIHW -> [k][ci2][co] packed bf16x2 (ci pair in one word).
// ---------------------------------------------------------------------------
__global__ __launch_bounds__(256) void transpose_w3(
    const float* __restrict__ Wt, u32* __restrict__ wt3)
{
    int i = blockIdx.x * 256 + threadIdx.x;
    if (i < 9 * 128 * 256) {
        int co  = i & 255;
        int ci2 = (i >> 8) & 127;
        int k   = i >> 15;
        float lo = Wt[((size_t)co * 256 + 2 * ci2) * 9 + k];
        float hi = Wt[((size_t)co * 256 + 2 * ci2 + 1) * 9 + k];
        wt3[i] = pkbf(lo, hi);
    }
}

__global__ __launch_bounds__(256) void transpose_w2(
    const float* __restrict__ Wk, const float* __restrict__ Wv,
    u32* __restrict__ wk2, u32* __restrict__ wv2)
{
    int i = blockIdx.x * 256 + threadIdx.x;
    if (i < 4 * 256 * 256) {
        int co = i & 255;
        int ci = (i >> 8) & 255;
        int k  = i >> 16;
        wk2[i] = f2tf(Wk[((size_t)co * 256 + ci) * 4 + k]);
        wv2[i] = f2tf(Wv[((size_t)co * 256 + ci) * 4 + k]);
    }
}

// ---------------------------------------------------------------------------
// 3x3 conv s1 p1, implicit GEMM bf16 (m16n8k16), ci-chunk 16, prefetched.
// Block: 64 co x 128 px (2 rows). 8 warps (2co x 4px), warp 32co x 32px.
// grid: (HH/2=32, CCH/64=4, B=8)
// ---------------------------------------------------------------------------
__global__ __launch_bounds__(256, 2) void conv3_mma(
    const u32* __restrict__ wt3, const float* __restrict__ x,
    const float* __restrict__ bias, float* __restrict__ out)
{
    const int h0  = blockIdx.x * 2;
    const int co0 = blockIdx.y * 64;
    const int b   = blockIdx.z;
    const int tid  = threadIdx.x;
    const int lane = tid & 31;
    const int w    = tid >> 5;
    const int gid  = lane >> 2;
    const int ctid = lane & 3;
    const int co_base = (w >> 2) * 32;
    const int px_base = (w & 3) * 32;

    __shared__ u32 sxt[4 * 8 * 72];   // [r 0..3][c2 0..7][col pad 72] bf16x2
    __shared__ u32 swt[8 * 9 * 72];   // [c2][k][co pad 72] bf16x2

    float acc[2][4][4];
#pragma unroll
    for (int i = 0; i < 2; i++)
#pragma unroll
        for (int j = 0; j < 4; j++)
#pragma unroll
            for (int l = 0; l < 4; l++) acc[i][j][l] = 0.f;

    const float* xb = x + (size_t)b * CCH * (HH * WW);

    // 4 rows x 8 c2 x 66 cols = 2112 packed words; 9 iters x 2 scalar loads
    float plo[9], phi[9], plo2[9], phi2[9];

#define C3_LOAD(dlo, dhi, CI0)                                              \
    {                                                                       \
        _Pragma("unroll")                                                   \
        for (int j = 0; j < 9; j++) {                                       \
            int i = tid + j * 256;                                          \
            if (i < 2112) {                                                 \
                int r   = i / 528;                                          \
                int c2  = (i / 66) & 7;                                     \
                int col = i % 66;                                           \
                int gh = h0 - 1 + r;                                        \
                int gw = col - 1;                                           \
                float vlo = 0.f, vhi = 0.f;                                 \
                if ((unsigned)gh < HH && (unsigned)gw < WW) {               \
                    size_t base = (size_t)((CI0) + 2 * c2) * (HH * WW)      \
                                  + gh * WW + gw;                           \
                    vlo = xb[base];                                         \
                    vhi = xb[base + HH * WW];                               \
                }                                                           \
                dlo[j] = vlo; dhi[j] = vhi;                                 \
            }                                                               \
        }                                                                   \
    }

    C3_LOAD(plo, phi, 0);

    for (int ci0 = 0; ci0 < CCH; ci0 += 16) {
#pragma unroll
        for (int j = 0; j < 9; j++) {
            int i = tid + j * 256;
            if (i < 2112) {
                int r   = i / 528;
                int c2  = (i / 66) & 7;
                int col = i % 66;
                sxt[(r * 8 + c2) * 72 + col] = pkbf(plo[j], phi[j]);
            }
        }
        // weights: straight copy from packed [k][ci2][co]
        for (int i = tid; i < 8 * 9 * 16; i += 256) {
            int k   = i / 128;
            int c2  = (i >> 4) & 7;
            int co4 = (i & 15) * 4;
            uint4 v = *reinterpret_cast<const uint4*>(
                &wt3[((size_t)k * 128 + (ci0 >> 1) + c2) * 256 + co0 + co4]);
            *reinterpret_cast<uint4*>(&swt[(c2 * 9 + k) * 72 + co4]) = v;
        }
        __syncthreads();

        if (ci0 + 16 < CCH) C3_LOAD(plo2, phi2, ci0 + 16);

#pragma unroll
        for (int k = 0; k < 9; k++) {
            const int kh = k / 3, kw = k % 3;
            u32 a[2][4];
#pragma unroll
            for (int rm = 0; rm < 2; rm++) {
                int cof = co_base + rm * 16;
                a[rm][0] = swt[((ctid) * 9 + k) * 72 + cof + gid];
                a[rm][1] = swt[((ctid) * 9 + k) * 72 + cof + gid + 8];
                a[rm][2] = swt[((ctid + 4) * 9 + k) * 72 + cof + gid];
                a[rm][3] = swt[((ctid + 4) * 9 + k) * 72 + cof + gid + 8];
            }
#pragma unroll
            for (int f = 0; f < 4; f++) {
                int px = px_base + f * 8 + gid;
                int rl = px >> 6;            // 0..1
                int wc = (px & 63) + kw;
                u32 bf[2];
                bf[0] = sxt[((rl + kh) * 8 + ctid) * 72 + wc];
                bf[1] = sxt[((rl + kh) * 8 + ctid + 4) * 72 + wc];
                mma_bf16(acc[0][f], a[0], bf);
                mma_bf16(acc[1][f], a[1], bf);
            }
        }
        __syncthreads();

#pragma unroll
        for (int j = 0; j < 9; j++) { plo[j] = plo2[j]; phi[j] = phi2[j]; }
    }

#pragma unroll
    for (int rm = 0; rm < 2; rm++) {
#pragma unroll
        for (int f = 0; f < 4; f++) {
            int coA = co0 + co_base + rm * 16 + gid;
            int coB = coA + 8;
            int px  = px_base + f * 8 + 2 * ctid;
            int n   = (h0 + (px >> 6)) * WW + (px & 63);
            float bA = bias[coA], bB = bias[coB];
            float2 sA = {acc[rm][f][0] + bA, acc[rm][f][1] + bA};
            float2 sB = {acc[rm][f][2] + bB, acc[rm][f][3] + bB};
            *reinterpret_cast<float2*>(&out[((size_t)b * CCH + coA) * NN + n]) = sA;
            *reinterpret_cast<float2*>(&out[((size_t)b * CCH + coB) * NN + n]) = sB;
        }
    }
}

// ---------------------------------------------------------------------------
// FUSED K+V 2x2 conv s2 p0, implicit GEMM tf32, prefetched.
// grid: (HK/4=8, CCH/64=4, B=8)
// ---------------------------------------------------------------------------
__global__ __launch_bounds__(256, 2) void conv2kv_mma(
    const u32* __restrict__ wtK, const u32* __restrict__ wtV,
    const float* __restrict__ y,
    const float* __restrict__ bK, const float* __restrict__ bV,
    float* __restrict__ outK, float* __restrict__ outV)
{
    const int h0  = blockIdx.x * 4;
    const int co0 = blockIdx.y * 64;
    const int b   = blockIdx.z;
    const int tid  = threadIdx.x;
    const int lane = tid & 31;
    const int w    = tid >> 5;
    const int gid  = lane >> 2;
    const int ctid = lane & 3;
    const int co_base = (w >> 2) * 32;
    const int px_base = (w & 3) * 32;

    __shared__ u32 sy[2 * 8 * 8 * 40];
    __shared__ u32 swK[8 * 4 * 74];
    __shared__ u32 swV[8 * 4 * 74];

    float accK[2][4][4], accV[2][4][4];
#pragma unroll
    for (int i = 0; i < 2; i++)
#pragma unroll
        for (int j = 0; j < 4; j++)
#pragma unroll
            for (int l = 0; l < 4; l++) { accK[i][j][l] = 0.f; accV[i][j][l] = 0.f; }

    const float* yb = y + (size_t)b * CCH * (HH * WW);
    const int ih0 = h0 * 2;

    float4 pin[4], pin2[4];

#define C2_LOAD(dst, CI0)                                                   \
    {                                                                       \
        _Pragma("unroll")                                                   \
        for (int j = 0; j < 4; j++) {                                       \
            int i  = tid + j * 256;                                         \
            int r  = i >> 7;                                                \
            int ci = (i >> 4) & 7;                                          \
            int c4 = (i & 15) * 4;                                          \
            dst[j] = *reinterpret_cast<const float4*>(                      \
                &yb[(size_t)((CI0) + ci) * (HH * WW) + (ih0 + r) * WW + c4]);\
        }                                                                   \
    }

    C2_LOAD(pin, 0);

    for (int ci0 = 0; ci0 < CCH; ci0 += 8) {
#pragma unroll
        for (int j = 0; j < 4; j++) {
            int i  = tid + j * 256;
            int r  = i >> 7;
            int ci = (i >> 4) & 7;
            int c4 = (i & 15) * 4;
            float4 v = pin[j];
            u32* even = &sy[((0 * 8 + r) * 8 + ci) * 40 + (c4 >> 1)];
            u32* odd  = &sy[((8 + r) * 8 + ci) * 40 + (c4 >> 1)];
            even[0] = f2tf(v.x); odd[0] = f2tf(v.y);
            even[1] = f2tf(v.z); odd[1] = f2tf(v.w);
        }
        for (int i = tid; i < 8 * 4 * 16; i += 256) {
            int k   = i / 128;
            int ci  = (i >> 4) & 7;
            int co4 = (i & 15) * 4;
            size_t off = ((size_t)k * 256 + ci0 + ci) * 256 + co0 + co4;
            uint4 vk = *reinterpret_cast<const uint4*>(&wtK[off]);
            uint4 vv = *reinterpret_cast<const uint4*>(&wtV[off]);
            u32* dk = &swK[(ci * 4 + k) * 74 + co4];
            dk[0] = vk.x; dk[1] = vk.y; dk[2] = vk.z; dk[3] = vk.w;
            u32* dv = &swV[(ci * 4 + k) * 74 + co4];
            dv[0] = vv.x; dv[1] = vv.y; dv[2] = vv.z; dv[3] = vv.w;
        }
        __syncthreads();

        if (ci0 + 8 < CCH) C2_LOAD(pin2, ci0 + 8);

#pragma unroll
        for (int k = 0; k < 4; k++) {
            const int kh = k >> 1, kw = k & 1;
            u32 aK[2][4], aV[2][4];
#pragma unroll
            for (int rm = 0; rm < 2; rm++) {
                int cof = co_base + rm * 16;
                int r0 = (ctid * 4 + k) * 74 + cof;
                int r1 = ((ctid + 4) * 4 + k) * 74 + cof;
                aK[rm][0] = swK[r0 + gid];     aK[rm][1] = swK[r0 + gid + 8];
                aK[rm][2] = swK[r1 + gid];     aK[rm][3] = swK[r1 + gid + 8];
                aV[rm][0] = swV[r0 + gid];     aV[rm][1] = swV[r0 + gid + 8];
                aV[rm][2] = swV[r1 + gid];     aV[rm][3] = swV[r1 + gid + 8];
            }
#pragma unroll
            for (int f = 0; f < 4; f++) {
                int px = px_base + f * 8 + gid;
                int r  = 2 * (px >> 5) + kh;
                int wl = px & 31;
                u32 bf[2];
                bf[0] = sy[((kw * 8 + r) * 8 + ctid) * 40 + wl];
                bf[1] = sy[((kw * 8 + r) * 8 + ctid + 4) * 40 + wl];
                mma_tf32(accK[0][f], aK[0], bf);
                mma_tf32(accK[1][f], aK[1], bf);
                mma_tf32(accV[0][f], aV[0], bf);
                mma_tf32(accV[1][f], aV[1], bf);
            }
        }
        __syncthreads();

#pragma unroll
        for (int j = 0; j < 4; j++) pin[j] = pin2[j];
    }

#pragma unroll
    for (int rm = 0; rm < 2; rm++) {
#pragma unroll
        for (int f = 0; f < 4; f++) {
            int coA = co0 + co_base + rm * 16 + gid;
            int coB = coA + 8;
            int px  = px_base + f * 8 + 2 * ctid;
            int n   = (h0 + (px >> 5)) * WK + (px & 31);
            size_t oA = ((size_t)b * CCH + coA) * MM + n;
            size_t oB = ((size_t)b * CCH + coB) * MM + n;
            float bkA = bK[coA], bkB = bK[coB];
            float bvA = bV[coA], bvB = bV[coB];
            float2 kA = {accK[rm][f][0] + bkA, accK[rm][f][1] + bkA};
            float2 kB = {accK[rm][f][2] + bkB, accK[rm][f][3] + bkB};
            float2 vA = {accV[rm][f][0] + bvA, accV[rm][f][1] + bvA};
            float2 vB = {accV[rm][f][2] + bvB, accV[rm][f][3] + bvB};
            *reinterpret_cast<float2*>(&outK[oA]) = kA;
            *reinterpret_cast<float2*>(&outK[oB]) = kB;
            *reinterpret_cast<float2*>(&outV[oA]) = vA;
            *reinterpret_cast<float2*>(&outV[oB]) = vB;
        }
    }
}

// ---------------------------------------------------------------------------
// GroupNorm(32 groups of 8 ch) + affine + SiLU, in place. float4, 512 thr.
// ---------------------------------------------------------------------------
__global__ __launch_bounds__(512) void gn_silu_kernel(
    float* __restrict__ buf, const float* __restrict__ scale,
    const float* __restrict__ bias, int S)
{
    const int b = blockIdx.x >> 5;
    const int g = blockIdx.x & 31;
    float* base = buf + ((size_t)b * CCH + g * 8) * S;
    float4* p4 = reinterpret_cast<float4*>(base);
    const int tot4 = (8 * S) >> 2;
    const int tid = threadIdx.x;

    float s = 0.f, ss = 0.f;
    for (int i = tid; i < tot4; i += 512) {
        float4 v = p4[i];
        s += v.x + v.y + v.z + v.w;
        ss = fmaf(v.x, v.x, ss);
        ss = fmaf(v.y, v.y, ss);
        ss = fmaf(v.z, v.z, ss);
        ss = fmaf(v.w, v.w, ss);
    }
    __shared__ float r1[512], r2[512];
    r1[tid] = s; r2[tid] = ss;
    __syncthreads();
    for (int st = 256; st > 0; st >>= 1) {
        if (tid < st) { r1[tid] += r1[tid + st]; r2[tid] += r2[tid + st]; }
        __syncthreads();
    }
    const float tot = (float)(8 * S);
    const float mu   = r1[0] / tot;
    const float var  = r2[0] / tot - mu * mu;
    const float rstd = rsqrtf(var + 1e-5f);

    const int s4 = S >> 2;
    for (int i = tid; i < tot4; i += 512) {
        int c = g * 8 + i / s4;
        float sc = scale[c] * rstd, bi = bias[c] - mu * scale[c] * rstd;
        float4 v = p4[i];
        v.x = fmaf(v.x, sc, bi);
        v.y = fmaf(v.y, sc, bi);
        v.z = fmaf(v.z, sc, bi);
        v.w = fmaf(v.w, sc, bi);
        v.x = v.x / (1.f + __expf(-v.x));
        v.y = v.y / (1.f + __expf(-v.y));
        v.z = v.z / (1.f + __expf(-v.z));
        v.w = v.w / (1.f + __expf(-v.w));
        p4[i] = v;
    }
}

// ---------------------------------------------------------------------------
// E = (1/16) Q^T K  (bf16 m16n8k16), staged loads double-buffered.
// grid: (MM/128=8, NN/128=32, B=8)
// ---------------------------------------------------------------------------
__global__ __launch_bounds__(256, 2) void gemm_qk_mma(
    const float* __restrict__ Q, const float* __restrict__ K,
    float* __restrict__ E)
{
    const int mb = blockIdx.x * 128;
    const int nb = blockIdx.y * 128;
    const int b  = blockIdx.z;
    const int tid  = threadIdx.x;
    const int lane = tid & 31;
    const int w    = tid >> 5;
    const int gid  = lane >> 2;
    const int ctid = lane & 3;
    const int m_base = (w & 1) * 64;
    const int n_base = (w >> 1) * 32;

    __shared__ u32 sq2[8 * 136];   // [c2][n pad 136]
    __shared__ u32 sk2[8 * 136];   // [c2][m pad 136]

    float acc[2][8][4];
#pragma unroll
    for (int i = 0; i < 2; i++)
#pragma unroll
        for (int j = 0; j < 8; j++)
#pragma unroll
            for (int l = 0; l < 4; l++) acc[i][j][l] = 0.f;

    const float* Qb = Q + (size_t)b * CCH * NN + nb;
    const float* Kb = K + (size_t)b * CCH * MM + mb;

    const int kc  = tid >> 5;
    const int col = (lane) * 4;

    float4 pq0, pq1, pk0, pk1, nq0, nq1, nk0, nk1;

#define QK_LOAD(q0, q1, k0, k1, C0)                                                        \
    {                                                                                      \
        q0 = *reinterpret_cast<const float4*>(&Qb[(size_t)((C0) + 2 * kc) * NN + col]);     \
        q1 = *reinterpret_cast<const float4*>(&Qb[(size_t)((C0) + 2 * kc + 1) * NN + col]); \
        k0 = *reinterpret_cast<const float4*>(&Kb[(size_t)((C0) + 2 * kc) * MM + col]);     \
        k1 = *reinterpret_cast<const float4*>(&Kb[(size_t)((C0) + 2 * kc + 1) * MM + col]); \
    }

    QK_LOAD(pq0, pq1, pk0, pk1, 0);

    for (int c0 = 0; c0 < CCH; c0 += 16) {
        uint4 qs = {pkbf(pq0.x, pq1.x), pkbf(pq0.y, pq1.y),
                    pkbf(pq0.z, pq1.z), pkbf(pq0.w, pq1.w)};
        uint4 ks = {pkbf(pk0.x, pk1.x), pkbf(pk0.y, pk1.y),
                    pkbf(pk0.z, pk1.z), pkbf(pk0.w, pk1.w)};
        *reinterpret_cast<uint4*>(&sq2[kc * 136 + col]) = qs;
        *reinterpret_cast<uint4*>(&sk2[kc * 136 + col]) = ks;
        __syncthreads();

        if (c0 + 16 < CCH) QK_LOAD(nq0, nq1, nk0, nk1, c0 + 16);

        u32 a[2][4];
#pragma unroll
        for (int rm = 0; rm < 2; rm++) {
            int n0 = n_base + rm * 16;
            a[rm][0] = sq2[ctid * 136 + n0 + gid];
            a[rm][1] = sq2[ctid * 136 + n0 + gid + 8];
            a[rm][2] = sq2[(ctid + 4) * 136 + n0 + gid];
            a[rm][3] = sq2[(ctid + 4) * 136 + n0 + gid + 8];
        }
#pragma unroll
        for (int f = 0; f < 8; f++) {
            u32 bf[2];
            bf[0] = sk2[ctid * 136 + m_base + f * 8 + gid];
            bf[1] = sk2[(ctid + 4) * 136 + m_base + f * 8 + gid];
            mma_bf16(acc[0][f], a[0], bf);
            mma_bf16(acc[1][f], a[1], bf);
        }
        __syncthreads();

        pq0 = nq0; pq1 = nq1; pk0 = nk0; pk1 = nk1;
    }

    const float scale = 0.0625f;
    float* Eb = E + ((size_t)b * NN + nb) * MM + mb;
#pragma unroll
    for (int rm = 0; rm < 2; rm++) {
#pragma unroll
        for (int f = 0; f < 8; f++) {
            int r0 = n_base + rm * 16 + gid;
            int cc = m_base + f * 8 + 2 * ctid;
            float2 s0 = {acc[rm][f][0] * scale, acc[rm][f][1] * scale};
            float2 s1 = {acc[rm][f][2] * scale, acc[rm][f][3] * scale};
            *reinterpret_cast<float2*>(&Eb[(size_t)r0 * MM + cc])       = s0;
            *reinterpret_cast<float2*>(&Eb[(size_t)(r0 + 8) * MM + cc]) = s1;
        }
    }
}

// ---------------------------------------------------------------------------
// In-place softmax over last dim (M=1024). One WARP per row.
// ---------------------------------------------------------------------------
__global__ __launch_bounds__(256) void softmax_kernel(float* __restrict__ E)
{
    const int warp = threadIdx.x >> 5;
    const int lane = threadIdx.x & 31;
    const size_t row = (size_t)blockIdx.x * 8 + warp;
    float4* p = reinterpret_cast<float4*>(E + row * MM);

    float4 v[8];
    float mx = -1e30f;
#pragma unroll
    for (int i = 0; i < 8; i++) {
        v[i] = p[lane + 32 * i];
        mx = fmaxf(mx, fmaxf(fmaxf(v[i].x, v[i].y), fmaxf(v[i].z, v[i].w)));
    }
#pragma unroll
    for (int o = 16; o > 0; o >>= 1)
        mx = fmaxf(mx, __shfl_xor_sync(0xFFFFFFFFu, mx, o));

    float sum = 0.f;
#pragma unroll
    for (int i = 0; i < 8; i++) {
        v[i].x = __expf(v[i].x - mx);
        v[i].y = __expf(v[i].y - mx);
        v[i].z = __expf(v[i].z - mx);
        v[i].w = __expf(v[i].w - mx);
        sum += v[i].x + v[i].y + v[i].z + v[i].w;
    }
#pragma unroll
    for (int o = 16; o > 0; o >>= 1)
        sum += __shfl_xor_sync(0xFFFFFFFFu, sum, o);

    float inv = 1.f / sum;
#pragma unroll
    for (int i = 0; i < 8; i++) {
        v[i].x *= inv; v[i].y *= inv; v[i].z *= inv; v[i].w *= inv;
        p[lane + 32 * i] = v[i];
    }
}

// ---------------------------------------------------------------------------
// out = gamma * V A^T (bf16 m16n8k16), staged loads double-buffered.
// grid: (NN/128=32, CCH/128=2, B=8)
// ---------------------------------------------------------------------------
__global__ __launch_bounds__(256, 2) void gemm_av_mma(
    const float* __restrict__ V, const float* __restrict__ A,
    const float* __restrict__ gamma, float* __restrict__ out)
{
    const int nb = blockIdx.x * 128;
    const int cb = blockIdx.y * 128;
    const int b  = blockIdx.z;
    const int tid  = threadIdx.x;
    const int lane = tid & 31;
    const int w    = tid >> 5;
    const int gid  = lane >> 2;
    const int ctid = lane & 3;
    const int n_base = (w & 1) * 64;
    const int c_base = (w >> 1) * 32;

    __shared__ u32 sv2[8 * 136];
    __shared__ u32 sa2[8 * 136];

    float acc[2][8][4];
#pragma unroll
    for (int i = 0; i < 2; i++)
#pragma unroll
        for (int j = 0; j < 8; j++)
#pragma unroll
            for (int l = 0; l < 4; l++) acc[i][j][l] = 0.f;

    const float* Vb = V + (size_t)b * CCH * MM;
    const float* Ab = A + (size_t)b * NN * MM;

    const int row0 = tid >> 2, f0 = tid & 3;
    const int row1 = row0 + 64;

    float4 pv0, pv1, pa0, pa1, nv0, nv1, na0, na1;

#define AV_LOAD(v0, v1, a0v, a1v, M0)                                                         \
    {                                                                                         \
        v0  = *reinterpret_cast<const float4*>(&Vb[(size_t)(cb + row0) * MM + (M0) + f0 * 4]); \
        v1  = *reinterpret_cast<const float4*>(&Vb[(size_t)(cb + row1) * MM + (M0) + f0 * 4]); \
        a0v = *reinterpret_cast<const float4*>(&Ab[(size_t)(nb + row0) * MM + (M0) + f0 * 4]); \
        a1v = *reinterpret_cast<const float4*>(&Ab[(size_t)(nb + row1) * MM + (M0) + f0 * 4]); \
    }

    AV_LOAD(pv0, pv1, pa0, pa1, 0);

    for (int m0 = 0; m0 < MM; m0 += 16) {
        sv2[(f0 * 2) * 136 + row0]     = pkbf(pv0.x, pv0.y);
        sv2[(f0 * 2 + 1) * 136 + row0] = pkbf(pv0.z, pv0.w);
        sv2[(f0 * 2) * 136 + row1]     = pkbf(pv1.x, pv1.y);
        sv2[(f0 * 2 + 1) * 136 + row1] = pkbf(pv1.z, pv1.w);
        sa2[(f0 * 2) * 136 + row0]     = pkbf(pa0.x, pa0.y);
        sa2[(f0 * 2 + 1) * 136 + row0] = pkbf(pa0.z, pa0.w);
        sa2[(f0 * 2) * 136 + row1]     = pkbf(pa1.x, pa1.y);
        sa2[(f0 * 2 + 1) * 136 + row1] = pkbf(pa1.z, pa1.w);
        __syncthreads();

        if (m0 + 16 < MM) AV_LOAD(nv0, nv1, na0, na1, m0 + 16);

        u32 a[2][4];
#pragma unroll
        for (int rm = 0; rm < 2; rm++) {
            int c0 = c_base + rm * 16;
            a[rm][0] = sv2[ctid * 136 + c0 + gid];
            a[rm][1] = sv2[ctid * 136 + c0 + gid + 8];
            a[rm][2] = sv2[(ctid + 4) * 136 + c0 + gid];
            a[rm][3] = sv2[(ctid + 4) * 136 + c0 + gid + 8];
        }
#pragma unroll
        for (int f = 0; f < 8; f++) {
            u32 bf[2];
            bf[0] = sa2[ctid * 136 + n_base + f * 8 + gid];
            bf[1] = sa2[(ctid + 4) * 136 + n_base + f * 8 + gid];
            mma_bf16(acc[0][f], a[0], bf);
            mma_bf16(acc[1][f], a[1], bf);
        }
        __syncthreads();

        pv0 = nv0; pv1 = nv1; pa0 = na0; pa1 = na1;
    }

    const float gm = gamma[0];
#pragma unroll
    for (int rm = 0; rm < 2; rm++) {
#pragma unroll
        for (int f = 0; f < 8; f++) {
            int c0 = cb + c_base + rm * 16 + gid;
            int nn2 = nb + n_base + f * 8 + 2 * ctid;
            float2 s0 = {gm * acc[rm][f][0], gm * acc[rm][f][1]};
            float2 s1 = {gm * acc[rm][f][2], gm * acc[rm][f][3]};
            *reinterpret_cast<float2*>(&out[((size_t)b * CCH + c0) * NN + nn2])     = s0;
            *reinterpret_cast<float2*>(&out[((size_t)b * CCH + c0 + 8) * NN + nn2]) = s1;
        }
    }
}

// ---------------------------------------------------------------------------
extern "C" void kernel_launch(void* const* d_in, const int* in_sizes, int n_in,
                              void* d_out, int out_size)
{
    const float* x        = (const float*)d_in[0];
    const float* y        = (const float*)d_in[1];
    const float* Wq       = (const float*)d_in[2];
    const float* bq       = (const float*)d_in[3];
    const float* gq_scale = (const float*)d_in[4];
    const float* gq_bias  = (const float*)d_in[5];
    const float* Wk       = (const float*)d_in[6];
    const float* bk       = (const float*)d_in[7];
    const float* gk_scale = (const float*)d_in[8];
    const float* gk_bias  = (const float*)d_in[9];
    const float* Wv       = (const float*)d_in[10];
    const float* bv       = (const float*)d_in[11];
    const float* gv_scale = (const float*)d_in[12];
    const float* gv_bias  = (const float*)d_in[13];
    const float* gamma    = (const float*)d_in[14];
    float* out = (float*)d_out;

    float *qp = nullptr, *kp = nullptr, *vp = nullptr, *ep = nullptr;
    u32 *wtp = nullptr, *wkp = nullptr, *wvp = nullptr;
    cudaGetSymbolAddress((void**)&qp, g_q);
    cudaGetSymbolAddress((void**)&kp, g_k);
    cudaGetSymbolAddress((void**)&vp, g_v);
    cudaGetSymbolAddress((void**)&ep, g_e);
    cudaGetSymbolAddress((void**)&wtp, g_wt3);
    cudaGetSymbolAddress((void**)&wkp, g_wk2);
    cudaGetSymbolAddress((void**)&wvp, g_wv2);

    transpose_w3<<<(9 * 128 * 256 + 255) / 256, 256>>>(Wq, wtp);
    transpose_w2<<<(4 * 256 * 256 + 255) / 256, 256>>>(Wk, Wv, wkp, wvp);

    conv3_mma<<<dim3(HH / 2, CCH / 64, BATCH), 256>>>(wtp, x, bq, qp);
    conv2kv_mma<<<dim3(HK / 4, CCH / 64, BATCH), 256>>>(wkp, wvp, y, bk, bv, kp, vp);

    gn_silu_kernel<<<BATCH * 32, 512>>>(qp, gq_scale, gq_bias, NN);
    gn_silu_kernel<<<BATCH * 32, 512>>>(kp, gk_scale, gk_bias, MM);
    gn_silu_kernel<<<BATCH * 32, 512>>>(vp, gv_scale, gv_bias, MM);

    gemm_qk_mma<<<dim3(MM / 128, NN / 128, BATCH), 256>>>(qp, kp, ep);
    softmax_kernel<<<BATCH * NN / 8, 256>>>(ep);
    gemm_av_mma<<<dim3(NN / 128, CCH / 128, BATCH), 256>>>(vp, ep, gamma, out);
}

// round 11
// speedup vs baseline: 9.1724x; 1.0323x over previous
#include <cuda_runtime.h>
#include <math.h>

#define BATCH 8
#define CCH   256
#define HH    64
#define WW    64
#define NN    4096   // HH*WW
#define MM    1024   // (HH/2)*(WW/2)
#define HK    32
#define WK    32

typedef unsigned long long u64;
typedef unsigned int u32;

__device__ __forceinline__ u32 f2tf(float f) {
    u32 u; asm("cvt.rna.tf32.f32 %0,%1;" : "=r"(u) : "f"(f)); return u;
}
// pack (lo, hi) floats -> bf16x2 word (lo in low half)
__device__ __forceinline__ u32 pkbf(float lo, float hi) {
    u32 d; asm("cvt.rn.bf16x2.f32 %0,%1,%2;" : "=r"(d) : "f"(hi), "f"(lo)); return d;
}
__device__ __forceinline__ void mma_tf32(float* d, const u32* a, const u32* b) {
    asm volatile(
        "mma.sync.aligned.m16n8k8.row.col.f32.tf32.tf32.f32 "
        "{%0,%1,%2,%3},{%4,%5,%6,%7},{%8,%9},{%0,%1,%2,%3};"
        : "+f"(d[0]), "+f"(d[1]), "+f"(d[2]), "+f"(d[3])
        : "r"(a[0]), "r"(a[1]), "r"(a[2]), "r"(a[3]), "r"(b[0]), "r"(b[1]));
}
__device__ __forceinline__ void mma_bf16(float* d, const u32* a, const u32* b) {
    asm volatile(
        "mma.sync.aligned.m16n8k16.row.col.f32.bf16.bf16.f32 "
        "{%0,%1,%2,%3},{%4,%5,%6,%7},{%8,%9},{%0,%1,%2,%3};"
        : "+f"(d[0]), "+f"(d[1]), "+f"(d[2]), "+f"(d[3])
        : "r"(a[0]), "r"(a[1]), "r"(a[2]), "r"(a[3]), "r"(b[0]), "r"(b[1]));
}

// Scratch
__device__ float g_q[(size_t)BATCH * CCH * NN];   // 32 MB
__device__ float g_k[(size_t)BATCH * CCH * MM];   // 8 MB
__device__ float g_v[(size_t)BATCH * CCH * MM];   // 8 MB
__device__ float g_e[(size_t)BATCH * NN * MM];    // 128 MB (pre-softmax, fp32)
__device__ u32   g_a[(size_t)BATCH * NN * (MM/2)]; // 64 MB (post-softmax, bf16x2 m-pairs)
__device__ u32   g_wt3[9 * 128 * 256];            // Wq [k][ci2][co] bf16x2
__device__ u32   g_wk2[4 * 256 * 256];            // Wk transposed, tf32
__device__ u32   g_wv2[4 * 256 * 256];            // Wv transposed, tf32

// ---------------------------------------------------------------------------
// Wq OIHW -> [k][ci2][co] packed bf16x2 (ci pair in one word).
// ---------------------------------------------------------------------------
__global__ __launch_bounds__(256) void transpose_w3(
    const float* __restrict__ Wt, u32* __restrict__ wt3)
{
    int i = blockIdx.x * 256 + threadIdx.x;
    if (i < 9 * 128 * 256) {
        int co  = i & 255;
        int ci2 = (i >> 8) & 127;
        int k   = i >> 15;
        float lo = Wt[((size_t)co * 256 + 2 * ci2) * 9 + k];
        float hi = Wt[((size_t)co * 256 + 2 * ci2 + 1) * 9 + k];
        wt3[i] = pkbf(lo, hi);
    }
}

__global__ __launch_bounds__(256) void transpose_w2(
    const float* __restrict__ Wk, const float* __restrict__ Wv,
    u32* __restrict__ wk2, u32* __restrict__ wv2)
{
    int i = blockIdx.x * 256 + threadIdx.x;
    if (i < 4 * 256 * 256) {
        int co = i & 255;
        int ci = (i >> 8) & 255;
        int k  = i >> 16;
        wk2[i] = f2tf(Wk[((size_t)co * 256 + ci) * 4 + k]);
        wv2[i] = f2tf(Wv[((size_t)co * 256 + ci) * 4 + k]);
    }
}

// ---------------------------------------------------------------------------
// 3x3 conv s1 p1, implicit GEMM bf16 (m16n8k16), ci-chunk 16, prefetched.
// grid: (HH/2=32, CCH/64=4, B=8)
// ---------------------------------------------------------------------------
__global__ __launch_bounds__(256, 2) void conv3_mma(
    const u32* __restrict__ wt3, const float* __restrict__ x,
    const float* __restrict__ bias, float* __restrict__ out)
{
    const int h0  = blockIdx.x * 2;
    const int co0 = blockIdx.y * 64;
    const int b   = blockIdx.z;
    const int tid  = threadIdx.x;
    const int lane = tid & 31;
    const int w    = tid >> 5;
    const int gid  = lane >> 2;
    const int ctid = lane & 3;
    const int co_base = (w >> 2) * 32;
    const int px_base = (w & 3) * 32;

    __shared__ u32 sxt[4 * 8 * 72];   // [r][c2][col pad 72] bf16x2
    __shared__ u32 swt[8 * 9 * 72];   // [c2][k][co pad 72] bf16x2

    float acc[2][4][4];
#pragma unroll
    for (int i = 0; i < 2; i++)
#pragma unroll
        for (int j = 0; j < 4; j++)
#pragma unroll
            for (int l = 0; l < 4; l++) acc[i][j][l] = 0.f;

    const float* xb = x + (size_t)b * CCH * (HH * WW);

    float plo[9], phi[9], plo2[9], phi2[9];

#define C3_LOAD(dlo, dhi, CI0)                                              \
    {                                                                       \
        _Pragma("unroll")                                                   \
        for (int j = 0; j < 9; j++) {                                       \
            int i = tid + j * 256;                                          \
            if (i < 2112) {                                                 \
                int r   = i / 528;                                          \
                int c2  = (i / 66) & 7;                                     \
                int col = i % 66;                                           \
                int gh = h0 - 1 + r;                                        \
                int gw = col - 1;                                           \
                float vlo = 0.f, vhi = 0.f;                                 \
                if ((unsigned)gh < HH && (unsigned)gw < WW) {               \
                    size_t base = (size_t)((CI0) + 2 * c2) * (HH * WW)      \
                                  + gh * WW + gw;                           \
                    vlo = xb[base];                                         \
                    vhi = xb[base + HH * WW];                               \
                }                                                           \
                dlo[j] = vlo; dhi[j] = vhi;                                 \
            }                                                               \
        }                                                                   \
    }

    C3_LOAD(plo, phi, 0);

    for (int ci0 = 0; ci0 < CCH; ci0 += 16) {
#pragma unroll
        for (int j = 0; j < 9; j++) {
            int i = tid + j * 256;
            if (i < 2112) {
                int r   = i / 528;
                int c2  = (i / 66) & 7;
                int col = i % 66;
                sxt[(r * 8 + c2) * 72 + col] = pkbf(plo[j], phi[j]);
            }
        }
        for (int i = tid; i < 8 * 9 * 16; i += 256) {
            int k   = i / 128;
            int c2  = (i >> 4) & 7;
            int co4 = (i & 15) * 4;
            uint4 v = *reinterpret_cast<const uint4*>(
                &wt3[((size_t)k * 128 + (ci0 >> 1) + c2) * 256 + co0 + co4]);
            *reinterpret_cast<uint4*>(&swt[(c2 * 9 + k) * 72 + co4]) = v;
        }
        __syncthreads();

        if (ci0 + 16 < CCH) C3_LOAD(plo2, phi2, ci0 + 16);

#pragma unroll
        for (int k = 0; k < 9; k++) {
            const int kh = k / 3, kw = k % 3;
            u32 a[2][4];
#pragma unroll
            for (int rm = 0; rm < 2; rm++) {
                int cof = co_base + rm * 16;
                a[rm][0] = swt[((ctid) * 9 + k) * 72 + cof + gid];
                a[rm][1] = swt[((ctid) * 9 + k) * 72 + cof + gid + 8];
                a[rm][2] = swt[((ctid + 4) * 9 + k) * 72 + cof + gid];
                a[rm][3] = swt[((ctid + 4) * 9 + k) * 72 + cof + gid + 8];
            }
#pragma unroll
            for (int f = 0; f < 4; f++) {
                int px = px_base + f * 8 + gid;
                int rl = px >> 6;
                int wc = (px & 63) + kw;
                u32 bf[2];
                bf[0] = sxt[((rl + kh) * 8 + ctid) * 72 + wc];
                bf[1] = sxt[((rl + kh) * 8 + ctid + 4) * 72 + wc];
                mma_bf16(acc[0][f], a[0], bf);
                mma_bf16(acc[1][f], a[1], bf);
            }
        }
        __syncthreads();

#pragma unroll
        for (int j = 0; j < 9; j++) { plo[j] = plo2[j]; phi[j] = phi2[j]; }
    }

#pragma unroll
    for (int rm = 0; rm < 2; rm++) {
#pragma unroll
        for (int f = 0; f < 4; f++) {
            int coA = co0 + co_base + rm * 16 + gid;
            int coB = coA + 8;
            int px  = px_base + f * 8 + 2 * ctid;
            int n   = (h0 + (px >> 6)) * WW + (px & 63);
            float bA = bias[coA], bB = bias[coB];
            float2 sA = {acc[rm][f][0] + bA, acc[rm][f][1] + bA};
            float2 sB = {acc[rm][f][2] + bB, acc[rm][f][3] + bB};
            *reinterpret_cast<float2*>(&out[((size_t)b * CCH + coA) * NN + n]) = sA;
            *reinterpret_cast<float2*>(&out[((size_t)b * CCH + coB) * NN + n]) = sB;
        }
    }
}

// ---------------------------------------------------------------------------
// FUSED K+V 2x2 conv s2 p0, implicit GEMM tf32, prefetched.
// grid: (HK/4=8, CCH/64=4, B=8)
// ---------------------------------------------------------------------------
__global__ __launch_bounds__(256, 2) void conv2kv_mma(
    const u32* __restrict__ wtK, const u32* __restrict__ wtV,
    const float* __restrict__ y,
    const float* __restrict__ bK, const float* __restrict__ bV,
    float* __restrict__ outK, float* __restrict__ outV)
{
    const int h0  = blockIdx.x * 4;
    const int co0 = blockIdx.y * 64;
    const int b   = blockIdx.z;
    const int tid  = threadIdx.x;
    const int lane = tid & 31;
    const int w    = tid >> 5;
    const int gid  = lane >> 2;
    const int ctid = lane & 3;
    const int co_base = (w >> 2) * 32;
    const int px_base = (w & 3) * 32;

    __shared__ u32 sy[2 * 8 * 8 * 40];
    __shared__ u32 swK[8 * 4 * 74];
    __shared__ u32 swV[8 * 4 * 74];

    float accK[2][4][4], accV[2][4][4];
#pragma unroll
    for (int i = 0; i < 2; i++)
#pragma unroll
        for (int j = 0; j < 4; j++)
#pragma unroll
            for (int l = 0; l < 4; l++) { accK[i][j][l] = 0.f; accV[i][j][l] = 0.f; }

    const float* yb = y + (size_t)b * CCH * (HH * WW);
    const int ih0 = h0 * 2;

    float4 pin[4], pin2[4];

#define C2_LOAD(dst, CI0)                                                   \
    {                                                                       \
        _Pragma("unroll")                                                   \
        for (int j = 0; j < 4; j++) {                                       \
            int i  = tid + j * 256;                                         \
            int r  = i >> 7;                                                \
            int ci = (i >> 4) & 7;                                          \
            int c4 = (i & 15) * 4;                                          \
            dst[j] = *reinterpret_cast<const float4*>(                      \
                &yb[(size_t)((CI0) + ci) * (HH * WW) + (ih0 + r) * WW + c4]);\
        }                                                                   \
    }

    C2_LOAD(pin, 0);

    for (int ci0 = 0; ci0 < CCH; ci0 += 8) {
#pragma unroll
        for (int j = 0; j < 4; j++) {
            int i  = tid + j * 256;
            int r  = i >> 7;
            int ci = (i >> 4) & 7;
            int c4 = (i & 15) * 4;
            float4 v = pin[j];
            u32* even = &sy[((0 * 8 + r) * 8 + ci) * 40 + (c4 >> 1)];
            u32* odd  = &sy[((8 + r) * 8 + ci) * 40 + (c4 >> 1)];
            even[0] = f2tf(v.x); odd[0] = f2tf(v.y);
            even[1] = f2tf(v.z); odd[1] = f2tf(v.w);
        }
        for (int i = tid; i < 8 * 4 * 16; i += 256) {
            int k   = i / 128;
            int ci  = (i >> 4) & 7;
            int co4 = (i & 15) * 4;
            size_t off = ((size_t)k * 256 + ci0 + ci) * 256 + co0 + co4;
            uint4 vk = *reinterpret_cast<const uint4*>(&wtK[off]);
            uint4 vv = *reinterpret_cast<const uint4*>(&wtV[off]);
            u32* dk = &swK[(ci * 4 + k) * 74 + co4];
            dk[0] = vk.x; dk[1] = vk.y; dk[2] = vk.z; dk[3] = vk.w;
            u32* dv = &swV[(ci * 4 + k) * 74 + co4];
            dv[0] = vv.x; dv[1] = vv.y; dv[2] = vv.z; dv[3] = vv.w;
        }
        __syncthreads();

        if (ci0 + 8 < CCH) C2_LOAD(pin2, ci0 + 8);

#pragma unroll
        for (int k = 0; k < 4; k++) {
            const int kh = k >> 1, kw = k & 1;
            u32 aK[2][4], aV[2][4];
#pragma unroll
            for (int rm = 0; rm < 2; rm++) {
                int cof = co_base + rm * 16;
                int r0 = (ctid * 4 + k) * 74 + cof;
                int r1 = ((ctid + 4) * 4 + k) * 74 + cof;
                aK[rm][0] = swK[r0 + gid];     aK[rm][1] = swK[r0 + gid + 8];
                aK[rm][2] = swK[r1 + gid];     aK[rm][3] = swK[r1 + gid + 8];
                aV[rm][0] = swV[r0 + gid];     aV[rm][1] = swV[r0 + gid + 8];
                aV[rm][2] = swV[r1 + gid];     aV[rm][3] = swV[r1 + gid + 8];
            }
#pragma unroll
            for (int f = 0; f < 4; f++) {
                int px = px_base + f * 8 + gid;
                int r  = 2 * (px >> 5) + kh;
                int wl = px & 31;
                u32 bf[2];
                bf[0] = sy[((kw * 8 + r) * 8 + ctid) * 40 + wl];
                bf[1] = sy[((kw * 8 + r) * 8 + ctid + 4) * 40 + wl];
                mma_tf32(accK[0][f], aK[0], bf);
                mma_tf32(accK[1][f], aK[1], bf);
                mma_tf32(accV[0][f], aV[0], bf);
                mma_tf32(accV[1][f], aV[1], bf);
            }
        }
        __syncthreads();

#pragma unroll
        for (int j = 0; j < 4; j++) pin[j] = pin2[j];
    }

#pragma unroll
    for (int rm = 0; rm < 2; rm++) {
#pragma unroll
        for (int f = 0; f < 4; f++) {
            int coA = co0 + co_base + rm * 16 + gid;
            int coB = coA + 8;
            int px  = px_base + f * 8 + 2 * ctid;
            int n   = (h0 + (px >> 5)) * WK + (px & 31);
            size_t oA = ((size_t)b * CCH + coA) * MM + n;
            size_t oB = ((size_t)b * CCH + coB) * MM + n;
            float bkA = bK[coA], bkB = bK[coB];
            float bvA = bV[coA], bvB = bV[coB];
            float2 kA = {accK[rm][f][0] + bkA, accK[rm][f][1] + bkA};
            float2 kB = {accK[rm][f][2] + bkB, accK[rm][f][3] + bkB};
            float2 vA = {accV[rm][f][0] + bvA, accV[rm][f][1] + bvA};
            float2 vB = {accV[rm][f][2] + bvB, accV[rm][f][3] + bvB};
            *reinterpret_cast<float2*>(&outK[oA]) = kA;
            *reinterpret_cast<float2*>(&outK[oB]) = kB;
            *reinterpret_cast<float2*>(&outV[oA]) = vA;
            *reinterpret_cast<float2*>(&outV[oB]) = vB;
        }
    }
}

// ---------------------------------------------------------------------------
// GroupNorm(32 groups of 8 ch) + affine + SiLU, in place. float4, 512 thr.
// ---------------------------------------------------------------------------
__global__ __launch_bounds__(512) void gn_silu_kernel(
    float* __restrict__ buf, const float* __restrict__ scale,
    const float* __restrict__ bias, int S)
{
    const int b = blockIdx.x >> 5;
    const int g = blockIdx.x & 31;
    float* base = buf + ((size_t)b * CCH + g * 8) * S;
    float4* p4 = reinterpret_cast<float4*>(base);
    const int tot4 = (8 * S) >> 2;
    const int tid = threadIdx.x;

    float s = 0.f, ss = 0.f;
    for (int i = tid; i < tot4; i += 512) {
        float4 v = p4[i];
        s += v.x + v.y + v.z + v.w;
        ss = fmaf(v.x, v.x, ss);
        ss = fmaf(v.y, v.y, ss);
        ss = fmaf(v.z, v.z, ss);
        ss = fmaf(v.w, v.w, ss);
    }
    __shared__ float r1[512], r2[512];
    r1[tid] = s; r2[tid] = ss;
    __syncthreads();
    for (int st = 256; st > 0; st >>= 1) {
        if (tid < st) { r1[tid] += r1[tid + st]; r2[tid] += r2[tid + st]; }
        __syncthreads();
    }
    const float tot = (float)(8 * S);
    const float mu   = r1[0] / tot;
    const float var  = r2[0] / tot - mu * mu;
    const float rstd = rsqrtf(var + 1e-5f);

    const int s4 = S >> 2;
    for (int i = tid; i < tot4; i += 512) {
        int c = g * 8 + i / s4;
        float sc = scale[c] * rstd, bi = bias[c] - mu * scale[c] * rstd;
        float4 v = p4[i];
        v.x = fmaf(v.x, sc, bi);
        v.y = fmaf(v.y, sc, bi);
        v.z = fmaf(v.z, sc, bi);
        v.w = fmaf(v.w, sc, bi);
        v.x = v.x / (1.f + __expf(-v.x));
        v.y = v.y / (1.f + __expf(-v.y));
        v.z = v.z / (1.f + __expf(-v.z));
        v.w = v.w / (1.f + __expf(-v.w));
        p4[i] = v;
    }
}

// ---------------------------------------------------------------------------
// E = (1/16) Q^T K  (bf16 m16n8k16), staged loads double-buffered.
// grid: (MM/128=8, NN/128=32, B=8)
// ---------------------------------------------------------------------------
__global__ __launch_bounds__(256, 2) void gemm_qk_mma(
    const float* __restrict__ Q, const float* __restrict__ K,
    float* __restrict__ E)
{
    const int mb = blockIdx.x * 128;
    const int nb = blockIdx.y * 128;
    const int b  = blockIdx.z;
    const int tid  = threadIdx.x;
    const int lane = tid & 31;
    const int w    = tid >> 5;
    const int gid  = lane >> 2;
    const int ctid = lane & 3;
    const int m_base = (w & 1) * 64;
    const int n_base = (w >> 1) * 32;

    __shared__ u32 sq2[8 * 136];
    __shared__ u32 sk2[8 * 136];

    float acc[2][8][4];
#pragma unroll
    for (int i = 0; i < 2; i++)
#pragma unroll
        for (int j = 0; j < 8; j++)
#pragma unroll
            for (int l = 0; l < 4; l++) acc[i][j][l] = 0.f;

    const float* Qb = Q + (size_t)b * CCH * NN + nb;
    const float* Kb = K + (size_t)b * CCH * MM + mb;

    const int kc  = tid >> 5;
    const int col = (lane) * 4;

    float4 pq0, pq1, pk0, pk1, nq0, nq1, nk0, nk1;

#define QK_LOAD(q0, q1, k0, k1, C0)                                                        \
    {                                                                                      \
        q0 = *reinterpret_cast<const float4*>(&Qb[(size_t)((C0) + 2 * kc) * NN + col]);     \
        q1 = *reinterpret_cast<const float4*>(&Qb[(size_t)((C0) + 2 * kc + 1) * NN + col]); \
        k0 = *reinterpret_cast<const float4*>(&Kb[(size_t)((C0) + 2 * kc) * MM + col]);     \
        k1 = *reinterpret_cast<const float4*>(&Kb[(size_t)((C0) + 2 * kc + 1) * MM + col]); \
    }

    QK_LOAD(pq0, pq1, pk0, pk1, 0);

    for (int c0 = 0; c0 < CCH; c0 += 16) {
        uint4 qs = {pkbf(pq0.x, pq1.x), pkbf(pq0.y, pq1.y),
                    pkbf(pq0.z, pq1.z), pkbf(pq0.w, pq1.w)};
        uint4 ks = {pkbf(pk0.x, pk1.x), pkbf(pk0.y, pk1.y),
                    pkbf(pk0.z, pk1.z), pkbf(pk0.w, pk1.w)};
        *reinterpret_cast<uint4*>(&sq2[kc * 136 + col]) = qs;
        *reinterpret_cast<uint4*>(&sk2[kc * 136 + col]) = ks;
        __syncthreads();

        if (c0 + 16 < CCH) QK_LOAD(nq0, nq1, nk0, nk1, c0 + 16);

        u32 a[2][4];
#pragma unroll
        for (int rm = 0; rm < 2; rm++) {
            int n0 = n_base + rm * 16;
            a[rm][0] = sq2[ctid * 136 + n0 + gid];
            a[rm][1] = sq2[ctid * 136 + n0 + gid + 8];
            a[rm][2] = sq2[(ctid + 4) * 136 + n0 + gid];
            a[rm][3] = sq2[(ctid + 4) * 136 + n0 + gid + 8];
        }
#pragma unroll
        for (int f = 0; f < 8; f++) {
            u32 bf[2];
            bf[0] = sk2[ctid * 136 + m_base + f * 8 + gid];
            bf[1] = sk2[(ctid + 4) * 136 + m_base + f * 8 + gid];
            mma_bf16(acc[0][f], a[0], bf);
            mma_bf16(acc[1][f], a[1], bf);
        }
        __syncthreads();

        pq0 = nq0; pq1 = nq1; pk0 = nk0; pk1 = nk1;
    }

    const float scale = 0.0625f;
    float* Eb = E + ((size_t)b * NN + nb) * MM + mb;
#pragma unroll
    for (int rm = 0; rm < 2; rm++) {
#pragma unroll
        for (int f = 0; f < 8; f++) {
            int r0 = n_base + rm * 16 + gid;
            int cc = m_base + f * 8 + 2 * ctid;
            float2 s0 = {acc[rm][f][0] * scale, acc[rm][f][1] * scale};
            float2 s1 = {acc[rm][f][2] * scale, acc[rm][f][3] * scale};
            *reinterpret_cast<float2*>(&Eb[(size_t)r0 * MM + cc])       = s0;
            *reinterpret_cast<float2*>(&Eb[(size_t)(r0 + 8) * MM + cc]) = s1;
        }
    }
}

// ---------------------------------------------------------------------------
// Softmax over last dim (M=1024), fp32 in -> packed bf16x2 out (m-pairs).
// One WARP per row. grid: B*NN/8 = 4096.
// ---------------------------------------------------------------------------
__global__ __launch_bounds__(256) void softmax_kernel(
    const float* __restrict__ E, u32* __restrict__ A)
{
    const int warp = threadIdx.x >> 5;
    const int lane = threadIdx.x & 31;
    const size_t row = (size_t)blockIdx.x * 8 + warp;
    const float4* p = reinterpret_cast<const float4*>(E + row * MM);
    u32* pa = A + row * (MM / 2);

    float4 v[8];
    float mx = -1e30f;
#pragma unroll
    for (int i = 0; i < 8; i++) {
        v[i] = p[lane + 32 * i];
        mx = fmaxf(mx, fmaxf(fmaxf(v[i].x, v[i].y), fmaxf(v[i].z, v[i].w)));
    }
#pragma unroll
    for (int o = 16; o > 0; o >>= 1)
        mx = fmaxf(mx, __shfl_xor_sync(0xFFFFFFFFu, mx, o));

    float sum = 0.f;
#pragma unroll
    for (int i = 0; i < 8; i++) {
        v[i].x = __expf(v[i].x - mx);
        v[i].y = __expf(v[i].y - mx);
        v[i].z = __expf(v[i].z - mx);
        v[i].w = __expf(v[i].w - mx);
        sum += v[i].x + v[i].y + v[i].z + v[i].w;
    }
#pragma unroll
    for (int o = 16; o > 0; o >>= 1)
        sum += __shfl_xor_sync(0xFFFFFFFFu, sum, o);

    float inv = 1.f / sum;
#pragma unroll
    for (int i = 0; i < 8; i++) {
        uint2 st;
        st.x = pkbf(v[i].x * inv, v[i].y * inv);
        st.y = pkbf(v[i].z * inv, v[i].w * inv);
        *reinterpret_cast<uint2*>(&pa[2 * (lane + 32 * i)]) = st;
    }
}

// ---------------------------------------------------------------------------
// out = gamma * V A^T (bf16 m16n8k16). A read pre-packed bf16x2 (m-pairs).
// grid: (NN/128=32, CCH/128=2, B=8)
// ---------------------------------------------------------------------------
__global__ __launch_bounds__(256, 2) void gemm_av_mma(
    const float* __restrict__ V, const u32* __restrict__ A,
    const float* __restrict__ gamma, float* __restrict__ out)
{
    const int nb = blockIdx.x * 128;
    const int cb = blockIdx.y * 128;
    const int b  = blockIdx.z;
    const int tid  = threadIdx.x;
    const int lane = tid & 31;
    const int w    = tid >> 5;
    const int gid  = lane >> 2;
    const int ctid = lane & 3;
    const int n_base = (w & 1) * 64;
    const int c_base = (w >> 1) * 32;

    __shared__ u32 sv2[8 * 136];
    __shared__ u32 sa2[8 * 136];

    float acc[2][8][4];
#pragma unroll
    for (int i = 0; i < 2; i++)
#pragma unroll
        for (int j = 0; j < 8; j++)
#pragma unroll
            for (int l = 0; l < 4; l++) acc[i][j][l] = 0.f;

    const float* Vb = V + (size_t)b * CCH * MM;
    const u32* Ab = A + (size_t)b * NN * (MM / 2);

    const int row0 = tid >> 2, f0 = tid & 3;
    const int row1 = row0 + 64;

    float4 pv0, pv1, nv0, nv1;
    uint2 pa0, pa1, na0, na1;

#define AV_LOAD(v0, v1, a0v, a1v, M0)                                                           \
    {                                                                                           \
        v0  = *reinterpret_cast<const float4*>(&Vb[(size_t)(cb + row0) * MM + (M0) + f0 * 4]);   \
        v1  = *reinterpret_cast<const float4*>(&Vb[(size_t)(cb + row1) * MM + (M0) + f0 * 4]);   \
        a0v = *reinterpret_cast<const uint2*>(&Ab[(size_t)(nb + row0) * (MM / 2) + ((M0) >> 1) + f0 * 2]); \
        a1v = *reinterpret_cast<const uint2*>(&Ab[(size_t)(nb + row1) * (MM / 2) + ((M0) >> 1) + f0 * 2]); \
    }

    AV_LOAD(pv0, pv1, pa0, pa1, 0);

    for (int m0 = 0; m0 < MM; m0 += 16) {
        sv2[(f0 * 2) * 136 + row0]     = pkbf(pv0.x, pv0.y);
        sv2[(f0 * 2 + 1) * 136 + row0] = pkbf(pv0.z, pv0.w);
        sv2[(f0 * 2) * 136 + row1]     = pkbf(pv1.x, pv1.y);
        sv2[(f0 * 2 + 1) * 136 + row1] = pkbf(pv1.z, pv1.w);
        sa2[(f0 * 2) * 136 + row0]     = pa0.x;
        sa2[(f0 * 2 + 1) * 136 + row0] = pa0.y;
        sa2[(f0 * 2) * 136 + row1]     = pa1.x;
        sa2[(f0 * 2 + 1) * 136 + row1] = pa1.y;
        __syncthreads();

        if (m0 + 16 < MM) AV_LOAD(nv0, nv1, na0, na1, m0 + 16);

        u32 a[2][4];
#pragma unroll
        for (int rm = 0; rm < 2; rm++) {
            int c0 = c_base + rm * 16;
            a[rm][0] = sv2[ctid * 136 + c0 + gid];
            a[rm][1] = sv2[ctid * 136 + c0 + gid + 8];
            a[rm][2] = sv2[(ctid + 4) * 136 + c0 + gid];
            a[rm][3] = sv2[(ctid + 4) * 136 + c0 + gid + 8];
        }
#pragma unroll
        for (int f = 0; f < 8; f++) {
            u32 bf[2];
            bf[0] = sa2[ctid * 136 + n_base + f * 8 + gid];
            bf[1] = sa2[(ctid + 4) * 136 + n_base + f * 8 + gid];
            mma_bf16(acc[0][f], a[0], bf);
            mma_bf16(acc[1][f], a[1], bf);
        }
        __syncthreads();

        pv0 = nv0; pv1 = nv1; pa0 = na0; pa1 = na1;
    }

    const float gm = gamma[0];
#pragma unroll
    for (int rm = 0; rm < 2; rm++) {
#pragma unroll
        for (int f = 0; f < 8; f++) {
            int c0 = cb + c_base + rm * 16 + gid;
            int nn2 = nb + n_base + f * 8 + 2 * ctid;
            float2 s0 = {gm * acc[rm][f][0], gm * acc[rm][f][1]};
            float2 s1 = {gm * acc[rm][f][2], gm * acc[rm][f][3]};
            *reinterpret_cast<float2*>(&out[((size_t)b * CCH + c0) * NN + nn2])     = s0;
            *reinterpret_cast<float2*>(&out[((size_t)b * CCH + c0 + 8) * NN + nn2]) = s1;
        }
    }
}

// ---------------------------------------------------------------------------
extern "C" void kernel_launch(void* const* d_in, const int* in_sizes, int n_in,
                              void* d_out, int out_size)
{
    const float* x        = (const float*)d_in[0];
    const float* y        = (const float*)d_in[1];
    const float* Wq       = (const float*)d_in[2];
    const float* bq       = (const float*)d_in[3];
    const float* gq_scale = (const float*)d_in[4];
    const float* gq_bias  = (const float*)d_in[5];
    const float* Wk       = (const float*)d_in[6];
    const float* bk       = (const float*)d_in[7];
    const float* gk_scale = (const float*)d_in[8];
    const float* gk_bias  = (const float*)d_in[9];
    const float* Wv       = (const float*)d_in[10];
    const float* bv       = (const float*)d_in[11];
    const float* gv_scale = (const float*)d_in[12];
    const float* gv_bias  = (const float*)d_in[13];
    const float* gamma    = (const float*)d_in[14];
    float* out = (float*)d_out;

    float *qp = nullptr, *kp = nullptr, *vp = nullptr, *ep = nullptr;
    u32 *ap = nullptr, *wtp = nullptr, *wkp = nullptr, *wvp = nullptr;
    cudaGetSymbolAddress((void**)&qp, g_q);
    cudaGetSymbolAddress((void**)&kp, g_k);
    cudaGetSymbolAddress((void**)&vp, g_v);
    cudaGetSymbolAddress((void**)&ep, g_e);
    cudaGetSymbolAddress((void**)&ap, g_a);
    cudaGetSymbolAddress((void**)&wtp, g_wt3);
    cudaGetSymbolAddress((void**)&wkp, g_wk2);
    cudaGetSymbolAddress((void**)&wvp, g_wv2);

    transpose_w3<<<(9 * 128 * 256 + 255) / 256, 256>>>(Wq, wtp);
    transpose_w2<<<(4 * 256 * 256 + 255) / 256, 256>>>(Wk, Wv, wkp, wvp);

    conv3_mma<<<dim3(HH / 2, CCH / 64, BATCH), 256>>>(wtp, x, bq, qp);
    conv2kv_mma<<<dim3(HK / 4, CCH / 64, BATCH), 256>>>(wkp, wvp, y, bk, bv, kp, vp);

    gn_silu_kernel<<<BATCH * 32, 512>>>(qp, gq_scale, gq_bias, NN);
    gn_silu_kernel<<<BATCH * 32, 512>>>(kp, gk_scale, gk_bias, MM);
    gn_silu_kernel<<<BATCH * 32, 512>>>(vp, gv_scale, gv_bias, MM);

    gemm_qk_mma<<<dim3(MM / 128, NN / 128, BATCH), 256>>>(qp, kp, ep);
    softmax_kernel<<<BATCH * NN / 8, 256>>>(ep, ap);
    gemm_av_mma<<<dim3(NN / 128, CCH / 128, BATCH), 256>>>(vp, ap, gamma, out);
}